// round 1
// baseline (speedup 1.0000x reference)
#include <cuda_runtime.h>
#include <math.h>

// ---------------------------------------------------------------------------
// Problem constants
// ---------------------------------------------------------------------------
namespace {
constexpr int BATCH = 128;
constexpr int LC    = 64;     // context length (L)
constexpr int LQ    = 448;    // query length (QLEN)
constexpr int DIM   = 768;    // D
constexpr int SEQ   = 512;    // LC + LQ
constexpr int C4    = 3072;   // 4*D

constexpr long long SZ_C1 = (long long)BATCH * LC;          // 8192
constexpr long long SZ_Q2 = (long long)BATCH * LQ;          // 57344
constexpr long long SZ_BD = (long long)BATCH * LC * DIM;    // 6291456
constexpr long long SZ_S  = (long long)BATCH * LC * LQ;     // 3670016
constexpr long long SZ_T  = (long long)BATCH * LC * LC;     // 524288
constexpr long long SZ_Y  = (long long)BATCH * LC * C4;     // 25165824
constexpr long long SZ_E  = SZ_BD;                          // (B,768,64)

constexpr long long OFF_C1  = 0;
constexpr long long OFF_Q2  = OFF_C1 + SZ_C1;
constexpr long long OFF_CW3 = OFF_Q2 + SZ_Q2;
constexpr long long OFF_S   = OFF_CW3 + SZ_BD;
constexpr long long OFF_S1  = OFF_S  + SZ_S;
constexpr long long OFF_S2  = OFF_S1 + SZ_S;
constexpr long long OFF_A   = OFF_S2 + SZ_S;
constexpr long long OFF_T   = OFF_A  + SZ_BD;
constexpr long long OFF_BT  = OFF_T  + SZ_T;
constexpr long long OFF_Y   = OFF_BT + SZ_BD;
constexpr long long OFF_E0  = OFF_Y  + SZ_Y;   // 8 encoder-sized buffers
constexpr long long OFF_MEAN = OFF_E0 + 8 * SZ_E;
constexpr long long OFF_RSTD = OFF_MEAN + 128;
constexpr long long OFF_PE   = OFF_RSTD + 128;
constexpr long long POOL_SZ  = OFF_PE + (long long)DIM * LC;
} // namespace

// Scratch pool (static device allocation; allowed by harness rules)
__device__ float g_pool[POOL_SZ];

// ---------------------------------------------------------------------------
// Generic batched GEMM:  C[bz] = alpha * op(A[bz]) @ op(B[bz]) (+biasM +biasN)
//                        (optional relu) (+residual), optional transposed store
// TA: A stored K x M (access A[k*lda+m]) ; else M x K
// TB: B stored N x K (access B[n*ldb+k]) ; else K x N
// OT: store C[n*ldc+m] ; else C[m*ldc+n]   (residual uses same layout)
// Requires: M % BM == 0, N % BN == 0, K % 16 == 0 (true for all calls here)
// ---------------------------------------------------------------------------
template<int BM, int BN, bool TA, bool TB, bool OT, bool RELU>
__global__ void __launch_bounds__(256) gemm_k(
    const float* __restrict__ A, long long sA, int lda,
    const float* __restrict__ B, long long sB, int ldb,
    float* __restrict__ C, long long sC, int ldc,
    const float* __restrict__ bM, long long sbM,
    const float* __restrict__ bN, long long sbN,
    const float* __restrict__ R, long long sR,
    float alpha, int K)
{
    constexpr int TM = BM / 16;
    constexpr int TN = BN / 16;
    const int bz = blockIdx.z;
    A += (long long)bz * sA;
    B += (long long)bz * sB;
    C += (long long)bz * sC;
    const float* bMp = bM ? bM + (long long)bz * sbM : nullptr;
    const float* bNp = bN ? bN + (long long)bz * sbN : nullptr;
    const float* Rp  = R  ? R  + (long long)bz * sR  : nullptr;

    const int m0 = blockIdx.y * BM;
    const int n0 = blockIdx.x * BN;

    __shared__ float As[16][BM + 4];
    __shared__ float Bs[16][BN + 4];

    const int tid = threadIdx.x;
    const int tx = tid & 15;
    const int ty = tid >> 4;

    float acc[TM][TN];
#pragma unroll
    for (int r = 0; r < TM; r++)
#pragma unroll
        for (int c = 0; c < TN; c++) acc[r][c] = 0.f;

    for (int k0 = 0; k0 < K; k0 += 16) {
        // ---- load A tile ----
        if (TA) {
#pragma unroll
            for (int i = 0; i < BM * 16 / 256; i++) {
                int idx = tid + i * 256;
                int k = idx / BM, m = idx % BM;
                As[k][m] = A[(long long)(k0 + k) * lda + (m0 + m)];
            }
        } else {
#pragma unroll
            for (int i = 0; i < BM * 16 / 256; i++) {
                int idx = tid + i * 256;
                int m = idx >> 4, k = idx & 15;
                As[k][m] = A[(long long)(m0 + m) * lda + (k0 + k)];
            }
        }
        // ---- load B tile ----
        if (TB) {
#pragma unroll
            for (int i = 0; i < BN * 16 / 256; i++) {
                int idx = tid + i * 256;
                int n = idx >> 4, k = idx & 15;
                Bs[k][n] = B[(long long)(n0 + n) * ldb + (k0 + k)];
            }
        } else {
#pragma unroll
            for (int i = 0; i < BN * 16 / 256; i++) {
                int idx = tid + i * 256;
                int k = idx / BN, n = idx % BN;
                Bs[k][n] = B[(long long)(k0 + k) * ldb + (n0 + n)];
            }
        }
        __syncthreads();

#pragma unroll
        for (int k = 0; k < 16; k++) {
            float a[TM], bb[TN];
            const float4* ap = reinterpret_cast<const float4*>(&As[k][ty * TM]);
#pragma unroll
            for (int r = 0; r < TM / 4; r++) {
                float4 t = ap[r];
                a[r * 4 + 0] = t.x; a[r * 4 + 1] = t.y;
                a[r * 4 + 2] = t.z; a[r * 4 + 3] = t.w;
            }
            const float4* bp = reinterpret_cast<const float4*>(&Bs[k][tx * TN]);
#pragma unroll
            for (int c = 0; c < TN / 4; c++) {
                float4 t = bp[c];
                bb[c * 4 + 0] = t.x; bb[c * 4 + 1] = t.y;
                bb[c * 4 + 2] = t.z; bb[c * 4 + 3] = t.w;
            }
#pragma unroll
            for (int r = 0; r < TM; r++)
#pragma unroll
                for (int c = 0; c < TN; c++)
                    acc[r][c] = fmaf(a[r], bb[c], acc[r][c]);
        }
        __syncthreads();
    }

    // ---- epilogue ----
#pragma unroll
    for (int r = 0; r < TM; r++) {
        int m = m0 + ty * TM + r;
#pragma unroll
        for (int c = 0; c < TN; c++) {
            int n = n0 + tx * TN + c;
            float v = acc[r][c] * alpha;
            if (bMp) v += bMp[m];
            if (bNp) v += bNp[n];
            if (RELU) v = fmaxf(v, 0.f);
            long long o = OT ? ((long long)n * ldc + m) : ((long long)m * ldc + n);
            if (Rp) v += Rp[o];
            C[o] = v;
        }
    }
}

// ---------------------------------------------------------------------------
// Small kernels
// ---------------------------------------------------------------------------

// rows of x (indexed via (b*512 + rowOff + i)) dotted with a 768-vector
__global__ void rowdot_k(const float* __restrict__ x, const float* __restrict__ w,
                         float* __restrict__ out, int rowsPerB, int rowOff)
{
    int warp = (blockIdx.x * blockDim.x + threadIdx.x) >> 5;
    int lane = threadIdx.x & 31;
    int b = warp / rowsPerB;
    int i = warp % rowsPerB;
    if (b >= BATCH) return;
    const float* src = x + ((long long)b * SEQ + rowOff + i) * DIM;
    float s = 0.f;
    for (int d = lane; d < DIM; d += 32) s += src[d] * w[d];
#pragma unroll
    for (int o = 16; o > 0; o >>= 1) s += __shfl_down_sync(0xffffffffu, s, o);
    if (lane == 0) out[warp] = s;
}

// cw3[b,i,d] = C[b,i,d] * w3[d]
__global__ void cw3_k(const float* __restrict__ x, const float* __restrict__ w3,
                      float* __restrict__ cw3)
{
    long long idx = (long long)blockIdx.x * 256 + threadIdx.x;
    if (idx >= SZ_BD) return;
    long long b = idx / ((long long)LC * DIM);
    long long r = idx % ((long long)LC * DIM);
    long long i = r / DIM;
    int d = (int)(r % DIM);
    cw3[idx] = x[((long long)b * SEQ + i) * DIM + d] * w3[d];
}

// row softmax; safe in-place (in == out)
__global__ void softmax_rows_k(const float* __restrict__ in, float* __restrict__ out, int len)
{
    long long base = (long long)blockIdx.x * len;
    int t = threadIdx.x; // 128 threads
    __shared__ float sh[128];
    float m = -1e30f;
    for (int i = t; i < len; i += 128) m = fmaxf(m, in[base + i]);
    sh[t] = m; __syncthreads();
    for (int o = 64; o > 0; o >>= 1) { if (t < o) sh[t] = fmaxf(sh[t], sh[t + o]); __syncthreads(); }
    m = sh[0]; __syncthreads();
    float s = 0.f;
    for (int i = t; i < len; i += 128) { float e = expf(in[base + i] - m); out[base + i] = e; s += e; }
    sh[t] = s; __syncthreads();
    for (int o = 64; o > 0; o >>= 1) { if (t < o) sh[t] += sh[t + o]; __syncthreads(); }
    float inv = 1.f / sh[0];
    for (int i = t; i < len; i += 128) out[base + i] *= inv;
}

// softmax over i (axis 1) of S (B, 64, 448): one thread per (b, j)
__global__ void softmax_cols_k(const float* __restrict__ S, float* __restrict__ S2)
{
    int idx = blockIdx.x * blockDim.x + threadIdx.x;
    if (idx >= BATCH * LQ) return;
    int b = idx / LQ, j = idx % LQ;
    long long base = (long long)b * LC * LQ + j;
    float m = -1e30f;
#pragma unroll 4
    for (int i = 0; i < LC; i++) m = fmaxf(m, S[base + (long long)i * LQ]);
    float s = 0.f;
#pragma unroll 4
    for (int i = 0; i < LC; i++) {
        float e = expf(S[base + (long long)i * LQ] - m);
        S2[base + (long long)i * LQ] = e;
        s += e;
    }
    float inv = 1.f / s;
#pragma unroll 4
    for (int i = 0; i < LC; i++) S2[base + (long long)i * LQ] *= inv;
}

// fused: build X0 (concat [C, A, C*A, C*Bt] transposed) on the fly + depthwise
// conv k=5 (groups=3072). Output layout Y[b, l, c] (so pointwise GEMM uses TB).
__global__ void rz_dw_fuse_k(const float* __restrict__ x, const float* __restrict__ Abuf,
                             const float* __restrict__ Btbuf,
                             const float* __restrict__ dww, const float* __restrict__ dwb,
                             float* __restrict__ Y)
{
    int c = blockIdx.x * 256 + threadIdx.x; // [0, 3072)
    int l = blockIdx.y;
    int b = blockIdx.z;
    int g = c / DIM;
    int d = c % DIM;
    float acc = dwb[c];
#pragma unroll
    for (int t = 0; t < 5; t++) {
        int l2 = l + t - 2;
        if (l2 < 0 || l2 >= LC) continue;
        float v;
        long long xo = ((long long)b * SEQ + l2) * DIM + d;
        long long ao = ((long long)b * LC + l2) * DIM + d;
        if (g == 0)      v = x[xo];
        else if (g == 1) v = Abuf[ao];
        else if (g == 2) v = x[xo] * Abuf[ao];
        else             v = x[xo] * Btbuf[ao];
        acc = fmaf(v, dww[c * 5 + t], acc);
    }
    Y[((long long)b * LC + l) * C4 + c] = acc;
}

// positional encoding pe[d*64 + l]
__global__ void pe_init_k(float* __restrict__ pe)
{
    int idx = blockIdx.x * 256 + threadIdx.x;
    if (idx >= DIM * LC) return;
    int d = idx / LC, l = idx % LC;
    float fd = (float)d;
    bool even = (d & 1) == 0;
    float freq = even ? powf(10000.f, -fd / 768.f)
                      : -powf(10000.f, (1.f - fd) / 768.f);
    float ph = even ? 0.f : 1.57079632679489662f;
    pe[idx] = sinf((float)l * freq + ph);
}

// P = X + pe (broadcast per batch)
__global__ void add_pe_k(const float* __restrict__ X, const float* __restrict__ pe,
                         float* __restrict__ P)
{
    long long i = (long long)blockIdx.x * 256 + threadIdx.x;
    if (i >= SZ_BD) return;
    P[i] = X[i] + pe[i % (DIM * LC)];
}

// per-batch mean / rstd over all D*L elements
__global__ void ln_stats_k(const float* __restrict__ in, float* __restrict__ mean,
                           float* __restrict__ rstd)
{
    int b = blockIdx.x;
    const float* p = in + (long long)b * (DIM * LC);
    float s = 0.f, s2 = 0.f;
    for (int i = threadIdx.x; i < DIM * LC; i += 256) {
        float v = p[i];
        s += v; s2 += v * v;
    }
    __shared__ float sh[256], sh2[256];
    sh[threadIdx.x] = s; sh2[threadIdx.x] = s2; __syncthreads();
    for (int o = 128; o > 0; o >>= 1) {
        if (threadIdx.x < o) { sh[threadIdx.x] += sh[threadIdx.x + o]; sh2[threadIdx.x] += sh2[threadIdx.x + o]; }
        __syncthreads();
    }
    if (threadIdx.x == 0) {
        float m = sh[0] / (float)(DIM * LC);
        float var = sh2[0] / (float)(DIM * LC) - m * m;
        mean[b] = m;
        rstd[b] = rsqrtf(var + 1e-5f);
    }
}

// out = (in - mean[b]) * rstd[b] * w[d,l] + bias[d,l]
__global__ void ln_apply_k(const float* __restrict__ in, const float* __restrict__ mean,
                           const float* __restrict__ rstd, const float* __restrict__ w,
                           const float* __restrict__ bias, float* __restrict__ out)
{
    long long i = (long long)blockIdx.x * 256 + threadIdx.x;
    if (i >= SZ_BD) return;
    long long b = i / (DIM * LC);
    int r = (int)(i % (DIM * LC));
    out[i] = (in[i] - mean[b]) * rstd[b] * w[r] + bias[r];
}

// depthwise conv k=3 pad 1 over l; layout (b, d, l)
__global__ void dwconv3_k(const float* __restrict__ in, const float* __restrict__ w,
                          const float* __restrict__ bias, float* __restrict__ out)
{
    long long idx = (long long)blockIdx.x * 256 + threadIdx.x;
    if (idx >= SZ_BD) return;
    int r = (int)(idx % (DIM * LC));
    int d = r / LC;
    int l = r % LC;
    long long rowbase = idx - l;
    float acc = bias[d];
#pragma unroll
    for (int t = 0; t < 3; t++) {
        int l2 = l + t - 1;
        if (l2 < 0 || l2 >= LC) continue;
        acc = fmaf(in[rowbase + l2], w[d * 3 + t], acc);
    }
    out[idx] = acc;
}

// final head: out[b] = sigmoid(dot(X[b], fcf_w) + fcf_b)
__global__ void final_head_k(const float* __restrict__ X, const float* __restrict__ w,
                             const float* __restrict__ bias, float* __restrict__ out)
{
    int b = blockIdx.x;
    const float* p = X + (long long)b * (DIM * LC);
    float s = 0.f;
    for (int i = threadIdx.x; i < DIM * LC; i += 256) s = fmaf(p[i], w[i], s);
    __shared__ float sh[256];
    sh[threadIdx.x] = s; __syncthreads();
    for (int o = 128; o > 0; o >>= 1) {
        if (threadIdx.x < o) sh[threadIdx.x] += sh[threadIdx.x + o];
        __syncthreads();
    }
    if (threadIdx.x == 0) out[b] = 1.f / (1.f + expf(-(sh[0] + bias[0])));
}

// ---------------------------------------------------------------------------
// Host-side helpers
// ---------------------------------------------------------------------------
template<int BM, int BN, bool TA, bool TB, bool OT, bool RELU>
static inline void run_gemm(const float* A, long long sA, int lda,
                            const float* B, long long sB, int ldb,
                            float* C, long long sC, int ldc,
                            const float* bM, long long sbM,
                            const float* bN, long long sbN,
                            const float* R, long long sR,
                            float alpha, int M, int N, int K)
{
    dim3 grid(N / BN, M / BM, BATCH);
    gemm_k<BM, BN, TA, TB, OT, RELU><<<grid, 256>>>(
        A, sA, lda, B, sB, ldb, C, sC, ldc, bM, sbM, bN, sbN, R, sR, alpha, K);
}

struct EncW {
    const float *c1dw, *c1db, *c1pw, *c1pb;
    const float *c2dw, *c2db, *c2pw, *c2pb;
    const float *wq, *wk, *wv, *wo;
    const float *fcw, *fcb;
    const float *nbw, *nbb, *n1w, *n1b, *n2w, *n2b, *nEw, *nEb;
};

static void enc_block(const float* Xin,
                      float* s1, float* s2, float* s3, float* s4, float* s5, float* s6,
                      float* Xout, const float* pe, float* mean, float* rstd,
                      float* scores, const EncW& w)
{
    const long long SE = (long long)DIM * LC; // per-batch stride 49152
    const int EB = (int)(SZ_BD / 256);
    const float scale = 0.03608439182435161f; // 1/sqrt(768)

    // out = X + pe  (res0 = s1)
    add_pe_k<<<EB, 256>>>(Xin, pe, s1);
    // ln(normb) -> s2
    ln_stats_k<<<BATCH, 256>>>(s1, mean, rstd);
    ln_apply_k<<<EB, 256>>>(s1, mean, rstd, w.nbw, w.nbb, s2);
    // dw conv c1 -> s3
    dwconv3_k<<<EB, 256>>>(s2, w.c1dw, w.c1db, s3);
    // pw c1 + relu + res(s1) -> s4  (res1 = s4)
    run_gemm<128, 64, false, false, false, true>(w.c1pw, 0, DIM, s3, SE, LC, s4, SE, LC,
                                                 w.c1pb, 0, nullptr, 0, s1, SE, 1.f, DIM, LC, DIM);
    // ln(norm1) -> s2
    ln_stats_k<<<BATCH, 256>>>(s4, mean, rstd);
    ln_apply_k<<<EB, 256>>>(s4, mean, rstd, w.n1w, w.n1b, s2);
    // dw conv c2 -> s3
    dwconv3_k<<<EB, 256>>>(s2, w.c2dw, w.c2db, s3);
    // pw c2 + relu + res(s4) -> s1  (res2 = s1 = P3)
    run_gemm<128, 64, false, false, false, true>(w.c2pw, 0, DIM, s3, SE, LC, s1, SE, LC,
                                                 w.c2pb, 0, nullptr, 0, s4, SE, 1.f, DIM, LC, DIM);
    // ln(norm2) -> s2
    ln_stats_k<<<BATCH, 256>>>(s1, mean, rstd);
    ln_apply_k<<<EB, 256>>>(s1, mean, rstd, w.n2w, w.n2b, s2);
    // q, k, v : (64x768) = s2^T @ W   (TA: s2 stored (768 x 64))
    run_gemm<64, 128, true, false, false, false>(s2, SE, LC, w.wq, 0, DIM, s3, SE, DIM,
                                                 nullptr, 0, nullptr, 0, nullptr, 0, 1.f, LC, DIM, DIM);
    run_gemm<64, 128, true, false, false, false>(s2, SE, LC, w.wk, 0, DIM, s5, SE, DIM,
                                                 nullptr, 0, nullptr, 0, nullptr, 0, 1.f, LC, DIM, DIM);
    run_gemm<64, 128, true, false, false, false>(s2, SE, LC, w.wv, 0, DIM, s6, SE, DIM,
                                                 nullptr, 0, nullptr, 0, nullptr, 0, 1.f, LC, DIM, DIM);
    // scores = q @ k^T * scale
    run_gemm<64, 64, false, true, false, false>(s3, SE, DIM, s5, SE, DIM, scores, (long long)LC * LC, LC,
                                                nullptr, 0, nullptr, 0, nullptr, 0, scale, LC, LC, DIM);
    softmax_rows_k<<<BATCH * LC, 128>>>(scores, scores, LC);
    // av = attn @ v -> s2
    run_gemm<64, 128, false, false, false, false>(scores, (long long)LC * LC, LC, s6, SE, DIM, s2, SE, DIM,
                                                  nullptr, 0, nullptr, 0, nullptr, 0, 1.f, LC, DIM, LC);
    // sa = (av @ wo)^T + res(s1) -> s4   (res3 = s4 = P4)
    run_gemm<64, 128, false, false, true, false>(s2, SE, DIM, w.wo, 0, DIM, s4, SE, LC,
                                                 nullptr, 0, nullptr, 0, s1, SE, 1.f, LC, DIM, DIM);
    // ln(norme) -> s2
    ln_stats_k<<<BATCH, 256>>>(s4, mean, rstd);
    ln_apply_k<<<EB, 256>>>(s4, mean, rstd, w.nEw, w.nEb, s2);
    // fc + relu + res(s4) -> Xout
    run_gemm<128, 64, false, false, false, true>(w.fcw, 0, DIM, s2, SE, LC, Xout, SE, LC,
                                                 w.fcb, 0, nullptr, 0, s4, SE, 1.f, DIM, LC, DIM);
}

// ---------------------------------------------------------------------------
// Entry point
// ---------------------------------------------------------------------------
extern "C" void kernel_launch(void* const* d_in, const int* in_sizes, int n_in,
                              void* d_out, int out_size)
{
    (void)in_sizes; (void)n_in; (void)out_size;
    const float* x       = (const float*)d_in[0];
    const float* Wv      = (const float*)d_in[1];
    const float* rz_dw_w = (const float*)d_in[2];
    const float* rz_dw_b = (const float*)d_in[3];
    const float* rz_pw_w = (const float*)d_in[4];
    const float* rz_pw_b = (const float*)d_in[5];
    EncW w;
    w.c1dw = (const float*)d_in[6];  w.c1db = (const float*)d_in[7];
    w.c1pw = (const float*)d_in[8];  w.c1pb = (const float*)d_in[9];
    w.c2dw = (const float*)d_in[10]; w.c2db = (const float*)d_in[11];
    w.c2pw = (const float*)d_in[12]; w.c2pb = (const float*)d_in[13];
    w.wq   = (const float*)d_in[14]; w.wk   = (const float*)d_in[15];
    w.wv   = (const float*)d_in[16]; w.wo   = (const float*)d_in[17];
    w.fcw  = (const float*)d_in[18]; w.fcb  = (const float*)d_in[19];
    w.nbw  = (const float*)d_in[20]; w.nbb  = (const float*)d_in[21];
    w.n1w  = (const float*)d_in[22]; w.n1b  = (const float*)d_in[23];
    w.n2w  = (const float*)d_in[24]; w.n2b  = (const float*)d_in[25];
    w.nEw  = (const float*)d_in[26]; w.nEb  = (const float*)d_in[27];
    const float* fcf_w = (const float*)d_in[28];
    const float* fcf_b = (const float*)d_in[29];

    float* pool = nullptr;
    cudaGetSymbolAddress((void**)&pool, g_pool);

    float* c1s  = pool + OFF_C1;
    float* q2s  = pool + OFF_Q2;
    float* cw3  = pool + OFF_CW3;
    float* S    = pool + OFF_S;
    float* S1   = pool + OFF_S1;
    float* S2   = pool + OFF_S2;
    float* Abuf = pool + OFF_A;
    float* Tbuf = pool + OFF_T;
    float* Btb  = pool + OFF_BT;
    float* Y    = pool + OFF_Y;
    float* E[8];
    for (int i = 0; i < 8; i++) E[i] = pool + OFF_E0 + (long long)i * SZ_E;
    float* mean = pool + OFF_MEAN;
    float* rstd = pool + OFF_RSTD;
    float* pe   = pool + OFF_PE;

    const int EB = (int)(SZ_BD / 256);

    // positional encoding (cheap; recomputed every call for determinism)
    pe_init_k<<<(DIM * LC + 255) / 256, 256>>>(pe);

    // ---- co-attention front end ----
    rowdot_k<<<(BATCH * LC * 32) / 256, 256>>>(x, Wv, c1s, LC, 0);            // C . w1
    rowdot_k<<<(BATCH * LQ * 32) / 256, 256>>>(x, Wv + DIM, q2s, LQ, LC);     // Q . w2
    cw3_k<<<EB, 256>>>(x, Wv + 2 * DIM, cw3);                                 // C * w3

    // S = (C*w3) @ Q^T + c1[:,None] + q2[None,:]
    run_gemm<64, 64, false, true, false, false>(
        cw3, (long long)LC * DIM, DIM,
        x + (long long)LC * DIM, (long long)SEQ * DIM, DIM,
        S, (long long)LC * LQ, LQ,
        c1s, LC, q2s, LQ, nullptr, 0, 1.f, LC, LQ, DIM);

    softmax_rows_k<<<BATCH * LC, 128>>>(S, S1, LQ);
    softmax_cols_k<<<(BATCH * LQ + 255) / 256, 256>>>(S, S2);

    // A = S1 @ Q
    run_gemm<64, 128, false, false, false, false>(
        S1, (long long)LC * LQ, LQ,
        x + (long long)LC * DIM, (long long)SEQ * DIM, DIM,
        Abuf, (long long)LC * DIM, DIM,
        nullptr, 0, nullptr, 0, nullptr, 0, 1.f, LC, DIM, LQ);

    // T = S1 @ S2^T
    run_gemm<64, 64, false, true, false, false>(
        S1, (long long)LC * LQ, LQ,
        S2, (long long)LC * LQ, LQ,
        Tbuf, (long long)LC * LC, LC,
        nullptr, 0, nullptr, 0, nullptr, 0, 1.f, LC, LC, LQ);

    // Bt = T @ C
    run_gemm<64, 128, false, false, false, false>(
        Tbuf, (long long)LC * LC, LC,
        x, (long long)SEQ * DIM, DIM,
        Btb, (long long)LC * DIM, DIM,
        nullptr, 0, nullptr, 0, nullptr, 0, 1.f, LC, DIM, LC);

    // fused concat-gather + depthwise k=5  ->  Y (b, l, c)
    rz_dw_fuse_k<<<dim3(C4 / 256, LC, BATCH), 256>>>(x, Abuf, Btb, rz_dw_w, rz_dw_b, Y);

    // pointwise 3072 -> 768 : X = rz_pw_w @ Y^T + bias  -> E0 (b, d, l)
    run_gemm<128, 64, false, true, false, false>(
        rz_pw_w, 0, C4,
        Y, (long long)LC * C4, C4,
        E[0], (long long)DIM * LC, LC,
        rz_pw_b, 0, nullptr, 0, nullptr, 0, 1.f, DIM, LC, C4);

    // ---- two encoder blocks ----
    enc_block(E[0], E[1], E[2], E[3], E[4], E[5], E[6], E[7], pe, mean, rstd, Tbuf, w);
    enc_block(E[7], E[1], E[2], E[3], E[4], E[5], E[6], E[0], pe, mean, rstd, Tbuf, w);

    // ---- final sigmoid head ----
    final_head_k<<<BATCH, 256>>>(E[0], fcf_w, fcf_b, (float*)d_out);
}

// round 2
// speedup vs baseline: 1.2652x; 1.2652x over previous
#include <cuda_runtime.h>
#include <math.h>

// ---------------------------------------------------------------------------
// Problem constants
// ---------------------------------------------------------------------------
namespace {
constexpr int BATCH = 128;
constexpr int LC    = 64;
constexpr int LQ    = 448;
constexpr int DIM   = 768;
constexpr int SEQ   = 512;
constexpr int C4    = 3072;

constexpr long long SZ_C1 = (long long)BATCH * LC;
constexpr long long SZ_Q2 = (long long)BATCH * LQ;
constexpr long long SZ_BD = (long long)BATCH * LC * DIM;   // 6291456
constexpr long long SZ_S  = (long long)BATCH * LC * LQ;
constexpr long long SZ_T  = (long long)BATCH * LC * LC;
constexpr long long SZ_Y  = (long long)BATCH * LC * C4;
constexpr long long SZ_E  = SZ_BD;

constexpr long long OFF_C1  = 0;
constexpr long long OFF_Q2  = OFF_C1 + SZ_C1;
constexpr long long OFF_CW3 = OFF_Q2 + SZ_Q2;
constexpr long long OFF_S   = OFF_CW3 + SZ_BD;
constexpr long long OFF_S1  = OFF_S  + SZ_S;
constexpr long long OFF_S2  = OFF_S1 + SZ_S;
constexpr long long OFF_A   = OFF_S2 + SZ_S;
constexpr long long OFF_T   = OFF_A  + SZ_BD;
constexpr long long OFF_BT  = OFF_T  + SZ_T;
constexpr long long OFF_Y   = OFF_BT + SZ_BD;
constexpr long long OFF_E0  = OFF_Y  + SZ_Y;   // 8 encoder-sized buffers
constexpr long long OFF_MEAN = OFF_E0 + 8 * SZ_E;
constexpr long long OFF_RSTD = OFF_MEAN + 128;
constexpr long long OFF_PE   = OFF_RSTD + 128;
constexpr long long POOL_SZ  = OFF_PE + (long long)DIM * LC;
} // namespace

__device__ float g_pool[POOL_SZ];

// ---------------------------------------------------------------------------
// GEMM, 8x8 register microtile, double-buffered smem, BK=16.
//   C[bz] = alpha * op(A) @ op(B) (+biasM)(+biasN) (relu) (+R) (+plane)
// TA: A stored K x M ; TB: B stored N x K ; OT: store C[n*ldc+m]
// Requires M%BM==0, N%BN==0, K%16==0.
// ---------------------------------------------------------------------------
template<int BM, int BN, bool TA, bool TB, bool OT, bool RELU>
__global__ void __launch_bounds__((BM/8)*(BN/8)) gemm8_k(
    const float* __restrict__ A, long long sA, int lda,
    const float* __restrict__ B, long long sB, int ldb,
    float* __restrict__ C, long long sC, int ldc,
    const float* __restrict__ bM, long long sbM,
    const float* __restrict__ bN, long long sbN,
    const float* __restrict__ R, long long sR,
    const float* __restrict__ plane,
    float alpha, int K)
{
    constexpr int THREADS = (BM / 8) * (BN / 8);
    constexpr int LA = BM * 16 / THREADS;
    constexpr int LB = BN * 16 / THREADS;

    const int bz = blockIdx.z;
    A += (long long)bz * sA;
    B += (long long)bz * sB;
    C += (long long)bz * sC;
    const float* bMp = bM ? bM + (long long)bz * sbM : nullptr;
    const float* bNp = bN ? bN + (long long)bz * sbN : nullptr;
    const float* Rp  = R  ? R  + (long long)bz * sR  : nullptr;

    const int m0 = blockIdx.y * BM;
    const int n0 = blockIdx.x * BN;

    __shared__ float As[2][16][BM + 4];
    __shared__ float Bs[2][16][BN + 4];

    const int tid = threadIdx.x;
    const int tx = tid % (BN / 8);
    const int ty = tid / (BN / 8);

    float acc[8][8];
#pragma unroll
    for (int r = 0; r < 8; r++)
#pragma unroll
        for (int c = 0; c < 8; c++) acc[r][c] = 0.f;

    float ra[LA], rb[LB];

    // ---- load tile 0 directly to smem ----
#pragma unroll
    for (int i = 0; i < LA; i++) {
        int idx = tid + i * THREADS;
        if (TA) { int k = idx / BM, m = idx % BM; As[0][k][m] = A[(long long)k * lda + (m0 + m)]; }
        else    { int m = idx / 16, k = idx % 16; As[0][k][m] = A[(long long)(m0 + m) * lda + k]; }
    }
#pragma unroll
    for (int i = 0; i < LB; i++) {
        int idx = tid + i * THREADS;
        if (TB) { int n = idx / 16, k = idx % 16; Bs[0][k][n] = B[(long long)(n0 + n) * ldb + k]; }
        else    { int k = idx / BN, n = idx % BN; Bs[0][k][n] = B[(long long)k * ldb + (n0 + n)]; }
    }
    __syncthreads();

    int buf = 0;
    for (int k0 = 0; k0 < K; k0 += 16) {
        const bool more = (k0 + 16) < K;
        if (more) {
            const int kn = k0 + 16;
#pragma unroll
            for (int i = 0; i < LA; i++) {
                int idx = tid + i * THREADS;
                if (TA) { int k = idx / BM, m = idx % BM; ra[i] = A[(long long)(kn + k) * lda + (m0 + m)]; }
                else    { int m = idx / 16, k = idx % 16; ra[i] = A[(long long)(m0 + m) * lda + (kn + k)]; }
            }
#pragma unroll
            for (int i = 0; i < LB; i++) {
                int idx = tid + i * THREADS;
                if (TB) { int n = idx / 16, k = idx % 16; rb[i] = B[(long long)(n0 + n) * ldb + (kn + k)]; }
                else    { int k = idx / BN, n = idx % BN; rb[i] = B[(long long)(kn + k) * ldb + (n0 + n)]; }
            }
        }

#pragma unroll
        for (int k = 0; k < 16; k++) {
            float a[8], b[8];
            float4 t;
            t = *reinterpret_cast<const float4*>(&As[buf][k][ty * 8]);
            a[0] = t.x; a[1] = t.y; a[2] = t.z; a[3] = t.w;
            t = *reinterpret_cast<const float4*>(&As[buf][k][ty * 8 + 4]);
            a[4] = t.x; a[5] = t.y; a[6] = t.z; a[7] = t.w;
            t = *reinterpret_cast<const float4*>(&Bs[buf][k][tx * 8]);
            b[0] = t.x; b[1] = t.y; b[2] = t.z; b[3] = t.w;
            t = *reinterpret_cast<const float4*>(&Bs[buf][k][tx * 8 + 4]);
            b[4] = t.x; b[5] = t.y; b[6] = t.z; b[7] = t.w;
#pragma unroll
            for (int r = 0; r < 8; r++)
#pragma unroll
                for (int c = 0; c < 8; c++)
                    acc[r][c] = fmaf(a[r], b[c], acc[r][c]);
        }

        if (more) {
            int nb = buf ^ 1;
#pragma unroll
            for (int i = 0; i < LA; i++) {
                int idx = tid + i * THREADS;
                if (TA) { int k = idx / BM, m = idx % BM; As[nb][k][m] = ra[i]; }
                else    { int m = idx / 16, k = idx % 16; As[nb][k][m] = ra[i]; }
            }
#pragma unroll
            for (int i = 0; i < LB; i++) {
                int idx = tid + i * THREADS;
                if (TB) { int n = idx / 16, k = idx % 16; Bs[nb][k][n] = rb[i]; }
                else    { int k = idx / BN, n = idx % BN; Bs[nb][k][n] = rb[i]; }
            }
            __syncthreads();
            buf = nb;
        }
    }

    // ---- epilogue ----
#pragma unroll
    for (int r = 0; r < 8; r++) {
        int m = m0 + ty * 8 + r;
#pragma unroll
        for (int c = 0; c < 8; c++) {
            int n = n0 + tx * 8 + c;
            float v = acc[r][c] * alpha;
            if (bMp) v += bMp[m];
            if (bNp) v += bNp[n];
            if (RELU) v = fmaxf(v, 0.f);
            long long o = OT ? ((long long)n * ldc + m) : ((long long)m * ldc + n);
            if (Rp) v += Rp[o];
            if (plane) v += plane[o];
            C[o] = v;
        }
    }
}

// ---------------------------------------------------------------------------
// Small kernels
// ---------------------------------------------------------------------------
__global__ void rowdot_k(const float* __restrict__ x, const float* __restrict__ w,
                         float* __restrict__ out, int rowsPerB, int rowOff)
{
    int warp = (blockIdx.x * blockDim.x + threadIdx.x) >> 5;
    int lane = threadIdx.x & 31;
    int b = warp / rowsPerB;
    int i = warp % rowsPerB;
    if (b >= BATCH) return;
    const float* src = x + ((long long)b * SEQ + rowOff + i) * DIM;
    float s = 0.f;
    for (int d = lane; d < DIM; d += 32) s += src[d] * w[d];
#pragma unroll
    for (int o = 16; o > 0; o >>= 1) s += __shfl_down_sync(0xffffffffu, s, o);
    if (lane == 0) out[warp] = s;
}

// cw3[b,i,d] = C[b,i,d] * w3[d]   (float4)
__global__ void cw3_k(const float* __restrict__ x, const float* __restrict__ w3,
                      float* __restrict__ cw3)
{
    long long i4 = (long long)blockIdx.x * 256 + threadIdx.x;
    if (i4 >= SZ_BD / 4) return;
    int d4 = (int)(i4 % (DIM / 4));
    long long row = i4 / (DIM / 4);             // b*64 + i
    long long b = row / LC, i = row % LC;
    float4 xv = reinterpret_cast<const float4*>(x)[((long long)b * SEQ + i) * (DIM / 4) + d4];
    float4 wv = reinterpret_cast<const float4*>(w3)[d4];
    float4 o; o.x = xv.x * wv.x; o.y = xv.y * wv.y; o.z = xv.z * wv.z; o.w = xv.w * wv.w;
    reinterpret_cast<float4*>(cw3)[i4] = o;
}

__global__ void softmax_rows_k(const float* __restrict__ in, float* __restrict__ out, int len)
{
    long long base = (long long)blockIdx.x * len;
    int t = threadIdx.x; // 128
    __shared__ float sh[128];
    float m = -1e30f;
    for (int i = t; i < len; i += 128) m = fmaxf(m, in[base + i]);
    sh[t] = m; __syncthreads();
    for (int o = 64; o > 0; o >>= 1) { if (t < o) sh[t] = fmaxf(sh[t], sh[t + o]); __syncthreads(); }
    m = sh[0]; __syncthreads();
    float s = 0.f;
    for (int i = t; i < len; i += 128) { float e = expf(in[base + i] - m); out[base + i] = e; s += e; }
    sh[t] = s; __syncthreads();
    for (int o = 64; o > 0; o >>= 1) { if (t < o) sh[t] += sh[t + o]; __syncthreads(); }
    float inv = 1.f / sh[0];
    for (int i = t; i < len; i += 128) out[base + i] *= inv;
}

__global__ void softmax_cols_k(const float* __restrict__ S, float* __restrict__ S2)
{
    int idx = blockIdx.x * blockDim.x + threadIdx.x;
    if (idx >= BATCH * LQ) return;
    int b = idx / LQ, j = idx % LQ;
    long long base = (long long)b * LC * LQ + j;
    float m = -1e30f;
#pragma unroll 4
    for (int i = 0; i < LC; i++) m = fmaxf(m, S[base + (long long)i * LQ]);
    float s = 0.f;
#pragma unroll 4
    for (int i = 0; i < LC; i++) {
        float e = expf(S[base + (long long)i * LQ] - m);
        S2[base + (long long)i * LQ] = e;
        s += e;
    }
    float inv = 1.f / s;
#pragma unroll 4
    for (int i = 0; i < LC; i++) S2[base + (long long)i * LQ] *= inv;
}

// fused concat-gather + depthwise k=5 (groups=3072), out Y[b, l, c]
__global__ void rz_dw_fuse_k(const float* __restrict__ x, const float* __restrict__ Abuf,
                             const float* __restrict__ Btbuf,
                             const float* __restrict__ dww, const float* __restrict__ dwb,
                             float* __restrict__ Y)
{
    int c = blockIdx.x * 256 + threadIdx.x;
    int l = blockIdx.y;
    int b = blockIdx.z;
    int g = c / DIM;
    int d = c % DIM;
    float acc = dwb[c];
#pragma unroll
    for (int t = 0; t < 5; t++) {
        int l2 = l + t - 2;
        if (l2 < 0 || l2 >= LC) continue;
        float v;
        long long xo = ((long long)b * SEQ + l2) * DIM + d;
        long long ao = ((long long)b * LC + l2) * DIM + d;
        if (g == 0)      v = x[xo];
        else if (g == 1) v = Abuf[ao];
        else if (g == 2) v = x[xo] * Abuf[ao];
        else             v = x[xo] * Btbuf[ao];
        acc = fmaf(v, dww[c * 5 + t], acc);
    }
    Y[((long long)b * LC + l) * C4 + c] = acc;
}

__global__ void pe_init_k(float* __restrict__ pe)
{
    int idx = blockIdx.x * 256 + threadIdx.x;
    if (idx >= DIM * LC) return;
    int d = idx / LC, l = idx % LC;
    float fd = (float)d;
    bool even = (d & 1) == 0;
    float freq = even ? powf(10000.f, -fd / 768.f)
                      : -powf(10000.f, (1.f - fd) / 768.f);
    float ph = even ? 0.f : 1.57079632679489662f;
    pe[idx] = sinf((float)l * freq + ph);
}

// per-batch mean / rstd over D*L elements (float4, 512 threads)
__global__ void ln_stats_k(const float* __restrict__ in, float* __restrict__ mean,
                           float* __restrict__ rstd)
{
    int b = blockIdx.x;
    const float4* p = reinterpret_cast<const float4*>(in + (long long)b * (DIM * LC));
    float s = 0.f, s2 = 0.f;
    for (int i = threadIdx.x; i < DIM * LC / 4; i += 512) {
        float4 v = p[i];
        s += v.x + v.y + v.z + v.w;
        s2 += v.x * v.x + v.y * v.y + v.z * v.z + v.w * v.w;
    }
    __shared__ float sh[512], sh2[512];
    sh[threadIdx.x] = s; sh2[threadIdx.x] = s2; __syncthreads();
    for (int o = 256; o > 0; o >>= 1) {
        if (threadIdx.x < o) { sh[threadIdx.x] += sh[threadIdx.x + o]; sh2[threadIdx.x] += sh2[threadIdx.x + o]; }
        __syncthreads();
    }
    if (threadIdx.x == 0) {
        float m = sh[0] / (float)(DIM * LC);
        float var = sh2[0] / (float)(DIM * LC) - m * m;
        mean[b] = m;
        rstd[b] = rsqrtf(var + 1e-5f);
    }
}

// ln apply only (float4)
__global__ void ln_apply_k(const float* __restrict__ in, const float* __restrict__ mean,
                           const float* __restrict__ rstd, const float* __restrict__ w,
                           const float* __restrict__ bias, float* __restrict__ out)
{
    long long i4 = (long long)blockIdx.x * 256 + threadIdx.x;
    if (i4 >= SZ_BD / 4) return;
    long long b = i4 / (DIM * LC / 4);
    int r4 = (int)(i4 % (DIM * LC / 4));
    float mu = mean[b], rs = rstd[b];
    float4 v = reinterpret_cast<const float4*>(in)[i4];
    float4 g = reinterpret_cast<const float4*>(w)[r4];
    float4 bb = reinterpret_cast<const float4*>(bias)[r4];
    float4 o;
    o.x = (v.x - mu) * rs * g.x + bb.x;
    o.y = (v.y - mu) * rs * g.y + bb.y;
    o.z = (v.z - mu) * rs * g.z + bb.z;
    o.w = (v.w - mu) * rs * g.w + bb.w;
    reinterpret_cast<float4*>(out)[i4] = o;
}

// fused: ln apply + depthwise conv3 over l; in/out layout (b, d, l)
__global__ void ln_conv_k(const float* __restrict__ in, const float* __restrict__ mean,
                          const float* __restrict__ rstd, const float* __restrict__ lw,
                          const float* __restrict__ lb, const float* __restrict__ cw,
                          const float* __restrict__ cb, float* __restrict__ out)
{
    long long idx = (long long)blockIdx.x * 256 + threadIdx.x;
    if (idx >= SZ_BD) return;
    long long b = idx / (DIM * LC);
    int r = (int)(idx % (DIM * LC));
    int d = r / LC;
    int l = r % LC;
    float mu = mean[b], rs = rstd[b];
    long long rowbase = idx - l;
    int wb = d * LC;
    float acc = cb[d];
#pragma unroll
    for (int t = 0; t < 3; t++) {
        int l2 = l + t - 1;
        if (l2 < 0 || l2 >= LC) continue;
        float v = (in[rowbase + l2] - mu) * rs * lw[wb + l2] + lb[wb + l2];
        acc = fmaf(v, cw[d * 3 + t], acc);
    }
    out[idx] = acc;
}

__global__ void final_head_k(const float* __restrict__ X, const float* __restrict__ w,
                             const float* __restrict__ bias, float* __restrict__ out)
{
    int b = blockIdx.x;
    const float* p = X + (long long)b * (DIM * LC);
    float s = 0.f;
    for (int i = threadIdx.x; i < DIM * LC; i += 256) s = fmaf(p[i], w[i], s);
    __shared__ float sh[256];
    sh[threadIdx.x] = s; __syncthreads();
    for (int o = 128; o > 0; o >>= 1) {
        if (threadIdx.x < o) sh[threadIdx.x] += sh[threadIdx.x + o];
        __syncthreads();
    }
    if (threadIdx.x == 0) out[b] = 1.f / (1.f + expf(-(sh[0] + bias[0])));
}

// ---------------------------------------------------------------------------
// Host-side helpers
// ---------------------------------------------------------------------------
template<int BM, int BN, bool TA, bool TB, bool OT, bool RELU>
static inline void run_gemm(const float* A, long long sA, int lda,
                            const float* B, long long sB, int ldb,
                            float* C, long long sC, int ldc,
                            const float* bM, long long sbM,
                            const float* bN, long long sbN,
                            const float* R, long long sR,
                            const float* plane,
                            float alpha, int M, int N, int K)
{
    dim3 grid(N / BN, M / BM, BATCH);
    gemm8_k<BM, BN, TA, TB, OT, RELU><<<grid, (BM / 8) * (BN / 8)>>>(
        A, sA, lda, B, sB, ldb, C, sC, ldc, bM, sbM, bN, sbN, R, sR, plane, alpha, K);
}

struct EncW {
    const float *c1dw, *c1db, *c1pw, *c1pb;
    const float *c2dw, *c2db, *c2pw, *c2pb;
    const float *wq, *wk, *wv, *wo;
    const float *fcw, *fcb;
    const float *nbw, *nbb, *n1w, *n1b, *n2w, *n2b, *nEw, *nEb;
};

// Xin already contains the positional encoding.
// outPlane: pe to fold into the fc epilogue (block 1) or nullptr (block 2).
static void enc_block(const float* Xin,
                      float* t1, float* t2, float* t3, float* q, float* kk, float* v,
                      float* Xout, const float* outPlane, float* mean, float* rstd,
                      float* scores, const EncW& w)
{
    const long long SE = (long long)DIM * LC;
    const int EB = (int)(SZ_BD / 256);
    const int EB4 = (int)(SZ_BD / 4 / 256);
    const float scale = 0.03608439182435161f; // 1/sqrt(768)

    // ln(normb) + dwconv c1 -> t1
    ln_stats_k<<<BATCH, 512>>>(Xin, mean, rstd);
    ln_conv_k<<<EB, 256>>>(Xin, mean, rstd, w.nbw, w.nbb, w.c1dw, w.c1db, t1);
    // pw c1 + relu + res(Xin) -> t2
    run_gemm<128, 64, false, false, false, true>(w.c1pw, 0, DIM, t1, SE, LC, t2, SE, LC,
                                                 w.c1pb, 0, nullptr, 0, Xin, SE, nullptr, 1.f, DIM, LC, DIM);
    // ln(norm1) + dwconv c2 -> t1
    ln_stats_k<<<BATCH, 512>>>(t2, mean, rstd);
    ln_conv_k<<<EB, 256>>>(t2, mean, rstd, w.n1w, w.n1b, w.c2dw, w.c2db, t1);
    // pw c2 + relu + res(t2) -> t3
    run_gemm<128, 64, false, false, false, true>(w.c2pw, 0, DIM, t1, SE, LC, t3, SE, LC,
                                                 w.c2pb, 0, nullptr, 0, t2, SE, nullptr, 1.f, DIM, LC, DIM);
    // ln(norm2) -> t1
    ln_stats_k<<<BATCH, 512>>>(t3, mean, rstd);
    ln_apply_k<<<EB4, 256>>>(t3, mean, rstd, w.n2w, w.n2b, t1);
    // q, k, v : (64 x 768) = t1^T @ W
    run_gemm<64, 128, true, false, false, false>(t1, SE, LC, w.wq, 0, DIM, q, SE, DIM,
                                                 nullptr, 0, nullptr, 0, nullptr, 0, nullptr, 1.f, LC, DIM, DIM);
    run_gemm<64, 128, true, false, false, false>(t1, SE, LC, w.wk, 0, DIM, kk, SE, DIM,
                                                 nullptr, 0, nullptr, 0, nullptr, 0, nullptr, 1.f, LC, DIM, DIM);
    run_gemm<64, 128, true, false, false, false>(t1, SE, LC, w.wv, 0, DIM, v, SE, DIM,
                                                 nullptr, 0, nullptr, 0, nullptr, 0, nullptr, 1.f, LC, DIM, DIM);
    // scores = q @ k^T * scale
    run_gemm<64, 64, false, true, false, false>(q, SE, DIM, kk, SE, DIM, scores, (long long)LC * LC, LC,
                                                nullptr, 0, nullptr, 0, nullptr, 0, nullptr, scale, LC, LC, DIM);
    softmax_rows_k<<<BATCH * LC, 128>>>(scores, scores, LC);
    // av = attn @ v -> t1
    run_gemm<64, 128, false, false, false, false>(scores, (long long)LC * LC, LC, v, SE, DIM, t1, SE, DIM,
                                                  nullptr, 0, nullptr, 0, nullptr, 0, nullptr, 1.f, LC, DIM, LC);
    // sa = (av @ wo)^T + res(t3) -> t2
    run_gemm<64, 128, false, false, true, false>(t1, SE, DIM, w.wo, 0, DIM, t2, SE, LC,
                                                 nullptr, 0, nullptr, 0, t3, SE, nullptr, 1.f, LC, DIM, DIM);
    // ln(norme) -> t1
    ln_stats_k<<<BATCH, 512>>>(t2, mean, rstd);
    ln_apply_k<<<EB4, 256>>>(t2, mean, rstd, w.nEw, w.nEb, t1);
    // fc + relu + res(t2) (+pe plane) -> Xout
    run_gemm<128, 64, false, false, false, true>(w.fcw, 0, DIM, t1, SE, LC, Xout, SE, LC,
                                                 w.fcb, 0, nullptr, 0, t2, SE, outPlane, 1.f, DIM, LC, DIM);
}

// ---------------------------------------------------------------------------
// Entry point
// ---------------------------------------------------------------------------
extern "C" void kernel_launch(void* const* d_in, const int* in_sizes, int n_in,
                              void* d_out, int out_size)
{
    (void)in_sizes; (void)n_in; (void)out_size;
    const float* x       = (const float*)d_in[0];
    const float* Wv      = (const float*)d_in[1];
    const float* rz_dw_w = (const float*)d_in[2];
    const float* rz_dw_b = (const float*)d_in[3];
    const float* rz_pw_w = (const float*)d_in[4];
    const float* rz_pw_b = (const float*)d_in[5];
    EncW w;
    w.c1dw = (const float*)d_in[6];  w.c1db = (const float*)d_in[7];
    w.c1pw = (const float*)d_in[8];  w.c1pb = (const float*)d_in[9];
    w.c2dw = (const float*)d_in[10]; w.c2db = (const float*)d_in[11];
    w.c2pw = (const float*)d_in[12]; w.c2pb = (const float*)d_in[13];
    w.wq   = (const float*)d_in[14]; w.wk   = (const float*)d_in[15];
    w.wv   = (const float*)d_in[16]; w.wo   = (const float*)d_in[17];
    w.fcw  = (const float*)d_in[18]; w.fcb  = (const float*)d_in[19];
    w.nbw  = (const float*)d_in[20]; w.nbb  = (const float*)d_in[21];
    w.n1w  = (const float*)d_in[22]; w.n1b  = (const float*)d_in[23];
    w.n2w  = (const float*)d_in[24]; w.n2b  = (const float*)d_in[25];
    w.nEw  = (const float*)d_in[26]; w.nEb  = (const float*)d_in[27];
    const float* fcf_w = (const float*)d_in[28];
    const float* fcf_b = (const float*)d_in[29];

    float* pool = nullptr;
    cudaGetSymbolAddress((void**)&pool, g_pool);

    float* c1s  = pool + OFF_C1;
    float* q2s  = pool + OFF_Q2;
    float* cw3  = pool + OFF_CW3;
    float* S    = pool + OFF_S;
    float* S1   = pool + OFF_S1;
    float* S2   = pool + OFF_S2;
    float* Abuf = pool + OFF_A;
    float* Tbuf = pool + OFF_T;
    float* Btb  = pool + OFF_BT;
    float* Y    = pool + OFF_Y;
    float* E[8];
    for (int i = 0; i < 8; i++) E[i] = pool + OFF_E0 + (long long)i * SZ_E;
    float* mean = pool + OFF_MEAN;
    float* rstd = pool + OFF_RSTD;
    float* pe   = pool + OFF_PE;

    pe_init_k<<<(DIM * LC + 255) / 256, 256>>>(pe);

    // ---- co-attention front end ----
    rowdot_k<<<(BATCH * LC * 32) / 256, 256>>>(x, Wv, c1s, LC, 0);
    rowdot_k<<<(BATCH * LQ * 32) / 256, 256>>>(x, Wv + DIM, q2s, LQ, LC);
    cw3_k<<<(int)(SZ_BD / 4 / 256), 256>>>(x, Wv + 2 * DIM, cw3);

    // S = (C*w3) @ Q^T + c1[:,None] + q2[None,:]
    run_gemm<64, 64, false, true, false, false>(
        cw3, (long long)LC * DIM, DIM,
        x + (long long)LC * DIM, (long long)SEQ * DIM, DIM,
        S, (long long)LC * LQ, LQ,
        c1s, LC, q2s, LQ, nullptr, 0, nullptr, 1.f, LC, LQ, DIM);

    softmax_rows_k<<<BATCH * LC, 128>>>(S, S1, LQ);
    softmax_cols_k<<<(BATCH * LQ + 255) / 256, 256>>>(S, S2);

    // A = S1 @ Q
    run_gemm<64, 128, false, false, false, false>(
        S1, (long long)LC * LQ, LQ,
        x + (long long)LC * DIM, (long long)SEQ * DIM, DIM,
        Abuf, (long long)LC * DIM, DIM,
        nullptr, 0, nullptr, 0, nullptr, 0, nullptr, 1.f, LC, DIM, LQ);

    // T = S1 @ S2^T
    run_gemm<64, 64, false, true, false, false>(
        S1, (long long)LC * LQ, LQ,
        S2, (long long)LC * LQ, LQ,
        Tbuf, (long long)LC * LC, LC,
        nullptr, 0, nullptr, 0, nullptr, 0, nullptr, 1.f, LC, LC, LQ);

    // Bt = T @ C
    run_gemm<64, 128, false, false, false, false>(
        Tbuf, (long long)LC * LC, LC,
        x, (long long)SEQ * DIM, DIM,
        Btb, (long long)LC * DIM, DIM,
        nullptr, 0, nullptr, 0, nullptr, 0, nullptr, 1.f, LC, DIM, LC);

    // fused concat-gather + depthwise k=5 -> Y (b, l, c)
    rz_dw_fuse_k<<<dim3(C4 / 256, LC, BATCH), 256>>>(x, Abuf, Btb, rz_dw_w, rz_dw_b, Y);

    // pointwise 3072 -> 768 (+bias +pe plane) -> E0 (b, d, l)
    run_gemm<128, 64, false, true, false, false>(
        rz_pw_w, 0, C4,
        Y, (long long)LC * C4, C4,
        E[0], (long long)DIM * LC, LC,
        rz_pw_b, 0, nullptr, 0, nullptr, 0, pe, 1.f, DIM, LC, C4);

    // ---- two encoder blocks ----
    enc_block(E[0], E[1], E[2], E[3], E[4], E[5], E[6], E[7], pe, mean, rstd, Tbuf, w);
    enc_block(E[7], E[1], E[2], E[3], E[4], E[5], E[6], E[0], nullptr, mean, rstd, Tbuf, w);

    // ---- final sigmoid head ----
    final_head_k<<<BATCH, 256>>>(E[0], fcf_w, fcf_b, (float*)d_out);
}

// round 4
// speedup vs baseline: 2.4652x; 1.9484x over previous
#include <cuda_runtime.h>
#include <cuda_bf16.h>
#include <math.h>
#include <stdint.h>

// ---------------------------------------------------------------------------
// Problem constants
// ---------------------------------------------------------------------------
namespace {
constexpr int BATCH = 128;
constexpr int LC    = 64;
constexpr int LQ    = 448;
constexpr int DIM   = 768;
constexpr int SEQ   = 512;
constexpr int C4    = 3072;

constexpr long long SZ_C1 = (long long)BATCH * LC;
constexpr long long SZ_Q2 = (long long)BATCH * LQ;
constexpr long long SZ_BD = (long long)BATCH * LC * DIM;   // 6291456
constexpr long long SZ_S  = (long long)BATCH * LC * LQ;
constexpr long long SZ_T  = (long long)BATCH * LC * LC;
constexpr long long SZ_Y  = (long long)BATCH * LC * C4;    // 25165824
constexpr long long SZ_E  = SZ_BD;
constexpr long long SE    = (long long)DIM * LC;           // 49152

constexpr long long OFF_C1  = 0;
constexpr long long OFF_Q2  = OFF_C1 + SZ_C1;
constexpr long long OFF_CW3 = OFF_Q2 + SZ_Q2;
constexpr long long OFF_S   = OFF_CW3 + SZ_BD;
constexpr long long OFF_S1  = OFF_S  + SZ_S;
constexpr long long OFF_S2  = OFF_S1 + SZ_S;
constexpr long long OFF_A   = OFF_S2 + SZ_S;
constexpr long long OFF_T   = OFF_A  + SZ_BD;
constexpr long long OFF_BT  = OFF_T  + SZ_T;
constexpr long long OFF_Y   = OFF_BT + SZ_BD;   // reused: Y hi/lo bf16 (fits: SZ_Y floats = 2*SZ_Y bf16)
constexpr long long OFF_E0  = OFF_Y  + SZ_Y;
constexpr long long OFF_MEAN = OFF_E0 + 8 * SZ_E;
constexpr long long OFF_RSTD = OFF_MEAN + 128;
constexpr long long OFF_PE   = OFF_RSTD + 128;
constexpr long long OFF_ACT  = OFF_PE + (long long)DIM * LC;   // 4 bf16 act buffers (SZ_BD each) = 2*SZ_BD floats
constexpr long long OFF_WB   = OFF_ACT + 2 * SZ_BD;
constexpr long long WB_FLOATS = (2LL * DIM * C4 + 14LL * DIM * DIM) / 2;
constexpr long long POOL_SZ  = OFF_WB + WB_FLOATS;
} // namespace

__device__ float g_pool[POOL_SZ];

// ---------------------------------------------------------------------------
// Family-portable tensor-core primitives (sm_80 baseline: work on target sm_103)
// ---------------------------------------------------------------------------
__device__ __forceinline__ uint32_t smem_u32(const void* p) {
    uint32_t a;
    asm("{ .reg .u64 t; cvta.to.shared.u64 t, %1; cvt.u32.u64 %0, t; }" : "=r"(a) : "l"(p));
    return a;
}
#define SW128(o) ((o) ^ (((o) >> 3) & 0x70))

__device__ __forceinline__ void cpa16(uint32_t dst, const void* src) {
    asm volatile("cp.async.cg.shared.global [%0], [%1], 16;" :: "r"(dst), "l"(src) : "memory");
}
__device__ __forceinline__ void cp_commit() {
    asm volatile("cp.async.commit_group;" ::: "memory");
}
__device__ __forceinline__ void cp_wait1() {
    asm volatile("cp.async.wait_group 1;" ::: "memory");
}
__device__ __forceinline__ void cp_wait0() {
    asm volatile("cp.async.wait_group 0;" ::: "memory");
}
__device__ __forceinline__ void ldsm4(uint32_t* r, uint32_t a) {
    asm volatile("ldmatrix.sync.aligned.m8n8.x4.shared.b16 {%0,%1,%2,%3}, [%4];"
        : "=r"(r[0]), "=r"(r[1]), "=r"(r[2]), "=r"(r[3]) : "r"(a));
}
__device__ __forceinline__ void mma_bf16(float* d, const uint32_t* a, uint32_t b0, uint32_t b1) {
    asm volatile("mma.sync.aligned.m16n8k16.row.col.f32.bf16.bf16.f32 "
        "{%0,%1,%2,%3}, {%4,%5,%6,%7}, {%8,%9}, {%0,%1,%2,%3};"
        : "+f"(d[0]), "+f"(d[1]), "+f"(d[2]), "+f"(d[3])
        : "r"(a[0]), "r"(a[1]), "r"(a[2]), "r"(a[3]), "r"(b0), "r"(b1));
}
__device__ __forceinline__ void bf16_split(float v, __nv_bfloat16& h, __nv_bfloat16& l) {
    h = __float2bfloat16(v);
    l = __float2bfloat16(v - __bfloat162float(h));
}

// ---------------------------------------------------------------------------
// Tensor-core GEMM via mma.sync (bf16 hi/lo split, fp32 accum)
// A: (BATCH*64, K) bf16 hi/lo, k-contiguous. B: (N, K) bf16 hi/lo, k-contiguous.
// CTA: 128 rows (2 batches) x 128 cols. K-chunks of 64, cp.async double-buffer.
// OMODE 0: O[b*sO + l*ldo + n] ; OMODE 1: O[b*sO + n*64 + l]
// ---------------------------------------------------------------------------
namespace {
constexpr int MT_TILE = 16384;                 // 128 rows x 128 bytes
constexpr int MT_SMEM = 2 * 4 * MT_TILE + 1024; // + alignment slack
}

template<int OMODE>
__global__ void __launch_bounds__(256, 1) mgemm_k(
    const __nv_bfloat16* __restrict__ Ah, const __nv_bfloat16* __restrict__ Al,
    const __nv_bfloat16* __restrict__ Bh, const __nv_bfloat16* __restrict__ Bl,
    float* __restrict__ O, long long sO, int ldo,
    const float* __restrict__ bias,
    const float* __restrict__ R, long long sR,
    const float* __restrict__ plane,
    int K, int relu)
{
    extern __shared__ char dsm[];
    const uint32_t tb = (smem_u32(dsm) + 1023u) & ~1023u;

    const int tid = threadIdx.x, lane = tid & 31, wid = tid >> 5;
    const int n0 = blockIdx.x * 128;
    const int rbase = blockIdx.y * 128;       // global A row base (= batch*64 + l)
    const int wm = wid & 1, wn = wid >> 1;    // warp tile: rows wm*64, cols wn*32

    float acc[4][4][4];
#pragma unroll
    for (int a = 0; a < 4; a++)
#pragma unroll
        for (int b = 0; b < 4; b++)
#pragma unroll
            for (int c = 0; c < 4; c++) acc[a][b][c] = 0.f;

    const int nch = K / 64;

    // ---- async copy of one chunk into buffer s ----
    auto copy_chunk = [&](int ci, int s) {
        const int k0 = ci * 64;
        const uint32_t tAh = tb + (s * 4 + 0) * MT_TILE;
        const uint32_t tAl = tb + (s * 4 + 1) * MT_TILE;
        const uint32_t tBh = tb + (s * 4 + 2) * MT_TILE;
        const uint32_t tBl = tb + (s * 4 + 3) * MT_TILE;
#pragma unroll
        for (int it = 0; it < 4; it++) {
            int idx = tid + it * 256;          // 0..1023
            int r = idx >> 3, c = idx & 7;
            uint32_t doff = SW128((uint32_t)(r * 128 + c * 16));
            long long aoff = (long long)(rbase + r) * K + k0 + c * 8;
            long long boff = (long long)(n0 + r) * K + k0 + c * 8;
            cpa16(tAh + doff, Ah + aoff);
            cpa16(tAl + doff, Al + aoff);
            cpa16(tBh + doff, Bh + boff);
            cpa16(tBl + doff, Bl + boff);
        }
    };

    copy_chunk(0, 0);
    cp_commit();

    const int rl = lane & 15, chalf = lane >> 4;

    for (int i = 0; i < nch; i++) {
        if (i + 1 < nch) { copy_chunk(i + 1, (i + 1) & 1); cp_commit(); cp_wait1(); }
        else             { cp_wait0(); }
        __syncthreads();

        const int s = i & 1;
        const uint32_t tAh = tb + (s * 4 + 0) * MT_TILE;
        const uint32_t tAl = tb + (s * 4 + 1) * MT_TILE;
        const uint32_t tBh = tb + (s * 4 + 2) * MT_TILE;
        const uint32_t tBl = tb + (s * 4 + 3) * MT_TILE;

#pragma unroll
        for (int ks = 0; ks < 4; ks++) {
            const uint32_t coff = (uint32_t)((ks * 2 + chalf) * 16);
            uint32_t ah[4][4], al[4][4], bh[2][4], bl[2][4];
#pragma unroll
            for (int mt = 0; mt < 4; mt++) {
                uint32_t off = SW128((uint32_t)((wm * 64 + mt * 16 + rl) * 128) + coff);
                ldsm4(ah[mt], tAh + off);
                ldsm4(al[mt], tAl + off);
            }
#pragma unroll
            for (int np = 0; np < 2; np++) {
                uint32_t off = SW128((uint32_t)((wn * 32 + np * 16 + rl) * 128) + coff);
                ldsm4(bh[np], tBh + off);
                ldsm4(bl[np], tBl + off);
            }
#pragma unroll
            for (int mt = 0; mt < 4; mt++)
#pragma unroll
                for (int np = 0; np < 2; np++)
#pragma unroll
                    for (int j = 0; j < 2; j++) {
                        float* d = acc[mt][np * 2 + j];
                        mma_bf16(d, ah[mt], bh[np][j], bh[np][j + 2]);
                        mma_bf16(d, ah[mt], bl[np][j], bl[np][j + 2]);
                        mma_bf16(d, al[mt], bh[np][j], bh[np][j + 2]);
                    }
        }
        __syncthreads();
    }

    // ---- epilogue ----
    const int b0 = blockIdx.y * 2;
#pragma unroll
    for (int mt = 0; mt < 4; mt++) {
        int row0 = wm * 64 + mt * 16 + (lane >> 2);
#pragma unroll
        for (int half = 0; half < 2; half++) {
            int row = row0 + half * 8;
            int bi = b0 + (row >> 6), l = row & 63;
            float* Ob = O + (long long)bi * sO;
            const float* Rb = R ? R + (long long)bi * sR : nullptr;
#pragma unroll
            for (int nn = 0; nn < 4; nn++) {
                int n = n0 + wn * 32 + nn * 8 + (lane & 3) * 2;
#pragma unroll
                for (int e = 0; e < 2; e++) {
                    float v = acc[mt][nn][half * 2 + e];
                    int nc = n + e;
                    if (bias) v += bias[nc];
                    if (relu) v = fmaxf(v, 0.f);
                    long long o = (OMODE == 1) ? ((long long)nc * 64 + l)
                                               : ((long long)l * ldo + nc);
                    if (Rb)    v += Rb[o];
                    if (plane) v += plane[o];
                    Ob[o] = v;
                }
            }
        }
    }
}

// ---------------------------------------------------------------------------
// SIMT GEMM (8x8 microtile, double-buffered) — front-end + scores/av
// Optional bf16 hi/lo secondary output (same index space as C).
// ---------------------------------------------------------------------------
template<int BM, int BN, bool TA, bool TB, bool OT, bool RELU>
__global__ void __launch_bounds__((BM/8)*(BN/8)) gemm8_k(
    const float* __restrict__ A, long long sA, int lda,
    const float* __restrict__ B, long long sB, int ldb,
    float* __restrict__ C, long long sC, int ldc,
    const float* __restrict__ bM, long long sbM,
    const float* __restrict__ bN, long long sbN,
    const float* __restrict__ R, long long sR,
    const float* __restrict__ plane,
    __nv_bfloat16* __restrict__ Ch, __nv_bfloat16* __restrict__ Cl,
    float alpha, int K)
{
    constexpr int THREADS = (BM / 8) * (BN / 8);
    constexpr int LA = BM * 16 / THREADS;
    constexpr int LB = BN * 16 / THREADS;

    const int bz = blockIdx.z;
    A += (long long)bz * sA;
    B += (long long)bz * sB;
    C += (long long)bz * sC;
    __nv_bfloat16* Chp = Ch ? Ch + (long long)bz * sC : nullptr;
    __nv_bfloat16* Clp = Cl ? Cl + (long long)bz * sC : nullptr;
    const float* bMp = bM ? bM + (long long)bz * sbM : nullptr;
    const float* bNp = bN ? bN + (long long)bz * sbN : nullptr;
    const float* Rp  = R  ? R  + (long long)bz * sR  : nullptr;

    const int m0 = blockIdx.y * BM;
    const int n0 = blockIdx.x * BN;

    __shared__ float As[2][16][BM + 4];
    __shared__ float Bs[2][16][BN + 4];

    const int tid = threadIdx.x;
    const int tx = tid % (BN / 8);
    const int ty = tid / (BN / 8);

    float acc[8][8];
#pragma unroll
    for (int r = 0; r < 8; r++)
#pragma unroll
        for (int c = 0; c < 8; c++) acc[r][c] = 0.f;

    float ra[LA], rb[LB];

#pragma unroll
    for (int i = 0; i < LA; i++) {
        int idx = tid + i * THREADS;
        if (TA) { int k = idx / BM, m = idx % BM; As[0][k][m] = A[(long long)k * lda + (m0 + m)]; }
        else    { int m = idx / 16, k = idx % 16; As[0][k][m] = A[(long long)(m0 + m) * lda + k]; }
    }
#pragma unroll
    for (int i = 0; i < LB; i++) {
        int idx = tid + i * THREADS;
        if (TB) { int n = idx / 16, k = idx % 16; Bs[0][k][n] = B[(long long)(n0 + n) * ldb + k]; }
        else    { int k = idx / BN, n = idx % BN; Bs[0][k][n] = B[(long long)k * ldb + (n0 + n)]; }
    }
    __syncthreads();

    int buf = 0;
    for (int k0 = 0; k0 < K; k0 += 16) {
        const bool more = (k0 + 16) < K;
        if (more) {
            const int kn = k0 + 16;
#pragma unroll
            for (int i = 0; i < LA; i++) {
                int idx = tid + i * THREADS;
                if (TA) { int k = idx / BM, m = idx % BM; ra[i] = A[(long long)(kn + k) * lda + (m0 + m)]; }
                else    { int m = idx / 16, k = idx % 16; ra[i] = A[(long long)(m0 + m) * lda + (kn + k)]; }
            }
#pragma unroll
            for (int i = 0; i < LB; i++) {
                int idx = tid + i * THREADS;
                if (TB) { int n = idx / 16, k = idx % 16; rb[i] = B[(long long)(n0 + n) * ldb + (kn + k)]; }
                else    { int k = idx / BN, n = idx % BN; rb[i] = B[(long long)(kn + k) * ldb + (n0 + n)]; }
            }
        }

#pragma unroll
        for (int k = 0; k < 16; k++) {
            float a[8], b[8];
            float4 t;
            t = *reinterpret_cast<const float4*>(&As[buf][k][ty * 8]);
            a[0] = t.x; a[1] = t.y; a[2] = t.z; a[3] = t.w;
            t = *reinterpret_cast<const float4*>(&As[buf][k][ty * 8 + 4]);
            a[4] = t.x; a[5] = t.y; a[6] = t.z; a[7] = t.w;
            t = *reinterpret_cast<const float4*>(&Bs[buf][k][tx * 8]);
            b[0] = t.x; b[1] = t.y; b[2] = t.z; b[3] = t.w;
            t = *reinterpret_cast<const float4*>(&Bs[buf][k][tx * 8 + 4]);
            b[4] = t.x; b[5] = t.y; b[6] = t.z; b[7] = t.w;
#pragma unroll
            for (int r = 0; r < 8; r++)
#pragma unroll
                for (int c = 0; c < 8; c++)
                    acc[r][c] = fmaf(a[r], b[c], acc[r][c]);
        }

        if (more) {
            int nb = buf ^ 1;
#pragma unroll
            for (int i = 0; i < LA; i++) {
                int idx = tid + i * THREADS;
                if (TA) { int k = idx / BM, m = idx % BM; As[nb][k][m] = ra[i]; }
                else    { int m = idx / 16, k = idx % 16; As[nb][k][m] = ra[i]; }
            }
#pragma unroll
            for (int i = 0; i < LB; i++) {
                int idx = tid + i * THREADS;
                if (TB) { int n = idx / 16, k = idx % 16; Bs[nb][k][n] = rb[i]; }
                else    { int k = idx / BN, n = idx % BN; Bs[nb][k][n] = rb[i]; }
            }
            __syncthreads();
            buf = nb;
        }
    }

#pragma unroll
    for (int r = 0; r < 8; r++) {
        int m = m0 + ty * 8 + r;
#pragma unroll
        for (int c = 0; c < 8; c++) {
            int n = n0 + tx * 8 + c;
            float v = acc[r][c] * alpha;
            if (bMp) v += bMp[m];
            if (bNp) v += bNp[n];
            if (RELU) v = fmaxf(v, 0.f);
            long long o = OT ? ((long long)n * ldc + m) : ((long long)m * ldc + n);
            if (Rp) v += Rp[o];
            if (plane) v += plane[o];
            C[o] = v;
            if (Chp) {
                __nv_bfloat16 h, lo;
                bf16_split(v, h, lo);
                Chp[o] = h; Clp[o] = lo;
            }
        }
    }
}

// ---------------------------------------------------------------------------
// Small kernels
// ---------------------------------------------------------------------------
__global__ void wsplit_k(const float* __restrict__ src, int ld, int trans,
                         long long total, int KK,
                         __nv_bfloat16* __restrict__ hi, __nv_bfloat16* __restrict__ lo)
{
    long long idx = (long long)blockIdx.x * 256 + threadIdx.x;
    if (idx >= total) return;
    int n = (int)(idx / KK), k = (int)(idx % KK);
    float v = trans ? src[(long long)k * ld + n] : src[(long long)n * ld + k];
    __nv_bfloat16 h, l;
    bf16_split(v, h, l);
    hi[idx] = h; lo[idx] = l;
}

__global__ void rowdot_k(const float* __restrict__ x, const float* __restrict__ w,
                         float* __restrict__ out, int rowsPerB, int rowOff)
{
    int warp = (blockIdx.x * blockDim.x + threadIdx.x) >> 5;
    int lane = threadIdx.x & 31;
    int b = warp / rowsPerB;
    int i = warp % rowsPerB;
    if (b >= BATCH) return;
    const float* src = x + ((long long)b * SEQ + rowOff + i) * DIM;
    float s = 0.f;
    for (int d = lane; d < DIM; d += 32) s += src[d] * w[d];
#pragma unroll
    for (int o = 16; o > 0; o >>= 1) s += __shfl_down_sync(0xffffffffu, s, o);
    if (lane == 0) out[warp] = s;
}

__global__ void cw3_k(const float* __restrict__ x, const float* __restrict__ w3,
                      float* __restrict__ cw3)
{
    long long i4 = (long long)blockIdx.x * 256 + threadIdx.x;
    if (i4 >= SZ_BD / 4) return;
    int d4 = (int)(i4 % (DIM / 4));
    long long row = i4 / (DIM / 4);
    long long b = row / LC, i = row % LC;
    float4 xv = reinterpret_cast<const float4*>(x)[((long long)b * SEQ + i) * (DIM / 4) + d4];
    float4 wv = reinterpret_cast<const float4*>(w3)[d4];
    float4 o; o.x = xv.x * wv.x; o.y = xv.y * wv.y; o.z = xv.z * wv.z; o.w = xv.w * wv.w;
    reinterpret_cast<float4*>(cw3)[i4] = o;
}

__global__ void softmax_rows_k(const float* __restrict__ in, float* __restrict__ out, int len)
{
    long long base = (long long)blockIdx.x * len;
    int t = threadIdx.x;
    __shared__ float sh[128];
    float m = -1e30f;
    for (int i = t; i < len; i += 128) m = fmaxf(m, in[base + i]);
    sh[t] = m; __syncthreads();
    for (int o = 64; o > 0; o >>= 1) { if (t < o) sh[t] = fmaxf(sh[t], sh[t + o]); __syncthreads(); }
    m = sh[0]; __syncthreads();
    float s = 0.f;
    for (int i = t; i < len; i += 128) { float e = expf(in[base + i] - m); out[base + i] = e; s += e; }
    sh[t] = s; __syncthreads();
    for (int o = 64; o > 0; o >>= 1) { if (t < o) sh[t] += sh[t + o]; __syncthreads(); }
    float inv = 1.f / sh[0];
    for (int i = t; i < len; i += 128) out[base + i] *= inv;
}

__global__ void softmax_cols_k(const float* __restrict__ S, float* __restrict__ S2)
{
    int idx = blockIdx.x * blockDim.x + threadIdx.x;
    if (idx >= BATCH * LQ) return;
    int b = idx / LQ, j = idx % LQ;
    long long base = (long long)b * LC * LQ + j;
    float m = -1e30f;
#pragma unroll 4
    for (int i = 0; i < LC; i++) m = fmaxf(m, S[base + (long long)i * LQ]);
    float s = 0.f;
#pragma unroll 4
    for (int i = 0; i < LC; i++) {
        float e = expf(S[base + (long long)i * LQ] - m);
        S2[base + (long long)i * LQ] = e;
        s += e;
    }
    float inv = 1.f / s;
#pragma unroll 4
    for (int i = 0; i < LC; i++) S2[base + (long long)i * LQ] *= inv;
}

// fused concat-gather + depthwise k=5 -> Y bf16 hi/lo, layout (b, l, c)
__global__ void rz_dw_fuse_k(const float* __restrict__ x, const float* __restrict__ Abuf,
                             const float* __restrict__ Btbuf,
                             const float* __restrict__ dww, const float* __restrict__ dwb,
                             __nv_bfloat16* __restrict__ Yh, __nv_bfloat16* __restrict__ Yl)
{
    int c = blockIdx.x * 256 + threadIdx.x;
    int l = blockIdx.y;
    int b = blockIdx.z;
    int g = c / DIM;
    int d = c % DIM;
    float acc = dwb[c];
#pragma unroll
    for (int t = 0; t < 5; t++) {
        int l2 = l + t - 2;
        if (l2 < 0 || l2 >= LC) continue;
        float v;
        long long xo = ((long long)b * SEQ + l2) * DIM + d;
        long long ao = ((long long)b * LC + l2) * DIM + d;
        if (g == 0)      v = x[xo];
        else if (g == 1) v = Abuf[ao];
        else if (g == 2) v = x[xo] * Abuf[ao];
        else             v = x[xo] * Btbuf[ao];
        acc = fmaf(v, dww[c * 5 + t], acc);
    }
    long long o = ((long long)b * LC + l) * C4 + c;
    __nv_bfloat16 h, lo;
    bf16_split(acc, h, lo);
    Yh[o] = h; Yl[o] = lo;
}

__global__ void pe_init_k(float* __restrict__ pe)
{
    int idx = blockIdx.x * 256 + threadIdx.x;
    if (idx >= DIM * LC) return;
    int d = idx / LC, l = idx % LC;
    float fd = (float)d;
    bool even = (d & 1) == 0;
    float freq = even ? powf(10000.f, -fd / 768.f)
                      : -powf(10000.f, (1.f - fd) / 768.f);
    float ph = even ? 0.f : 1.57079632679489662f;
    pe[idx] = sinf((float)l * freq + ph);
}

__global__ void ln_stats_k(const float* __restrict__ in, float* __restrict__ mean,
                           float* __restrict__ rstd)
{
    int b = blockIdx.x;
    const float4* p = reinterpret_cast<const float4*>(in + (long long)b * (DIM * LC));
    float s = 0.f, s2 = 0.f;
    for (int i = threadIdx.x; i < DIM * LC / 4; i += 512) {
        float4 v = p[i];
        s += v.x + v.y + v.z + v.w;
        s2 += v.x * v.x + v.y * v.y + v.z * v.z + v.w * v.w;
    }
    __shared__ float sh[512], sh2[512];
    sh[threadIdx.x] = s; sh2[threadIdx.x] = s2; __syncthreads();
    for (int o = 256; o > 0; o >>= 1) {
        if (threadIdx.x < o) { sh[threadIdx.x] += sh[threadIdx.x + o]; sh2[threadIdx.x] += sh2[threadIdx.x + o]; }
        __syncthreads();
    }
    if (threadIdx.x == 0) {
        float m = sh[0] / (float)(DIM * LC);
        float var = sh2[0] / (float)(DIM * LC) - m * m;
        mean[b] = m;
        rstd[b] = rsqrtf(var + 1e-5f);
    }
}

// fused ln + dwconv3 + transpose-convert: in (b,d,l) float -> out (b,l,d) bf16 hi/lo
__global__ void ln_conv_t_k(const float* __restrict__ in, const float* __restrict__ mean,
                            const float* __restrict__ rstd, const float* __restrict__ lw,
                            const float* __restrict__ lb, const float* __restrict__ cw,
                            const float* __restrict__ cb,
                            __nv_bfloat16* __restrict__ oh, __nv_bfloat16* __restrict__ ol)
{
    __shared__ float sm[32][65];
    int b = blockIdx.x, d0 = blockIdx.y * 32;
    float mu = mean[b], rs = rstd[b];
    const float* ib = in + (long long)b * (DIM * LC);
#pragma unroll
    for (int it = 0; it < 8; it++) {
        int idx = threadIdx.x + it * 256;
        int dd = idx >> 6, l = idx & 63;
        int d = d0 + dd;
        const float* rowp = ib + (long long)d * 64;
        int wb = d * 64;
        float a = cb[d];
#pragma unroll
        for (int t = 0; t < 3; t++) {
            int l2 = l + t - 1;
            if (l2 < 0 || l2 >= 64) continue;
            float v = (rowp[l2] - mu) * rs * lw[wb + l2] + lb[wb + l2];
            a = fmaf(v, cw[d * 3 + t], a);
        }
        sm[dd][l] = a;
    }
    __syncthreads();
    __nv_bfloat16* ohb = oh + (long long)b * 64 * 768;
    __nv_bfloat16* olb = ol + (long long)b * 64 * 768;
#pragma unroll
    for (int it = 0; it < 8; it++) {
        int idx = threadIdx.x + it * 256;
        int l = idx >> 5, dd = idx & 31;
        float v = sm[dd][l];
        __nv_bfloat16 h, lo;
        bf16_split(v, h, lo);
        long long o = (long long)l * 768 + d0 + dd;
        ohb[o] = h; olb[o] = lo;
    }
}

// fused ln + transpose-convert (no conv)
__global__ void ln_apply_t_k(const float* __restrict__ in, const float* __restrict__ mean,
                             const float* __restrict__ rstd, const float* __restrict__ lw,
                             const float* __restrict__ lb,
                             __nv_bfloat16* __restrict__ oh, __nv_bfloat16* __restrict__ ol)
{
    __shared__ float sm[32][65];
    int b = blockIdx.x, d0 = blockIdx.y * 32;
    float mu = mean[b], rs = rstd[b];
    const float* ib = in + (long long)b * (DIM * LC);
#pragma unroll
    for (int it = 0; it < 8; it++) {
        int idx = threadIdx.x + it * 256;
        int dd = idx >> 6, l = idx & 63;
        int d = d0 + dd;
        float v = (ib[(long long)d * 64 + l] - mu) * rs * lw[d * 64 + l] + lb[d * 64 + l];
        sm[dd][l] = v;
    }
    __syncthreads();
    __nv_bfloat16* ohb = oh + (long long)b * 64 * 768;
    __nv_bfloat16* olb = ol + (long long)b * 64 * 768;
#pragma unroll
    for (int it = 0; it < 8; it++) {
        int idx = threadIdx.x + it * 256;
        int l = idx >> 5, dd = idx & 31;
        float v = sm[dd][l];
        __nv_bfloat16 h, lo;
        bf16_split(v, h, lo);
        long long o = (long long)l * 768 + d0 + dd;
        ohb[o] = h; olb[o] = lo;
    }
}

__global__ void final_head_k(const float* __restrict__ X, const float* __restrict__ w,
                             const float* __restrict__ bias, float* __restrict__ out)
{
    int b = blockIdx.x;
    const float* p = X + (long long)b * (DIM * LC);
    float s = 0.f;
    for (int i = threadIdx.x; i < DIM * LC; i += 256) s = fmaf(p[i], w[i], s);
    __shared__ float sh[256];
    sh[threadIdx.x] = s; __syncthreads();
    for (int o = 128; o > 0; o >>= 1) {
        if (threadIdx.x < o) sh[threadIdx.x] += sh[threadIdx.x + o];
        __syncthreads();
    }
    if (threadIdx.x == 0) out[b] = 1.f / (1.f + expf(-(sh[0] + bias[0])));
}

// ---------------------------------------------------------------------------
// Host-side helpers
// ---------------------------------------------------------------------------
template<int BM, int BN, bool TA, bool TB, bool OT, bool RELU>
static inline void run_gemm(const float* A, long long sA, int lda,
                            const float* B, long long sB, int ldb,
                            float* C, long long sC, int ldc,
                            const float* bM, long long sbM,
                            const float* bN, long long sbN,
                            const float* R, long long sR,
                            const float* plane,
                            __nv_bfloat16* Ch, __nv_bfloat16* Cl,
                            float alpha, int M, int N, int K)
{
    dim3 grid(N / BN, M / BM, BATCH);
    gemm8_k<BM, BN, TA, TB, OT, RELU><<<grid, (BM / 8) * (BN / 8)>>>(
        A, sA, lda, B, sB, ldb, C, sC, ldc, bM, sbM, bN, sbN, R, sR, plane, Ch, Cl, alpha, K);
}

template<int OMODE>
static inline void run_mgemm(const __nv_bfloat16* Ah, const __nv_bfloat16* Al,
                             const __nv_bfloat16* Bh, const __nv_bfloat16* Bl,
                             float* O, long long sO, int ldo,
                             const float* bias,
                             const float* R, long long sR,
                             const float* plane,
                             int N, int K, int relu)
{
    cudaFuncSetAttribute((const void*)mgemm_k<OMODE>,
                         cudaFuncAttributeMaxDynamicSharedMemorySize, MT_SMEM);
    dim3 grid(N / 128, BATCH / 2);
    mgemm_k<OMODE><<<grid, 256, MT_SMEM>>>(
        Ah, Al, Bh, Bl, O, sO, ldo, bias, R, sR, plane, K, relu);
}

struct EncW {
    const float *c1dw, *c1db, *c1pw, *c1pb;
    const float *c2dw, *c2db, *c2pw, *c2pb;
    const float *wq, *wk, *wv, *wo;
    const float *fcw, *fcb;
    const float *nbw, *nbb, *n1w, *n1b, *n2w, *n2b, *nEw, *nEb;
};

struct BfW {
    __nv_bfloat16 *rzh, *rzl, *c1h, *c1l, *c2h, *c2l, *fch, *fcl;
    __nv_bfloat16 *qh, *ql, *kh, *kl, *vh, *vl, *oh, *ol;
};

static void enc_block(const float* Xin,
                      float* t1, float* t2, float* t3, float* q, float* kk, float* v,
                      float* Xout, const float* outPlane, float* mean, float* rstd,
                      float* scores, const EncW& w, const BfW& bw,
                      __nv_bfloat16* a1h, __nv_bfloat16* a1l,
                      __nv_bfloat16* a2h, __nv_bfloat16* a2l)
{
    const float scale = 0.03608439182435161f; // 1/sqrt(768)

    // ln(normb) + dwconv c1 -> ACT1 bf16 (b,l,d)
    ln_stats_k<<<BATCH, 512>>>(Xin, mean, rstd);
    ln_conv_t_k<<<dim3(BATCH, 24), 256>>>(Xin, mean, rstd, w.nbw, w.nbb, w.c1dw, w.c1db, a1h, a1l);
    // pw c1 (mma): relu(W@x + b) + Xin -> t2 (b,d,l)
    run_mgemm<1>(a1h, a1l, bw.c1h, bw.c1l, t2, SE, 64, w.c1pb, Xin, SE, nullptr, DIM, DIM, 1);
    // ln(norm1) + dwconv c2 -> ACT1
    ln_stats_k<<<BATCH, 512>>>(t2, mean, rstd);
    ln_conv_t_k<<<dim3(BATCH, 24), 256>>>(t2, mean, rstd, w.n1w, w.n1b, w.c2dw, w.c2db, a1h, a1l);
    // pw c2 (mma) -> t3
    run_mgemm<1>(a1h, a1l, bw.c2h, bw.c2l, t3, SE, 64, w.c2pb, t2, SE, nullptr, DIM, DIM, 1);
    // ln(norm2) -> ACT1
    ln_stats_k<<<BATCH, 512>>>(t3, mean, rstd);
    ln_apply_t_k<<<dim3(BATCH, 24), 256>>>(t3, mean, rstd, w.n2w, w.n2b, a1h, a1l);
    // q, k, v (mma): (b,l,768)
    run_mgemm<0>(a1h, a1l, bw.qh, bw.ql, q,  SE, DIM, nullptr, nullptr, 0, nullptr, DIM, DIM, 0);
    run_mgemm<0>(a1h, a1l, bw.kh, bw.kl, kk, SE, DIM, nullptr, nullptr, 0, nullptr, DIM, DIM, 0);
    run_mgemm<0>(a1h, a1l, bw.vh, bw.vl, v,  SE, DIM, nullptr, nullptr, 0, nullptr, DIM, DIM, 0);
    // scores = q @ k^T * scale (SIMT fp32)
    run_gemm<64, 64, false, true, false, false>(q, SE, DIM, kk, SE, DIM, scores, (long long)LC * LC, LC,
                                                nullptr, 0, nullptr, 0, nullptr, 0, nullptr, nullptr, nullptr,
                                                scale, LC, LC, DIM);
    softmax_rows_k<<<BATCH * LC, 128>>>(scores, scores, LC);
    // av = attn @ v -> t1 float + ACT2 bf16 (b,l,768)
    run_gemm<64, 128, false, false, false, false>(scores, (long long)LC * LC, LC, v, SE, DIM, t1, SE, DIM,
                                                  nullptr, 0, nullptr, 0, nullptr, 0, nullptr, a2h, a2l,
                                                  1.f, LC, DIM, LC);
    // sa = (av @ wo)^T + t3 -> t2 (mma, transposed store)
    run_mgemm<1>(a2h, a2l, bw.oh, bw.ol, t2, SE, 64, nullptr, t3, SE, nullptr, DIM, DIM, 0);
    // ln(norme) -> ACT1
    ln_stats_k<<<BATCH, 512>>>(t2, mean, rstd);
    ln_apply_t_k<<<dim3(BATCH, 24), 256>>>(t2, mean, rstd, w.nEw, w.nEb, a1h, a1l);
    // fc + relu + t2 (+pe) -> Xout (mma)
    run_mgemm<1>(a1h, a1l, bw.fch, bw.fcl, Xout, SE, 64, w.fcb, t2, SE, outPlane, DIM, DIM, 1);
}

// ---------------------------------------------------------------------------
// Entry point
// ---------------------------------------------------------------------------
extern "C" void kernel_launch(void* const* d_in, const int* in_sizes, int n_in,
                              void* d_out, int out_size)
{
    (void)in_sizes; (void)n_in; (void)out_size;
    const float* x       = (const float*)d_in[0];
    const float* Wv      = (const float*)d_in[1];
    const float* rz_dw_w = (const float*)d_in[2];
    const float* rz_dw_b = (const float*)d_in[3];
    const float* rz_pw_w = (const float*)d_in[4];
    const float* rz_pw_b = (const float*)d_in[5];
    EncW w;
    w.c1dw = (const float*)d_in[6];  w.c1db = (const float*)d_in[7];
    w.c1pw = (const float*)d_in[8];  w.c1pb = (const float*)d_in[9];
    w.c2dw = (const float*)d_in[10]; w.c2db = (const float*)d_in[11];
    w.c2pw = (const float*)d_in[12]; w.c2pb = (const float*)d_in[13];
    w.wq   = (const float*)d_in[14]; w.wk   = (const float*)d_in[15];
    w.wv   = (const float*)d_in[16]; w.wo   = (const float*)d_in[17];
    w.fcw  = (const float*)d_in[18]; w.fcb  = (const float*)d_in[19];
    w.nbw  = (const float*)d_in[20]; w.nbb  = (const float*)d_in[21];
    w.n1w  = (const float*)d_in[22]; w.n1b  = (const float*)d_in[23];
    w.n2w  = (const float*)d_in[24]; w.n2b  = (const float*)d_in[25];
    w.nEw  = (const float*)d_in[26]; w.nEb  = (const float*)d_in[27];
    const float* fcf_w = (const float*)d_in[28];
    const float* fcf_b = (const float*)d_in[29];

    float* pool = nullptr;
    cudaGetSymbolAddress((void**)&pool, g_pool);

    float* c1s  = pool + OFF_C1;
    float* q2s  = pool + OFF_Q2;
    float* cw3  = pool + OFF_CW3;
    float* S    = pool + OFF_S;
    float* S1   = pool + OFF_S1;
    float* S2   = pool + OFF_S2;
    float* Abuf = pool + OFF_A;
    float* Tbuf = pool + OFF_T;
    float* Btb  = pool + OFF_BT;
    float* E[8];
    for (int i = 0; i < 8; i++) E[i] = pool + OFF_E0 + (long long)i * SZ_E;
    float* mean = pool + OFF_MEAN;
    float* rstd = pool + OFF_RSTD;
    float* pe   = pool + OFF_PE;

    __nv_bfloat16* Yh = (__nv_bfloat16*)(pool + OFF_Y);
    __nv_bfloat16* Yl = Yh + SZ_Y;
    __nv_bfloat16* actb = (__nv_bfloat16*)(pool + OFF_ACT);
    __nv_bfloat16* a1h = actb;
    __nv_bfloat16* a1l = a1h + SZ_BD;
    __nv_bfloat16* a2h = a1l + SZ_BD;
    __nv_bfloat16* a2l = a2h + SZ_BD;

    BfW bw;
    {
        __nv_bfloat16* p = (__nv_bfloat16*)(pool + OFF_WB);
        bw.rzh = p; p += (long long)DIM * C4;
        bw.rzl = p; p += (long long)DIM * C4;
        bw.c1h = p; p += (long long)DIM * DIM;
        bw.c1l = p; p += (long long)DIM * DIM;
        bw.c2h = p; p += (long long)DIM * DIM;
        bw.c2l = p; p += (long long)DIM * DIM;
        bw.fch = p; p += (long long)DIM * DIM;
        bw.fcl = p; p += (long long)DIM * DIM;
        bw.qh  = p; p += (long long)DIM * DIM;
        bw.ql  = p; p += (long long)DIM * DIM;
        bw.kh  = p; p += (long long)DIM * DIM;
        bw.kl  = p; p += (long long)DIM * DIM;
        bw.vh  = p; p += (long long)DIM * DIM;
        bw.vl  = p; p += (long long)DIM * DIM;
        bw.oh  = p; p += (long long)DIM * DIM;
        bw.ol  = p;
    }

    // ---- weight conversion (bf16 hi/lo, n x k, k-contiguous) ----
    {
        long long trz = (long long)DIM * C4;
        long long tsq = (long long)DIM * DIM;
        int gs = (int)((tsq + 255) / 256);
        wsplit_k<<<(int)((trz + 255) / 256), 256>>>(rz_pw_w, C4, 0, trz, C4, bw.rzh, bw.rzl);
        wsplit_k<<<gs, 256>>>(w.c1pw, DIM, 0, tsq, DIM, bw.c1h, bw.c1l);
        wsplit_k<<<gs, 256>>>(w.c2pw, DIM, 0, tsq, DIM, bw.c2h, bw.c2l);
        wsplit_k<<<gs, 256>>>(w.fcw,  DIM, 0, tsq, DIM, bw.fch, bw.fcl);
        wsplit_k<<<gs, 256>>>(w.wq,   DIM, 1, tsq, DIM, bw.qh,  bw.ql);
        wsplit_k<<<gs, 256>>>(w.wk,   DIM, 1, tsq, DIM, bw.kh,  bw.kl);
        wsplit_k<<<gs, 256>>>(w.wv,   DIM, 1, tsq, DIM, bw.vh,  bw.vl);
        wsplit_k<<<gs, 256>>>(w.wo,   DIM, 1, tsq, DIM, bw.oh,  bw.ol);
    }

    pe_init_k<<<(DIM * LC + 255) / 256, 256>>>(pe);

    // ---- co-attention front end (SIMT fp32) ----
    rowdot_k<<<(BATCH * LC * 32) / 256, 256>>>(x, Wv, c1s, LC, 0);
    rowdot_k<<<(BATCH * LQ * 32) / 256, 256>>>(x, Wv + DIM, q2s, LQ, LC);
    cw3_k<<<(int)(SZ_BD / 4 / 256), 256>>>(x, Wv + 2 * DIM, cw3);

    run_gemm<64, 64, false, true, false, false>(
        cw3, (long long)LC * DIM, DIM,
        x + (long long)LC * DIM, (long long)SEQ * DIM, DIM,
        S, (long long)LC * LQ, LQ,
        c1s, LC, q2s, LQ, nullptr, 0, nullptr, nullptr, nullptr, 1.f, LC, LQ, DIM);

    softmax_rows_k<<<BATCH * LC, 128>>>(S, S1, LQ);
    softmax_cols_k<<<(BATCH * LQ + 255) / 256, 256>>>(S, S2);

    run_gemm<64, 128, false, false, false, false>(
        S1, (long long)LC * LQ, LQ,
        x + (long long)LC * DIM, (long long)SEQ * DIM, DIM,
        Abuf, (long long)LC * DIM, DIM,
        nullptr, 0, nullptr, 0, nullptr, 0, nullptr, nullptr, nullptr, 1.f, LC, DIM, LQ);

    run_gemm<64, 64, false, true, false, false>(
        S1, (long long)LC * LQ, LQ,
        S2, (long long)LC * LQ, LQ,
        Tbuf, (long long)LC * LC, LC,
        nullptr, 0, nullptr, 0, nullptr, 0, nullptr, nullptr, nullptr, 1.f, LC, LC, LQ);

    run_gemm<64, 128, false, false, false, false>(
        Tbuf, (long long)LC * LC, LC,
        x, (long long)SEQ * DIM, DIM,
        Btb, (long long)LC * DIM, DIM,
        nullptr, 0, nullptr, 0, nullptr, 0, nullptr, nullptr, nullptr, 1.f, LC, DIM, LC);

    // fused concat-gather + depthwise k=5 -> Y bf16 hi/lo (b,l,c)
    rz_dw_fuse_k<<<dim3(C4 / 256, LC, BATCH), 256>>>(x, Abuf, Btb, rz_dw_w, rz_dw_b, Yh, Yl);

    // pointwise 3072 -> 768 (mma): +bias +pe -> E0 (b,d,l)
    run_mgemm<1>(Yh, Yl, bw.rzh, bw.rzl, E[0], SE, 64, rz_pw_b, nullptr, 0, pe, DIM, C4, 0);

    // ---- two encoder blocks ----
    enc_block(E[0], E[1], E[2], E[3], E[4], E[5], E[6], E[7], pe, mean, rstd, Tbuf, w, bw,
              a1h, a1l, a2h, a2l);
    enc_block(E[7], E[1], E[2], E[3], E[4], E[5], E[6], E[0], nullptr, mean, rstd, Tbuf, w, bw,
              a1h, a1l, a2h, a2l);

    // ---- final sigmoid head ----
    final_head_k<<<BATCH, 256>>>(E[0], fcf_w, fcf_b, (float*)d_out);
}

// round 5
// speedup vs baseline: 2.5463x; 1.0329x over previous
#include <cuda_runtime.h>
#include <cuda_bf16.h>
#include <math.h>
#include <stdint.h>

// ---------------------------------------------------------------------------
// Problem constants
// ---------------------------------------------------------------------------
namespace {
constexpr int BATCH = 128;
constexpr int LC    = 64;
constexpr int LQ    = 448;
constexpr int DIM   = 768;
constexpr int SEQ   = 512;
constexpr int C4    = 3072;

constexpr long long SZ_C1 = (long long)BATCH * LC;
constexpr long long SZ_Q2 = (long long)BATCH * LQ;
constexpr long long SZ_BD = (long long)BATCH * LC * DIM;   // 6291456
constexpr long long SZ_S  = (long long)BATCH * LC * LQ;    // 3670016
constexpr long long SZ_T  = (long long)BATCH * LC * LC;
constexpr long long SZ_Y  = (long long)BATCH * LC * C4;
constexpr long long SZ_E  = SZ_BD;
constexpr long long SZ_Q  = (long long)BATCH * LQ * DIM;   // 44040192
constexpr long long SE    = (long long)DIM * LC;

constexpr long long OFF_C1  = 0;
constexpr long long OFF_Q2  = OFF_C1 + SZ_C1;
constexpr long long OFF_CW3 = OFF_Q2 + SZ_Q2;    // cw3 bf16 hi/lo (SZ_BD float slots)
constexpr long long OFF_S   = OFF_CW3 + SZ_BD;
constexpr long long OFF_S1  = OFF_S  + SZ_S;     // S1 bf16 hi/lo
constexpr long long OFF_S2  = OFF_S1 + SZ_S;     // S2 bf16 hi/lo
constexpr long long OFF_A   = OFF_S2 + SZ_S;
constexpr long long OFF_T   = OFF_A  + SZ_BD;
constexpr long long OFF_BT  = OFF_T  + SZ_T;
constexpr long long OFF_Y   = OFF_BT + SZ_BD;    // Y bf16 hi/lo
constexpr long long OFF_E0  = OFF_Y  + SZ_Y;
constexpr long long OFF_MEAN = OFF_E0 + 8 * SZ_E;
constexpr long long OFF_RSTD = OFF_MEAN + 128;
constexpr long long OFF_PE   = OFF_RSTD + 128;
constexpr long long OFF_ACT  = OFF_PE + (long long)DIM * LC;  // 4 bf16 act buffers
constexpr long long OFF_WB   = OFF_ACT + 2 * SZ_BD;
constexpr long long WB_FLOATS = (2LL * DIM * C4 + 14LL * DIM * DIM) / 2;
constexpr long long OFF_QS   = OFF_WB + WB_FLOATS;   // Q bf16 hi/lo (b,448,768)
constexpr long long OFF_QT   = OFF_QS + SZ_Q;        // Q^T bf16 hi/lo (b,768,448)
constexpr long long POOL_SZ  = OFF_QT + SZ_Q;
} // namespace

__device__ float g_pool[POOL_SZ];

// ---------------------------------------------------------------------------
// Family-portable tensor-core primitives (sm_80 baseline; valid on target sm_103)
// ---------------------------------------------------------------------------
__device__ __forceinline__ uint32_t smem_u32(const void* p) {
    uint32_t a;
    asm("{ .reg .u64 t; cvta.to.shared.u64 t, %1; cvt.u32.u64 %0, t; }" : "=r"(a) : "l"(p));
    return a;
}
#define SW128(o) ((o) ^ (((o) >> 3) & 0x70))

__device__ __forceinline__ void cpa16(uint32_t dst, const void* src) {
    asm volatile("cp.async.cg.shared.global [%0], [%1], 16;" :: "r"(dst), "l"(src) : "memory");
}
__device__ __forceinline__ void cp_commit() {
    asm volatile("cp.async.commit_group;" ::: "memory");
}
__device__ __forceinline__ void cp_wait1() {
    asm volatile("cp.async.wait_group 1;" ::: "memory");
}
__device__ __forceinline__ void cp_wait0() {
    asm volatile("cp.async.wait_group 0;" ::: "memory");
}
__device__ __forceinline__ void ldsm4(uint32_t* r, uint32_t a) {
    asm volatile("ldmatrix.sync.aligned.m8n8.x4.shared.b16 {%0,%1,%2,%3}, [%4];"
        : "=r"(r[0]), "=r"(r[1]), "=r"(r[2]), "=r"(r[3]) : "r"(a));
}
__device__ __forceinline__ void mma_bf16(float* d, const uint32_t* a, uint32_t b0, uint32_t b1) {
    asm volatile("mma.sync.aligned.m16n8k16.row.col.f32.bf16.bf16.f32 "
        "{%0,%1,%2,%3}, {%4,%5,%6,%7}, {%8,%9}, {%0,%1,%2,%3};"
        : "+f"(d[0]), "+f"(d[1]), "+f"(d[2]), "+f"(d[3])
        : "r"(a[0]), "r"(a[1]), "r"(a[2]), "r"(a[3]), "r"(b0), "r"(b1));
}
__device__ __forceinline__ void bf16_split(float v, __nv_bfloat16& h, __nv_bfloat16& l) {
    h = __float2bfloat16(v);
    l = __float2bfloat16(v - __bfloat162float(h));
}

// ---------------------------------------------------------------------------
// mgemm: batch-shared-B tensor GEMM (bf16 hi/lo 3-term, fp32 accum)
// A: (BATCH*64, K) hi/lo k-contig; B: (N, K) hi/lo k-contig (weights).
// CTA = 128 rows (2 batches) x 128 cols; K-chunks of 64; 3-stage cp.async.
// OMODE 0: O[b*sO + l*ldo + n] ; OMODE 1: O[b*sO + n*64 + l]
// ---------------------------------------------------------------------------
namespace {
constexpr int MT_TILE = 16384;                  // 128 rows x 128 B
constexpr int MT_SMEM = 3 * 4 * MT_TILE + 1024;
constexpr int PG_TILE = 8192;                   // 64 rows x 128 B
constexpr int PG_SMEM = 2 * 4 * PG_TILE + 1024;
}

template<int OMODE>
__global__ void __launch_bounds__(256, 1) mgemm_k(
    const __nv_bfloat16* __restrict__ Ah, const __nv_bfloat16* __restrict__ Al,
    const __nv_bfloat16* __restrict__ Bh, const __nv_bfloat16* __restrict__ Bl,
    float* __restrict__ O, long long sO, int ldo,
    const float* __restrict__ bias,
    const float* __restrict__ R, long long sR,
    const float* __restrict__ plane,
    int K, int relu)
{
    extern __shared__ char dsm[];
    const uint32_t tb = (smem_u32(dsm) + 1023u) & ~1023u;

    const int tid = threadIdx.x, lane = tid & 31, wid = tid >> 5;
    const int n0 = blockIdx.x * 128;
    const int rbase = blockIdx.y * 128;
    const int wm = wid & 1, wn = wid >> 1;   // warp tile 64x32

    float acc[4][4][4];
#pragma unroll
    for (int a = 0; a < 4; a++)
#pragma unroll
        for (int b = 0; b < 4; b++)
#pragma unroll
            for (int c = 0; c < 4; c++) acc[a][b][c] = 0.f;

    const int nch = K / 64;

    auto copy_chunk = [&](int ci, int s) {
        const int k0 = ci * 64;
        const uint32_t tAh = tb + (s * 4 + 0) * MT_TILE;
        const uint32_t tAl = tb + (s * 4 + 1) * MT_TILE;
        const uint32_t tBh = tb + (s * 4 + 2) * MT_TILE;
        const uint32_t tBl = tb + (s * 4 + 3) * MT_TILE;
#pragma unroll
        for (int it = 0; it < 4; it++) {
            int idx = tid + it * 256;
            int r = idx >> 3, c = idx & 7;
            uint32_t doff = SW128((uint32_t)(r * 128 + c * 16));
            long long aoff = (long long)(rbase + r) * K + k0 + c * 8;
            long long boff = (long long)(n0 + r) * K + k0 + c * 8;
            cpa16(tAh + doff, Ah + aoff);
            cpa16(tAl + doff, Al + aoff);
            cpa16(tBh + doff, Bh + boff);
            cpa16(tBl + doff, Bl + boff);
        }
    };

    copy_chunk(0, 0); cp_commit();
    copy_chunk(1, 1); cp_commit();

    const int rl = lane & 15, chalf = lane >> 4;

    for (int i = 0; i < nch; i++) {
        if (i + 1 < nch) cp_wait1(); else cp_wait0();
        __syncthreads();
        if (i + 2 < nch) { copy_chunk(i + 2, (i + 2) % 3); cp_commit(); }

        const int s = i % 3;
        const uint32_t tAh = tb + (s * 4 + 0) * MT_TILE;
        const uint32_t tAl = tb + (s * 4 + 1) * MT_TILE;
        const uint32_t tBh = tb + (s * 4 + 2) * MT_TILE;
        const uint32_t tBl = tb + (s * 4 + 3) * MT_TILE;

#pragma unroll
        for (int ks = 0; ks < 4; ks++) {
            const uint32_t coff = (uint32_t)((ks * 2 + chalf) * 16);
            uint32_t ah[4][4], al[4][4], bh[2][4], bl[2][4];
#pragma unroll
            for (int mt = 0; mt < 4; mt++) {
                uint32_t off = SW128((uint32_t)((wm * 64 + mt * 16 + rl) * 128) + coff);
                ldsm4(ah[mt], tAh + off);
                ldsm4(al[mt], tAl + off);
            }
#pragma unroll
            for (int np = 0; np < 2; np++) {
                uint32_t off = SW128((uint32_t)((wn * 32 + np * 16 + rl) * 128) + coff);
                ldsm4(bh[np], tBh + off);
                ldsm4(bl[np], tBl + off);
            }
#pragma unroll
            for (int mt = 0; mt < 4; mt++)
#pragma unroll
                for (int np = 0; np < 2; np++)
#pragma unroll
                    for (int j = 0; j < 2; j++) {
                        float* d = acc[mt][np * 2 + j];
                        mma_bf16(d, ah[mt], bh[np][j], bh[np][j + 2]);
                        mma_bf16(d, ah[mt], bl[np][j], bl[np][j + 2]);
                        mma_bf16(d, al[mt], bh[np][j], bh[np][j + 2]);
                    }
        }
    }

    const int b0 = blockIdx.y * 2;
#pragma unroll
    for (int mt = 0; mt < 4; mt++) {
        int row0 = wm * 64 + mt * 16 + (lane >> 2);
#pragma unroll
        for (int half = 0; half < 2; half++) {
            int row = row0 + half * 8;
            int bi = b0 + (row >> 6), l = row & 63;
            float* Ob = O + (long long)bi * sO;
            const float* Rb = R ? R + (long long)bi * sR : nullptr;
#pragma unroll
            for (int nn = 0; nn < 4; nn++) {
                int n = n0 + wn * 32 + nn * 8 + (lane & 3) * 2;
#pragma unroll
                for (int e = 0; e < 2; e++) {
                    float v = acc[mt][nn][half * 2 + e];
                    int nc = n + e;
                    if (bias) v += bias[nc];
                    if (relu) v = fmaxf(v, 0.f);
                    long long o = (OMODE == 1) ? ((long long)nc * 64 + l)
                                               : ((long long)l * ldo + nc);
                    if (Rb)    v += Rb[o];
                    if (plane) v += plane[o];
                    Ob[o] = v;
                }
            }
        }
    }
}

// ---------------------------------------------------------------------------
// pgemm: per-batch-A, per-batch-B tensor GEMM (bf16 hi/lo 3-term, fp32 accum)
// A: (b) 64 x K hi/lo k-contig; B: (b) Nb x K hi/lo k-contig.
// CTA = 64 x 64 tile, grid (N/64, BATCH). 2-stage cp.async, 1 sync/chunk.
// Out: O[b*sO + m*ldo + n] (+bM[b] per-row, +bN[b] per-col)
// ---------------------------------------------------------------------------
__global__ void __launch_bounds__(256, 1) pgemm_k(
    const __nv_bfloat16* __restrict__ Ah, const __nv_bfloat16* __restrict__ Al, long long sA,
    const __nv_bfloat16* __restrict__ Bh, const __nv_bfloat16* __restrict__ Bl, long long sB,
    float* __restrict__ O, long long sO, int ldo,
    const float* __restrict__ bM, long long sbM,
    const float* __restrict__ bN, long long sbN,
    int K)
{
    extern __shared__ char dsm[];
    const uint32_t tb = (smem_u32(dsm) + 1023u) & ~1023u;

    const int tid = threadIdx.x, lane = tid & 31, wid = tid >> 5;
    const int n0 = blockIdx.x * 64;
    const int b  = blockIdx.y;
    const int wm = wid >> 1, wn = wid & 1;    // warp tile 16x32

    const __nv_bfloat16* Ahb = Ah + (long long)b * sA;
    const __nv_bfloat16* Alb = Al + (long long)b * sA;
    const __nv_bfloat16* Bhb = Bh + (long long)b * sB + (long long)n0 * K;
    const __nv_bfloat16* Blb = Bl + (long long)b * sB + (long long)n0 * K;

    float acc[4][4];
#pragma unroll
    for (int a = 0; a < 4; a++)
#pragma unroll
        for (int c = 0; c < 4; c++) acc[a][c] = 0.f;

    const int nch = K / 64;

    auto copy_chunk = [&](int ci, int s) {
        const int k0 = ci * 64;
        const uint32_t tAh = tb + (s * 4 + 0) * PG_TILE;
        const uint32_t tAl = tb + (s * 4 + 1) * PG_TILE;
        const uint32_t tBh = tb + (s * 4 + 2) * PG_TILE;
        const uint32_t tBl = tb + (s * 4 + 3) * PG_TILE;
#pragma unroll
        for (int it = 0; it < 2; it++) {
            int idx = tid + it * 256;          // 0..511
            int r = idx >> 3, c = idx & 7;
            uint32_t doff = SW128((uint32_t)(r * 128 + c * 16));
            long long off = (long long)r * K + k0 + c * 8;
            cpa16(tAh + doff, Ahb + off);
            cpa16(tAl + doff, Alb + off);
            cpa16(tBh + doff, Bhb + off);
            cpa16(tBl + doff, Blb + off);
        }
    };

    copy_chunk(0, 0); cp_commit();

    const int rl = lane & 15, chalf = lane >> 4;

    for (int i = 0; i < nch; i++) {
        cp_wait0();
        __syncthreads();
        if (i + 1 < nch) { copy_chunk(i + 1, (i + 1) & 1); cp_commit(); }

        const int s = i & 1;
        const uint32_t tAh = tb + (s * 4 + 0) * PG_TILE;
        const uint32_t tAl = tb + (s * 4 + 1) * PG_TILE;
        const uint32_t tBh = tb + (s * 4 + 2) * PG_TILE;
        const uint32_t tBl = tb + (s * 4 + 3) * PG_TILE;

#pragma unroll
        for (int ks = 0; ks < 4; ks++) {
            const uint32_t coff = (uint32_t)((ks * 2 + chalf) * 16);
            uint32_t ah[4], al[4], bh[2][4], bl[2][4];
            {
                uint32_t off = SW128((uint32_t)((wm * 16 + rl) * 128) + coff);
                ldsm4(ah, tAh + off);
                ldsm4(al, tAl + off);
            }
#pragma unroll
            for (int np = 0; np < 2; np++) {
                uint32_t off = SW128((uint32_t)((wn * 32 + np * 16 + rl) * 128) + coff);
                ldsm4(bh[np], tBh + off);
                ldsm4(bl[np], tBl + off);
            }
#pragma unroll
            for (int np = 0; np < 2; np++)
#pragma unroll
                for (int j = 0; j < 2; j++) {
                    float* d = acc[np * 2 + j];
                    mma_bf16(d, ah, bh[np][j], bh[np][j + 2]);
                    mma_bf16(d, ah, bl[np][j], bl[np][j + 2]);
                    mma_bf16(d, al, bh[np][j], bh[np][j + 2]);
                }
        }
    }

    float* Ob = O + (long long)b * sO;
    const float* bMp = bM ? bM + (long long)b * sbM : nullptr;
    const float* bNp = bN ? bN + (long long)b * sbN : nullptr;
#pragma unroll
    for (int half = 0; half < 2; half++) {
        int row = wm * 16 + (lane >> 2) + half * 8;
#pragma unroll
        for (int nn = 0; nn < 4; nn++) {
            int n = n0 + wn * 32 + nn * 8 + (lane & 3) * 2;
#pragma unroll
            for (int e = 0; e < 2; e++) {
                float v = acc[nn][half * 2 + e];
                int nc = n + e;
                if (bMp) v += bMp[row];
                if (bNp) v += bNp[nc];
                Ob[(long long)row * ldo + nc] = v;
            }
        }
    }
}

// ---------------------------------------------------------------------------
// SIMT GEMM (8x8 microtile) — scores/av/Bt only
// ---------------------------------------------------------------------------
template<int BM, int BN, bool TA, bool TB, bool OT, bool RELU>
__global__ void __launch_bounds__((BM/8)*(BN/8)) gemm8_k(
    const float* __restrict__ A, long long sA, int lda,
    const float* __restrict__ B, long long sB, int ldb,
    float* __restrict__ C, long long sC, int ldc,
    const float* __restrict__ bM, long long sbM,
    const float* __restrict__ bN, long long sbN,
    const float* __restrict__ R, long long sR,
    const float* __restrict__ plane,
    __nv_bfloat16* __restrict__ Ch, __nv_bfloat16* __restrict__ Cl,
    float alpha, int K)
{
    constexpr int THREADS = (BM / 8) * (BN / 8);
    constexpr int LA = BM * 16 / THREADS;
    constexpr int LB = BN * 16 / THREADS;

    const int bz = blockIdx.z;
    A += (long long)bz * sA;
    B += (long long)bz * sB;
    C += (long long)bz * sC;
    __nv_bfloat16* Chp = Ch ? Ch + (long long)bz * sC : nullptr;
    __nv_bfloat16* Clp = Cl ? Cl + (long long)bz * sC : nullptr;
    const float* bMp = bM ? bM + (long long)bz * sbM : nullptr;
    const float* bNp = bN ? bN + (long long)bz * sbN : nullptr;
    const float* Rp  = R  ? R  + (long long)bz * sR  : nullptr;

    const int m0 = blockIdx.y * BM;
    const int n0 = blockIdx.x * BN;

    __shared__ float As[2][16][BM + 4];
    __shared__ float Bs[2][16][BN + 4];

    const int tid = threadIdx.x;
    const int tx = tid % (BN / 8);
    const int ty = tid / (BN / 8);

    float acc[8][8];
#pragma unroll
    for (int r = 0; r < 8; r++)
#pragma unroll
        for (int c = 0; c < 8; c++) acc[r][c] = 0.f;

    float ra[LA], rb[LB];

#pragma unroll
    for (int i = 0; i < LA; i++) {
        int idx = tid + i * THREADS;
        if (TA) { int k = idx / BM, m = idx % BM; As[0][k][m] = A[(long long)k * lda + (m0 + m)]; }
        else    { int m = idx / 16, k = idx % 16; As[0][k][m] = A[(long long)(m0 + m) * lda + k]; }
    }
#pragma unroll
    for (int i = 0; i < LB; i++) {
        int idx = tid + i * THREADS;
        if (TB) { int n = idx / 16, k = idx % 16; Bs[0][k][n] = B[(long long)(n0 + n) * ldb + k]; }
        else    { int k = idx / BN, n = idx % BN; Bs[0][k][n] = B[(long long)k * ldb + (n0 + n)]; }
    }
    __syncthreads();

    int buf = 0;
    for (int k0 = 0; k0 < K; k0 += 16) {
        const bool more = (k0 + 16) < K;
        if (more) {
            const int kn = k0 + 16;
#pragma unroll
            for (int i = 0; i < LA; i++) {
                int idx = tid + i * THREADS;
                if (TA) { int k = idx / BM, m = idx % BM; ra[i] = A[(long long)(kn + k) * lda + (m0 + m)]; }
                else    { int m = idx / 16, k = idx % 16; ra[i] = A[(long long)(m0 + m) * lda + (kn + k)]; }
            }
#pragma unroll
            for (int i = 0; i < LB; i++) {
                int idx = tid + i * THREADS;
                if (TB) { int n = idx / 16, k = idx % 16; rb[i] = B[(long long)(n0 + n) * ldb + (kn + k)]; }
                else    { int k = idx / BN, n = idx % BN; rb[i] = B[(long long)(kn + k) * ldb + (n0 + n)]; }
            }
        }

#pragma unroll
        for (int k = 0; k < 16; k++) {
            float a[8], b[8];
            float4 t;
            t = *reinterpret_cast<const float4*>(&As[buf][k][ty * 8]);
            a[0] = t.x; a[1] = t.y; a[2] = t.z; a[3] = t.w;
            t = *reinterpret_cast<const float4*>(&As[buf][k][ty * 8 + 4]);
            a[4] = t.x; a[5] = t.y; a[6] = t.z; a[7] = t.w;
            t = *reinterpret_cast<const float4*>(&Bs[buf][k][tx * 8]);
            b[0] = t.x; b[1] = t.y; b[2] = t.z; b[3] = t.w;
            t = *reinterpret_cast<const float4*>(&Bs[buf][k][tx * 8 + 4]);
            b[4] = t.x; b[5] = t.y; b[6] = t.z; b[7] = t.w;
#pragma unroll
            for (int r = 0; r < 8; r++)
#pragma unroll
                for (int c = 0; c < 8; c++)
                    acc[r][c] = fmaf(a[r], b[c], acc[r][c]);
        }

        if (more) {
            int nb = buf ^ 1;
#pragma unroll
            for (int i = 0; i < LA; i++) {
                int idx = tid + i * THREADS;
                if (TA) { int k = idx / BM, m = idx % BM; As[nb][k][m] = ra[i]; }
                else    { int m = idx / 16, k = idx % 16; As[nb][k][m] = ra[i]; }
            }
#pragma unroll
            for (int i = 0; i < LB; i++) {
                int idx = tid + i * THREADS;
                if (TB) { int n = idx / 16, k = idx % 16; Bs[nb][k][n] = rb[i]; }
                else    { int k = idx / BN, n = idx % BN; Bs[nb][k][n] = rb[i]; }
            }
            __syncthreads();
            buf = nb;
        }
    }

#pragma unroll
    for (int r = 0; r < 8; r++) {
        int m = m0 + ty * 8 + r;
#pragma unroll
        for (int c = 0; c < 8; c++) {
            int n = n0 + tx * 8 + c;
            float v = acc[r][c] * alpha;
            if (bMp) v += bMp[m];
            if (bNp) v += bNp[n];
            if (RELU) v = fmaxf(v, 0.f);
            long long o = OT ? ((long long)n * ldc + m) : ((long long)m * ldc + n);
            if (Rp) v += Rp[o];
            if (plane) v += plane[o];
            C[o] = v;
            if (Chp) {
                __nv_bfloat16 h, lo;
                bf16_split(v, h, lo);
                Chp[o] = h; Clp[o] = lo;
            }
        }
    }
}

// ---------------------------------------------------------------------------
// Small kernels
// ---------------------------------------------------------------------------
__global__ void wsplit_k(const float* __restrict__ src, int ld, int trans,
                         long long total, int KK,
                         __nv_bfloat16* __restrict__ hi, __nv_bfloat16* __restrict__ lo)
{
    long long idx = (long long)blockIdx.x * 256 + threadIdx.x;
    if (idx >= total) return;
    int n = (int)(idx / KK), k = (int)(idx % KK);
    float v = trans ? src[(long long)k * ld + n] : src[(long long)n * ld + k];
    __nv_bfloat16 h, l;
    bf16_split(v, h, l);
    hi[idx] = h; lo[idx] = l;
}

__global__ void rowdot_k(const float* __restrict__ x, const float* __restrict__ w,
                         float* __restrict__ out, int rowsPerB, int rowOff)
{
    int warp = (blockIdx.x * blockDim.x + threadIdx.x) >> 5;
    int lane = threadIdx.x & 31;
    int b = warp / rowsPerB;
    int i = warp % rowsPerB;
    if (b >= BATCH) return;
    const float* src = x + ((long long)b * SEQ + rowOff + i) * DIM;
    float s = 0.f;
    for (int d = lane; d < DIM; d += 32) s += src[d] * w[d];
#pragma unroll
    for (int o = 16; o > 0; o >>= 1) s += __shfl_down_sync(0xffffffffu, s, o);
    if (lane == 0) out[warp] = s;
}

// cw3 = C * w3 directly as bf16 hi/lo (b,64,768)
__global__ void cw3split_k(const float* __restrict__ x, const float* __restrict__ w3,
                           __nv_bfloat16* __restrict__ hi, __nv_bfloat16* __restrict__ lo)
{
    long long idx = (long long)blockIdx.x * 256 + threadIdx.x;
    if (idx >= SZ_BD) return;
    int d = (int)(idx % DIM);
    long long row = idx / DIM;
    long long b = row / LC, i = row % LC;
    float v = x[((long long)b * SEQ + i) * DIM + d] * w3[d];
    __nv_bfloat16 h, l;
    bf16_split(v, h, l);
    hi[idx] = h; lo[idx] = l;
}

// Q part of x as bf16 hi/lo (b,448,768)
__global__ void qsplit_k(const float* __restrict__ x,
                         __nv_bfloat16* __restrict__ hi, __nv_bfloat16* __restrict__ lo)
{
    long long idx = (long long)blockIdx.x * 256 + threadIdx.x;
    if (idx >= SZ_Q) return;
    int d = (int)(idx % DIM);
    long long row = idx / DIM;
    long long b = row / LQ, j = row % LQ;
    float v = x[((long long)b * SEQ + LC + j) * DIM + d];
    __nv_bfloat16 h, l;
    bf16_split(v, h, l);
    hi[idx] = h; lo[idx] = l;
}

// Q^T as bf16 hi/lo (b,768,448) via tiled transpose
__global__ void qtsplit_k(const float* __restrict__ x,
                          __nv_bfloat16* __restrict__ hi, __nv_bfloat16* __restrict__ lo)
{
    __shared__ float sm[32][33];
    int j0 = blockIdx.x * 32, d0 = blockIdx.y * 32, b = blockIdx.z;
    int tx = threadIdx.x & 31, ty = threadIdx.x >> 5;  // 256 thr: ty 0..7
#pragma unroll
    for (int r = 0; r < 4; r++) {
        int j = j0 + ty + r * 8;
        sm[ty + r * 8][tx] = x[((long long)b * SEQ + LC + j) * DIM + d0 + tx];
    }
    __syncthreads();
    __nv_bfloat16* hb = hi + (long long)b * DIM * LQ;
    __nv_bfloat16* lb = lo + (long long)b * DIM * LQ;
#pragma unroll
    for (int r = 0; r < 4; r++) {
        int d = d0 + ty + r * 8;
        float v = sm[tx][ty + r * 8];
        __nv_bfloat16 h, l;
        bf16_split(v, h, l);
        long long o = (long long)d * LQ + j0 + tx;
        hb[o] = h; lb[o] = l;
    }
}

// row softmax, float in -> bf16 hi/lo out
__global__ void softmax_rows_bf_k(const float* __restrict__ in,
                                  __nv_bfloat16* __restrict__ oh,
                                  __nv_bfloat16* __restrict__ ol, int len)
{
    long long base = (long long)blockIdx.x * len;
    int t = threadIdx.x;
    __shared__ float sh[128];
    float m = -1e30f;
    for (int i = t; i < len; i += 128) m = fmaxf(m, in[base + i]);
    sh[t] = m; __syncthreads();
    for (int o = 64; o > 0; o >>= 1) { if (t < o) sh[t] = fmaxf(sh[t], sh[t + o]); __syncthreads(); }
    m = sh[0]; __syncthreads();
    float s = 0.f;
    float loc[4];
    for (int i = t, c = 0; i < len; i += 128, c++) { float e = expf(in[base + i] - m); loc[c] = e; s += e; }
    sh[t] = s; __syncthreads();
    for (int o = 64; o > 0; o >>= 1) { if (t < o) sh[t] += sh[t + o]; __syncthreads(); }
    float inv = 1.f / sh[0];
    for (int i = t, c = 0; i < len; i += 128, c++) {
        __nv_bfloat16 h, l;
        bf16_split(loc[c] * inv, h, l);
        oh[base + i] = h; ol[base + i] = l;
    }
}

// row softmax, float in-place (scores)
__global__ void softmax_rows_k(const float* __restrict__ in, float* __restrict__ out, int len)
{
    long long base = (long long)blockIdx.x * len;
    int t = threadIdx.x;
    __shared__ float sh[128];
    float m = -1e30f;
    for (int i = t; i < len; i += 128) m = fmaxf(m, in[base + i]);
    sh[t] = m; __syncthreads();
    for (int o = 64; o > 0; o >>= 1) { if (t < o) sh[t] = fmaxf(sh[t], sh[t + o]); __syncthreads(); }
    m = sh[0]; __syncthreads();
    float s = 0.f;
    for (int i = t; i < len; i += 128) { float e = expf(in[base + i] - m); out[base + i] = e; s += e; }
    sh[t] = s; __syncthreads();
    for (int o = 64; o > 0; o >>= 1) { if (t < o) sh[t] += sh[t + o]; __syncthreads(); }
    float inv = 1.f / sh[0];
    for (int i = t; i < len; i += 128) out[base + i] *= inv;
}

// column softmax over i of S (B,64,448) -> bf16 hi/lo
__global__ void softmax_cols_bf_k(const float* __restrict__ S,
                                  __nv_bfloat16* __restrict__ oh,
                                  __nv_bfloat16* __restrict__ ol)
{
    int idx = blockIdx.x * blockDim.x + threadIdx.x;
    if (idx >= BATCH * LQ) return;
    int b = idx / LQ, j = idx % LQ;
    long long base = (long long)b * LC * LQ + j;
    float m = -1e30f;
#pragma unroll 4
    for (int i = 0; i < LC; i++) m = fmaxf(m, S[base + (long long)i * LQ]);
    float s = 0.f;
    float e[LC];
#pragma unroll 4
    for (int i = 0; i < LC; i++) { e[i] = expf(S[base + (long long)i * LQ] - m); s += e[i]; }
    float inv = 1.f / s;
#pragma unroll 4
    for (int i = 0; i < LC; i++) {
        __nv_bfloat16 h, l;
        bf16_split(e[i] * inv, h, l);
        oh[base + (long long)i * LQ] = h;
        ol[base + (long long)i * LQ] = l;
    }
}

// fused concat-gather + depthwise k=5 -> Y bf16 hi/lo (b,l,c)
__global__ void rz_dw_fuse_k(const float* __restrict__ x, const float* __restrict__ Abuf,
                             const float* __restrict__ Btbuf,
                             const float* __restrict__ dww, const float* __restrict__ dwb,
                             __nv_bfloat16* __restrict__ Yh, __nv_bfloat16* __restrict__ Yl)
{
    int c = blockIdx.x * 256 + threadIdx.x;
    int l = blockIdx.y;
    int b = blockIdx.z;
    int g = c / DIM;
    int d = c % DIM;
    float acc = dwb[c];
#pragma unroll
    for (int t = 0; t < 5; t++) {
        int l2 = l + t - 2;
        if (l2 < 0 || l2 >= LC) continue;
        float v;
        long long xo = ((long long)b * SEQ + l2) * DIM + d;
        long long ao = ((long long)b * LC + l2) * DIM + d;
        if (g == 0)      v = x[xo];
        else if (g == 1) v = Abuf[ao];
        else if (g == 2) v = x[xo] * Abuf[ao];
        else             v = x[xo] * Btbuf[ao];
        acc = fmaf(v, dww[c * 5 + t], acc);
    }
    long long o = ((long long)b * LC + l) * C4 + c;
    __nv_bfloat16 h, lo;
    bf16_split(acc, h, lo);
    Yh[o] = h; Yl[o] = lo;
}

__global__ void pe_init_k(float* __restrict__ pe)
{
    int idx = blockIdx.x * 256 + threadIdx.x;
    if (idx >= DIM * LC) return;
    int d = idx / LC, l = idx % LC;
    float fd = (float)d;
    bool even = (d & 1) == 0;
    float freq = even ? powf(10000.f, -fd / 768.f)
                      : -powf(10000.f, (1.f - fd) / 768.f);
    float ph = even ? 0.f : 1.57079632679489662f;
    pe[idx] = sinf((float)l * freq + ph);
}

__global__ void ln_stats_k(const float* __restrict__ in, float* __restrict__ mean,
                           float* __restrict__ rstd)
{
    int b = blockIdx.x;
    const float4* p = reinterpret_cast<const float4*>(in + (long long)b * (DIM * LC));
    float s = 0.f, s2 = 0.f;
    for (int i = threadIdx.x; i < DIM * LC / 4; i += 512) {
        float4 v = p[i];
        s += v.x + v.y + v.z + v.w;
        s2 += v.x * v.x + v.y * v.y + v.z * v.z + v.w * v.w;
    }
    __shared__ float sh[512], sh2[512];
    sh[threadIdx.x] = s; sh2[threadIdx.x] = s2; __syncthreads();
    for (int o = 256; o > 0; o >>= 1) {
        if (threadIdx.x < o) { sh[threadIdx.x] += sh[threadIdx.x + o]; sh2[threadIdx.x] += sh2[threadIdx.x + o]; }
        __syncthreads();
    }
    if (threadIdx.x == 0) {
        float m = sh[0] / (float)(DIM * LC);
        float var = sh2[0] / (float)(DIM * LC) - m * m;
        mean[b] = m;
        rstd[b] = rsqrtf(var + 1e-5f);
    }
}

// fused ln + dwconv3 + transpose-convert: (b,d,l) float -> (b,l,d) bf16 hi/lo
__global__ void ln_conv_t_k(const float* __restrict__ in, const float* __restrict__ mean,
                            const float* __restrict__ rstd, const float* __restrict__ lw,
                            const float* __restrict__ lb, const float* __restrict__ cw,
                            const float* __restrict__ cb,
                            __nv_bfloat16* __restrict__ oh, __nv_bfloat16* __restrict__ ol)
{
    __shared__ float sm[32][65];
    int b = blockIdx.x, d0 = blockIdx.y * 32;
    float mu = mean[b], rs = rstd[b];
    const float* ib = in + (long long)b * (DIM * LC);
#pragma unroll
    for (int it = 0; it < 8; it++) {
        int idx = threadIdx.x + it * 256;
        int dd = idx >> 6, l = idx & 63;
        int d = d0 + dd;
        const float* rowp = ib + (long long)d * 64;
        int wb = d * 64;
        float a = cb[d];
#pragma unroll
        for (int t = 0; t < 3; t++) {
            int l2 = l + t - 1;
            if (l2 < 0 || l2 >= 64) continue;
            float v = (rowp[l2] - mu) * rs * lw[wb + l2] + lb[wb + l2];
            a = fmaf(v, cw[d * 3 + t], a);
        }
        sm[dd][l] = a;
    }
    __syncthreads();
    __nv_bfloat16* ohb = oh + (long long)b * 64 * 768;
    __nv_bfloat16* olb = ol + (long long)b * 64 * 768;
#pragma unroll
    for (int it = 0; it < 8; it++) {
        int idx = threadIdx.x + it * 256;
        int l = idx >> 5, dd = idx & 31;
        float v = sm[dd][l];
        __nv_bfloat16 h, lo;
        bf16_split(v, h, lo);
        long long o = (long long)l * 768 + d0 + dd;
        ohb[o] = h; olb[o] = lo;
    }
}

// fused ln + transpose-convert (no conv)
__global__ void ln_apply_t_k(const float* __restrict__ in, const float* __restrict__ mean,
                             const float* __restrict__ rstd, const float* __restrict__ lw,
                             const float* __restrict__ lb,
                             __nv_bfloat16* __restrict__ oh, __nv_bfloat16* __restrict__ ol)
{
    __shared__ float sm[32][65];
    int b = blockIdx.x, d0 = blockIdx.y * 32;
    float mu = mean[b], rs = rstd[b];
    const float* ib = in + (long long)b * (DIM * LC);
#pragma unroll
    for (int it = 0; it < 8; it++) {
        int idx = threadIdx.x + it * 256;
        int dd = idx >> 6, l = idx & 63;
        int d = d0 + dd;
        float v = (ib[(long long)d * 64 + l] - mu) * rs * lw[d * 64 + l] + lb[d * 64 + l];
        sm[dd][l] = v;
    }
    __syncthreads();
    __nv_bfloat16* ohb = oh + (long long)b * 64 * 768;
    __nv_bfloat16* olb = ol + (long long)b * 64 * 768;
#pragma unroll
    for (int it = 0; it < 8; it++) {
        int idx = threadIdx.x + it * 256;
        int l = idx >> 5, dd = idx & 31;
        float v = sm[dd][l];
        __nv_bfloat16 h, lo;
        bf16_split(v, h, lo);
        long long o = (long long)l * 768 + d0 + dd;
        ohb[o] = h; olb[o] = lo;
    }
}

__global__ void final_head_k(const float* __restrict__ X, const float* __restrict__ w,
                             const float* __restrict__ bias, float* __restrict__ out)
{
    int b = blockIdx.x;
    const float* p = X + (long long)b * (DIM * LC);
    float s = 0.f;
    for (int i = threadIdx.x; i < DIM * LC; i += 256) s = fmaf(p[i], w[i], s);
    __shared__ float sh[256];
    sh[threadIdx.x] = s; __syncthreads();
    for (int o = 128; o > 0; o >>= 1) {
        if (threadIdx.x < o) sh[threadIdx.x] += sh[threadIdx.x + o];
        __syncthreads();
    }
    if (threadIdx.x == 0) out[b] = 1.f / (1.f + expf(-(sh[0] + bias[0])));
}

// ---------------------------------------------------------------------------
// Host-side helpers
// ---------------------------------------------------------------------------
template<int BM, int BN, bool TA, bool TB, bool OT, bool RELU>
static inline void run_gemm(const float* A, long long sA, int lda,
                            const float* B, long long sB, int ldb,
                            float* C, long long sC, int ldc,
                            const float* bM, long long sbM,
                            const float* bN, long long sbN,
                            const float* R, long long sR,
                            const float* plane,
                            __nv_bfloat16* Ch, __nv_bfloat16* Cl,
                            float alpha, int M, int N, int K)
{
    dim3 grid(N / BN, M / BM, BATCH);
    gemm8_k<BM, BN, TA, TB, OT, RELU><<<grid, (BM / 8) * (BN / 8)>>>(
        A, sA, lda, B, sB, ldb, C, sC, ldc, bM, sbM, bN, sbN, R, sR, plane, Ch, Cl, alpha, K);
}

template<int OMODE>
static inline void run_mgemm(const __nv_bfloat16* Ah, const __nv_bfloat16* Al,
                             const __nv_bfloat16* Bh, const __nv_bfloat16* Bl,
                             float* O, long long sO, int ldo,
                             const float* bias,
                             const float* R, long long sR,
                             const float* plane,
                             int N, int K, int relu)
{
    cudaFuncSetAttribute((const void*)mgemm_k<OMODE>,
                         cudaFuncAttributeMaxDynamicSharedMemorySize, MT_SMEM);
    dim3 grid(N / 128, BATCH / 2);
    mgemm_k<OMODE><<<grid, 256, MT_SMEM>>>(
        Ah, Al, Bh, Bl, O, sO, ldo, bias, R, sR, plane, K, relu);
}

static inline void run_pgemm(const __nv_bfloat16* Ah, const __nv_bfloat16* Al, long long sA,
                             const __nv_bfloat16* Bh, const __nv_bfloat16* Bl, long long sB,
                             float* O, long long sO, int ldo,
                             const float* bM, long long sbM,
                             const float* bN, long long sbN,
                             int N, int K)
{
    cudaFuncSetAttribute((const void*)pgemm_k,
                         cudaFuncAttributeMaxDynamicSharedMemorySize, PG_SMEM);
    dim3 grid(N / 64, BATCH);
    pgemm_k<<<grid, 256, PG_SMEM>>>(Ah, Al, sA, Bh, Bl, sB, O, sO, ldo, bM, sbM, bN, sbN, K);
}

struct EncW {
    const float *c1dw, *c1db, *c1pw, *c1pb;
    const float *c2dw, *c2db, *c2pw, *c2pb;
    const float *wq, *wk, *wv, *wo;
    const float *fcw, *fcb;
    const float *nbw, *nbb, *n1w, *n1b, *n2w, *n2b, *nEw, *nEb;
};

struct BfW {
    __nv_bfloat16 *rzh, *rzl, *c1h, *c1l, *c2h, *c2l, *fch, *fcl;
    __nv_bfloat16 *qkvh, *qkvl, *oh, *ol;
};

static void enc_block(const float* Xin,
                      float* t1, float* t2, float* t3, float* qkv,
                      float* Xout, const float* outPlane, float* mean, float* rstd,
                      float* scores, const EncW& w, const BfW& bw,
                      __nv_bfloat16* a1h, __nv_bfloat16* a1l,
                      __nv_bfloat16* a2h, __nv_bfloat16* a2l)
{
    const float scale = 0.03608439182435161f; // 1/sqrt(768)
    const long long SQKV = 64LL * 2304;

    // ln(normb) + dwconv c1 -> ACT1 bf16 (b,l,d)
    ln_stats_k<<<BATCH, 512>>>(Xin, mean, rstd);
    ln_conv_t_k<<<dim3(BATCH, 24), 256>>>(Xin, mean, rstd, w.nbw, w.nbb, w.c1dw, w.c1db, a1h, a1l);
    // pw c1 (mma): relu(W@x + b) + Xin -> t2 (b,d,l)
    run_mgemm<1>(a1h, a1l, bw.c1h, bw.c1l, t2, SE, 64, w.c1pb, Xin, SE, nullptr, DIM, DIM, 1);
    // ln(norm1) + dwconv c2 -> ACT1
    ln_stats_k<<<BATCH, 512>>>(t2, mean, rstd);
    ln_conv_t_k<<<dim3(BATCH, 24), 256>>>(t2, mean, rstd, w.n1w, w.n1b, w.c2dw, w.c2db, a1h, a1l);
    // pw c2 (mma) -> t3
    run_mgemm<1>(a1h, a1l, bw.c2h, bw.c2l, t3, SE, 64, w.c2pb, t2, SE, nullptr, DIM, DIM, 1);
    // ln(norm2) -> ACT1
    ln_stats_k<<<BATCH, 512>>>(t3, mean, rstd);
    ln_apply_t_k<<<dim3(BATCH, 24), 256>>>(t3, mean, rstd, w.n2w, w.n2b, a1h, a1l);
    // merged q|k|v (mma, N=2304): (b,l,2304)
    run_mgemm<0>(a1h, a1l, bw.qkvh, bw.qkvl, qkv, SQKV, 2304, nullptr, nullptr, 0, nullptr, 2304, DIM, 0);
    // scores = q @ k^T * scale (SIMT fp32)
    run_gemm<64, 64, false, true, false, false>(qkv, SQKV, 2304, qkv + DIM, SQKV, 2304,
                                                scores, (long long)LC * LC, LC,
                                                nullptr, 0, nullptr, 0, nullptr, 0, nullptr, nullptr, nullptr,
                                                scale, LC, LC, DIM);
    softmax_rows_k<<<BATCH * LC, 128>>>(scores, scores, LC);
    // av = attn @ v -> t1 float + ACT2 bf16 (b,l,768)
    run_gemm<64, 128, false, false, false, false>(scores, (long long)LC * LC, LC, qkv + 2 * DIM, SQKV, 2304,
                                                  t1, SE, DIM,
                                                  nullptr, 0, nullptr, 0, nullptr, 0, nullptr, a2h, a2l,
                                                  1.f, LC, DIM, LC);
    // sa = (av @ wo)^T + t3 -> t2 (mma, transposed store)
    run_mgemm<1>(a2h, a2l, bw.oh, bw.ol, t2, SE, 64, nullptr, t3, SE, nullptr, DIM, DIM, 0);
    // ln(norme) -> ACT1
    ln_stats_k<<<BATCH, 512>>>(t2, mean, rstd);
    ln_apply_t_k<<<dim3(BATCH, 24), 256>>>(t2, mean, rstd, w.nEw, w.nEb, a1h, a1l);
    // fc + relu + t2 (+pe) -> Xout (mma)
    run_mgemm<1>(a1h, a1l, bw.fch, bw.fcl, Xout, SE, 64, w.fcb, t2, SE, outPlane, DIM, DIM, 1);
}

// ---------------------------------------------------------------------------
// Entry point
// ---------------------------------------------------------------------------
extern "C" void kernel_launch(void* const* d_in, const int* in_sizes, int n_in,
                              void* d_out, int out_size)
{
    (void)in_sizes; (void)n_in; (void)out_size;
    const float* x       = (const float*)d_in[0];
    const float* Wv      = (const float*)d_in[1];
    const float* rz_dw_w = (const float*)d_in[2];
    const float* rz_dw_b = (const float*)d_in[3];
    const float* rz_pw_w = (const float*)d_in[4];
    const float* rz_pw_b = (const float*)d_in[5];
    EncW w;
    w.c1dw = (const float*)d_in[6];  w.c1db = (const float*)d_in[7];
    w.c1pw = (const float*)d_in[8];  w.c1pb = (const float*)d_in[9];
    w.c2dw = (const float*)d_in[10]; w.c2db = (const float*)d_in[11];
    w.c2pw = (const float*)d_in[12]; w.c2pb = (const float*)d_in[13];
    w.wq   = (const float*)d_in[14]; w.wk   = (const float*)d_in[15];
    w.wv   = (const float*)d_in[16]; w.wo   = (const float*)d_in[17];
    w.fcw  = (const float*)d_in[18]; w.fcb  = (const float*)d_in[19];
    w.nbw  = (const float*)d_in[20]; w.nbb  = (const float*)d_in[21];
    w.n1w  = (const float*)d_in[22]; w.n1b  = (const float*)d_in[23];
    w.n2w  = (const float*)d_in[24]; w.n2b  = (const float*)d_in[25];
    w.nEw  = (const float*)d_in[26]; w.nEb  = (const float*)d_in[27];
    const float* fcf_w = (const float*)d_in[28];
    const float* fcf_b = (const float*)d_in[29];

    float* pool = nullptr;
    cudaGetSymbolAddress((void**)&pool, g_pool);

    float* c1s  = pool + OFF_C1;
    float* q2s  = pool + OFF_Q2;
    float* S    = pool + OFF_S;
    float* Abuf = pool + OFF_A;
    float* Tbuf = pool + OFF_T;
    float* Btb  = pool + OFF_BT;
    float* E[8];
    for (int i = 0; i < 8; i++) E[i] = pool + OFF_E0 + (long long)i * SZ_E;
    float* mean = pool + OFF_MEAN;
    float* rstd = pool + OFF_RSTD;
    float* pe   = pool + OFF_PE;

    __nv_bfloat16* cw3h = (__nv_bfloat16*)(pool + OFF_CW3);
    __nv_bfloat16* cw3l = cw3h + SZ_BD;
    __nv_bfloat16* S1h  = (__nv_bfloat16*)(pool + OFF_S1);
    __nv_bfloat16* S1l  = S1h + SZ_S;
    __nv_bfloat16* S2h  = (__nv_bfloat16*)(pool + OFF_S2);
    __nv_bfloat16* S2l  = S2h + SZ_S;
    __nv_bfloat16* Yh   = (__nv_bfloat16*)(pool + OFF_Y);
    __nv_bfloat16* Yl   = Yh + SZ_Y;
    __nv_bfloat16* Qsh  = (__nv_bfloat16*)(pool + OFF_QS);
    __nv_bfloat16* Qsl  = Qsh + SZ_Q;
    __nv_bfloat16* Qth  = (__nv_bfloat16*)(pool + OFF_QT);
    __nv_bfloat16* Qtl  = Qth + SZ_Q;
    __nv_bfloat16* a1h  = (__nv_bfloat16*)(pool + OFF_ACT);
    __nv_bfloat16* a1l  = a1h + SZ_BD;
    __nv_bfloat16* a2h  = a1l + SZ_BD;
    __nv_bfloat16* a2l  = a2h + SZ_BD;

    BfW bw;
    {
        __nv_bfloat16* p = (__nv_bfloat16*)(pool + OFF_WB);
        bw.rzh  = p; p += (long long)DIM * C4;
        bw.rzl  = p; p += (long long)DIM * C4;
        bw.c1h  = p; p += (long long)DIM * DIM;
        bw.c1l  = p; p += (long long)DIM * DIM;
        bw.c2h  = p; p += (long long)DIM * DIM;
        bw.c2l  = p; p += (long long)DIM * DIM;
        bw.fch  = p; p += (long long)DIM * DIM;
        bw.fcl  = p; p += (long long)DIM * DIM;
        bw.qkvh = p; p += 3LL * DIM * DIM;
        bw.qkvl = p; p += 3LL * DIM * DIM;
        bw.oh   = p; p += (long long)DIM * DIM;
        bw.ol   = p;
    }

    const long long WDD = (long long)DIM * DIM;

    // ---- launch order chosen so ncu (-s 5) profiles the S pgemm ----
    pe_init_k<<<(DIM * LC + 255) / 256, 256>>>(pe);                               // 0
    rowdot_k<<<(BATCH * LC * 32) / 256, 256>>>(x, Wv, c1s, LC, 0);                // 1
    rowdot_k<<<(BATCH * LQ * 32) / 256, 256>>>(x, Wv + DIM, q2s, LQ, LC);         // 2
    cw3split_k<<<(int)((SZ_BD + 255) / 256), 256>>>(x, Wv + 2 * DIM, cw3h, cw3l); // 3
    qsplit_k<<<(int)((SZ_Q + 255) / 256), 256>>>(x, Qsh, Qsl);                    // 4

    // 5: S = cw3 @ Q^T + c1[:,None] + q2[None,:]   (tensor, per-batch)
    run_pgemm(cw3h, cw3l, 64LL * DIM, Qsh, Qsl, (long long)LQ * DIM,
              S, (long long)LC * LQ, LQ, c1s, LC, q2s, LQ, LQ, DIM);

    qtsplit_k<<<dim3(LQ / 32, DIM / 32, BATCH), 256>>>(x, Qth, Qtl);              // 6
    softmax_rows_bf_k<<<BATCH * LC, 128>>>(S, S1h, S1l, LQ);                      // 7
    softmax_cols_bf_k<<<(BATCH * LQ + 255) / 256, 256>>>(S, S2h, S2l);            // 8

    // A = S1 @ Q  (tensor, per-batch; B = Q^T rows=d, k=j)
    run_pgemm(S1h, S1l, (long long)LC * LQ, Qth, Qtl, (long long)DIM * LQ,
              Abuf, (long long)LC * DIM, DIM, nullptr, 0, nullptr, 0, DIM, LQ);

    // T = S1 @ S2^T (tensor, per-batch)
    run_pgemm(S1h, S1l, (long long)LC * LQ, S2h, S2l, (long long)LC * LQ,
              Tbuf, (long long)LC * LC, LC, nullptr, 0, nullptr, 0, LC, LQ);

    // Bt = T @ C (SIMT, K=64)
    run_gemm<64, 128, false, false, false, false>(
        Tbuf, (long long)LC * LC, LC,
        x, (long long)SEQ * DIM, DIM,
        Btb, (long long)LC * DIM, DIM,
        nullptr, 0, nullptr, 0, nullptr, 0, nullptr, nullptr, nullptr, 1.f, LC, DIM, LC);

    // fused concat-gather + depthwise k=5 -> Y bf16 hi/lo (b,l,c)
    rz_dw_fuse_k<<<dim3(C4 / 256, LC, BATCH), 256>>>(x, Abuf, Btb, rz_dw_w, rz_dw_b, Yh, Yl);

    // ---- weight conversion (bf16 hi/lo, n x k, k-contiguous) ----
    {
        long long trz = (long long)DIM * C4;
        int gs = (int)((WDD + 255) / 256);
        wsplit_k<<<(int)((trz + 255) / 256), 256>>>(rz_pw_w, C4, 0, trz, C4, bw.rzh, bw.rzl);
        wsplit_k<<<gs, 256>>>(w.c1pw, DIM, 0, WDD, DIM, bw.c1h, bw.c1l);
        wsplit_k<<<gs, 256>>>(w.c2pw, DIM, 0, WDD, DIM, bw.c2h, bw.c2l);
        wsplit_k<<<gs, 256>>>(w.fcw,  DIM, 0, WDD, DIM, bw.fch, bw.fcl);
        wsplit_k<<<gs, 256>>>(w.wq,   DIM, 1, WDD, DIM, bw.qkvh,           bw.qkvl);
        wsplit_k<<<gs, 256>>>(w.wk,   DIM, 1, WDD, DIM, bw.qkvh + WDD,     bw.qkvl + WDD);
        wsplit_k<<<gs, 256>>>(w.wv,   DIM, 1, WDD, DIM, bw.qkvh + 2 * WDD, bw.qkvl + 2 * WDD);
        wsplit_k<<<gs, 256>>>(w.wo,   DIM, 1, WDD, DIM, bw.oh,  bw.ol);
    }

    // pointwise 3072 -> 768 (mma): +bias +pe -> E0 (b,d,l)
    run_mgemm<1>(Yh, Yl, bw.rzh, bw.rzl, E[0], SE, 64, rz_pw_b, nullptr, 0, pe, DIM, C4, 0);

    // ---- two encoder blocks (qkv buffer spans E[4..6]) ----
    enc_block(E[0], E[1], E[2], E[3], E[4], E[7], pe, mean, rstd, Tbuf, w, bw,
              a1h, a1l, a2h, a2l);
    enc_block(E[7], E[1], E[2], E[3], E[4], E[0], nullptr, mean, rstd, Tbuf, w, bw,
              a1h, a1l, a2h, a2l);

    // ---- final sigmoid head ----
    final_head_k<<<BATCH, 256>>>(E[0], fcf_w, fcf_b, (float*)d_out);
}

// round 6
// speedup vs baseline: 3.1557x; 1.2393x over previous
#include <cuda_runtime.h>
#include <cuda_fp16.h>
#include <math.h>
#include <stdint.h>

// ---------------------------------------------------------------------------
// Problem constants
// ---------------------------------------------------------------------------
namespace {
constexpr int BATCH = 128;
constexpr int LC    = 64;
constexpr int LQ    = 448;
constexpr int DIM   = 768;
constexpr int SEQ   = 512;
constexpr int C4    = 3072;

constexpr long long SZ_C1 = (long long)BATCH * LC;
constexpr long long SZ_Q2 = (long long)BATCH * LQ;
constexpr long long SZ_BD = (long long)BATCH * LC * DIM;
constexpr long long SZ_S  = (long long)BATCH * LC * LQ;
constexpr long long SZ_T  = (long long)BATCH * LC * LC;
constexpr long long SZ_Y  = (long long)BATCH * LC * C4;
constexpr long long SZ_E  = SZ_BD;
constexpr long long SZ_Q  = (long long)BATCH * LQ * DIM;
constexpr long long SE    = (long long)DIM * LC;

constexpr long long OFF_C1  = 0;
constexpr long long OFF_Q2  = OFF_C1 + SZ_C1;
constexpr long long OFF_CW3 = OFF_Q2 + SZ_Q2;    // cw3 fp16 single
constexpr long long OFF_S   = OFF_CW3 + SZ_BD;
constexpr long long OFF_S1  = OFF_S  + SZ_S;     // S1 fp16 single
constexpr long long OFF_S2  = OFF_S1 + SZ_S;     // S2 fp16 hi/lo
constexpr long long OFF_A   = OFF_S2 + SZ_S;
constexpr long long OFF_T   = OFF_A  + SZ_BD;
constexpr long long OFF_BT  = OFF_T  + SZ_T;
constexpr long long OFF_Y   = OFF_BT + SZ_BD;    // Y fp16 single
constexpr long long OFF_E0  = OFF_Y  + SZ_Y;
constexpr long long OFF_MEAN = OFF_E0 + 8 * SZ_E;
constexpr long long OFF_RSTD = OFF_MEAN + 128;
constexpr long long OFF_PE   = OFF_RSTD + 128;
constexpr long long OFF_ACT  = OFF_PE + (long long)DIM * LC;  // act fp16 buffers
constexpr long long OFF_WB   = OFF_ACT + 2 * SZ_BD;
constexpr long long WB_FLOATS = (2LL * DIM * C4 + 14LL * DIM * DIM) / 2;
constexpr long long OFF_QS   = OFF_WB + WB_FLOATS;   // Q fp16 hi/lo (b,448,768)
constexpr long long OFF_QT   = OFF_QS + SZ_Q;        // Q^T fp16 hi/lo (b,768,448)
constexpr long long POOL_SZ  = OFF_QT + SZ_Q;
} // namespace

__device__ float g_pool[POOL_SZ];

// ---------------------------------------------------------------------------
// Family-portable tensor-core primitives
// ---------------------------------------------------------------------------
__device__ __forceinline__ uint32_t smem_u32(const void* p) {
    uint32_t a;
    asm("{ .reg .u64 t; cvta.to.shared.u64 t, %1; cvt.u32.u64 %0, t; }" : "=r"(a) : "l"(p));
    return a;
}
#define SW128(o) ((o) ^ (((o) >> 3) & 0x70))

__device__ __forceinline__ void cpa16(uint32_t dst, const void* src) {
    asm volatile("cp.async.cg.shared.global [%0], [%1], 16;" :: "r"(dst), "l"(src) : "memory");
}
__device__ __forceinline__ void cp_commit() {
    asm volatile("cp.async.commit_group;" ::: "memory");
}
__device__ __forceinline__ void cp_wait1() {
    asm volatile("cp.async.wait_group 1;" ::: "memory");
}
__device__ __forceinline__ void cp_wait0() {
    asm volatile("cp.async.wait_group 0;" ::: "memory");
}
__device__ __forceinline__ void ldsm4(uint32_t* r, uint32_t a) {
    asm volatile("ldmatrix.sync.aligned.m8n8.x4.shared.b16 {%0,%1,%2,%3}, [%4];"
        : "=r"(r[0]), "=r"(r[1]), "=r"(r[2]), "=r"(r[3]) : "r"(a));
}
__device__ __forceinline__ void mma_f16(float* d, const uint32_t* a, uint32_t b0, uint32_t b1) {
    asm volatile("mma.sync.aligned.m16n8k16.row.col.f32.f16.f16.f32 "
        "{%0,%1,%2,%3}, {%4,%5,%6,%7}, {%8,%9}, {%0,%1,%2,%3};"
        : "+f"(d[0]), "+f"(d[1]), "+f"(d[2]), "+f"(d[3])
        : "r"(a[0]), "r"(a[1]), "r"(a[2]), "r"(a[3]), "r"(b0), "r"(b1));
}
__device__ __forceinline__ void fp16_split(float v, __half& h, __half& l) {
    h = __float2half(v);
    l = __float2half(v - __half2float(h));
}

// ---------------------------------------------------------------------------
// mgemm: batch-shared-B tensor GEMM. A: fp16 single (BATCH*64, K) k-contig;
// B: fp16 hi/lo (N, K) k-contig.  D = A*Bh + A*Bl, fp32 accum.
// CTA = 128 rows x 128 cols, K-chunks of 64, 3-stage cp.async.
// OMODE 0: O[b*sO + l*ldo + n] ; OMODE 1: O[b*sO + n*64 + l]
// ---------------------------------------------------------------------------
namespace {
constexpr int MT_TILE = 16384;                  // 128 rows x 128 B
constexpr int MT_SMEM = 3 * 3 * MT_TILE + 1024; // 3 stages x 3 tiles
constexpr int PG_TILE = 8192;                   // 64 rows x 128 B
constexpr int PG_SMEM = 2 * 3 * PG_TILE + 1024; // 2 stages x 3 tiles
}

template<int OMODE>
__global__ void __launch_bounds__(256, 1) mgemm_k(
    const __half* __restrict__ Af,
    const __half* __restrict__ Bh, const __half* __restrict__ Bl,
    float* __restrict__ O, long long sO, int ldo,
    const float* __restrict__ bias,
    const float* __restrict__ R, long long sR,
    const float* __restrict__ plane,
    int K, int relu)
{
    extern __shared__ char dsm[];
    const uint32_t tb = (smem_u32(dsm) + 1023u) & ~1023u;

    const int tid = threadIdx.x, lane = tid & 31, wid = tid >> 5;
    const int n0 = blockIdx.x * 128;
    const int rbase = blockIdx.y * 128;
    const int wm = wid & 1, wn = wid >> 1;   // warp tile 64x32

    float acc[4][4][4];
#pragma unroll
    for (int a = 0; a < 4; a++)
#pragma unroll
        for (int b = 0; b < 4; b++)
#pragma unroll
            for (int c = 0; c < 4; c++) acc[a][b][c] = 0.f;

    const int nch = K / 64;

    auto copy_chunk = [&](int ci, int s) {
        const int k0 = ci * 64;
        const uint32_t tA  = tb + (s * 3 + 0) * MT_TILE;
        const uint32_t tBh = tb + (s * 3 + 1) * MT_TILE;
        const uint32_t tBl = tb + (s * 3 + 2) * MT_TILE;
#pragma unroll
        for (int it = 0; it < 4; it++) {
            int idx = tid + it * 256;
            int r = idx >> 3, c = idx & 7;
            uint32_t doff = SW128((uint32_t)(r * 128 + c * 16));
            long long aoff = (long long)(rbase + r) * K + k0 + c * 8;
            long long boff = (long long)(n0 + r) * K + k0 + c * 8;
            cpa16(tA  + doff, Af + aoff);
            cpa16(tBh + doff, Bh + boff);
            cpa16(tBl + doff, Bl + boff);
        }
    };

    copy_chunk(0, 0); cp_commit();
    copy_chunk(1, 1); cp_commit();

    const int rl = lane & 15, chalf = lane >> 4;

    for (int i = 0; i < nch; i++) {
        if (i + 1 < nch) cp_wait1(); else cp_wait0();
        __syncthreads();
        if (i + 2 < nch) { copy_chunk(i + 2, (i + 2) % 3); cp_commit(); }

        const int s = i % 3;
        const uint32_t tA  = tb + (s * 3 + 0) * MT_TILE;
        const uint32_t tBh = tb + (s * 3 + 1) * MT_TILE;
        const uint32_t tBl = tb + (s * 3 + 2) * MT_TILE;

#pragma unroll
        for (int ks = 0; ks < 4; ks++) {
            const uint32_t coff = (uint32_t)((ks * 2 + chalf) * 16);
            uint32_t af[4][4], bh[2][4], bl[2][4];
#pragma unroll
            for (int mt = 0; mt < 4; mt++) {
                uint32_t off = SW128((uint32_t)((wm * 64 + mt * 16 + rl) * 128) + coff);
                ldsm4(af[mt], tA + off);
            }
#pragma unroll
            for (int np = 0; np < 2; np++) {
                uint32_t off = SW128((uint32_t)((wn * 32 + np * 16 + rl) * 128) + coff);
                ldsm4(bh[np], tBh + off);
                ldsm4(bl[np], tBl + off);
            }
#pragma unroll
            for (int mt = 0; mt < 4; mt++)
#pragma unroll
                for (int np = 0; np < 2; np++)
#pragma unroll
                    for (int j = 0; j < 2; j++) {
                        float* d = acc[mt][np * 2 + j];
                        mma_f16(d, af[mt], bh[np][j], bh[np][j + 2]);
                        mma_f16(d, af[mt], bl[np][j], bl[np][j + 2]);
                    }
        }
    }

    const int b0 = blockIdx.y * 2;
#pragma unroll
    for (int mt = 0; mt < 4; mt++) {
        int row0 = wm * 64 + mt * 16 + (lane >> 2);
#pragma unroll
        for (int half = 0; half < 2; half++) {
            int row = row0 + half * 8;
            int bi = b0 + (row >> 6), l = row & 63;
            float* Ob = O + (long long)bi * sO;
            const float* Rb = R ? R + (long long)bi * sR : nullptr;
#pragma unroll
            for (int nn = 0; nn < 4; nn++) {
                int n = n0 + wn * 32 + nn * 8 + (lane & 3) * 2;
#pragma unroll
                for (int e = 0; e < 2; e++) {
                    float v = acc[mt][nn][half * 2 + e];
                    int nc = n + e;
                    if (bias) v += bias[nc];
                    if (relu) v = fmaxf(v, 0.f);
                    long long o = (OMODE == 1) ? ((long long)nc * 64 + l)
                                               : ((long long)l * ldo + nc);
                    if (Rb)    v += Rb[o];
                    if (plane) v += plane[o];
                    Ob[o] = v;
                }
            }
        }
    }
}

// ---------------------------------------------------------------------------
// pgemm: per-batch GEMM. A fp16 single (b)64xK; B fp16 hi/lo (b)NbxK.
// CTA = 64 x 64 tile, grid (N/64, BATCH). 2-stage cp.async.
// ---------------------------------------------------------------------------
__global__ void __launch_bounds__(256, 1) pgemm_k(
    const __half* __restrict__ Af, long long sA,
    const __half* __restrict__ Bh, const __half* __restrict__ Bl, long long sB,
    float* __restrict__ O, long long sO, int ldo,
    const float* __restrict__ bM, long long sbM,
    const float* __restrict__ bN, long long sbN,
    int K)
{
    extern __shared__ char dsm[];
    const uint32_t tb = (smem_u32(dsm) + 1023u) & ~1023u;

    const int tid = threadIdx.x, lane = tid & 31, wid = tid >> 5;
    const int n0 = blockIdx.x * 64;
    const int b  = blockIdx.y;
    const int wm = wid >> 1, wn = wid & 1;    // warp tile 16x32

    const __half* Afb = Af + (long long)b * sA;
    const __half* Bhb = Bh + (long long)b * sB + (long long)n0 * K;
    const __half* Blb = Bl + (long long)b * sB + (long long)n0 * K;

    float acc[4][4];
#pragma unroll
    for (int a = 0; a < 4; a++)
#pragma unroll
        for (int c = 0; c < 4; c++) acc[a][c] = 0.f;

    const int nch = K / 64;

    auto copy_chunk = [&](int ci, int s) {
        const int k0 = ci * 64;
        const uint32_t tA  = tb + (s * 3 + 0) * PG_TILE;
        const uint32_t tBh = tb + (s * 3 + 1) * PG_TILE;
        const uint32_t tBl = tb + (s * 3 + 2) * PG_TILE;
#pragma unroll
        for (int it = 0; it < 2; it++) {
            int idx = tid + it * 256;          // 0..511
            int r = idx >> 3, c = idx & 7;
            uint32_t doff = SW128((uint32_t)(r * 128 + c * 16));
            long long off = (long long)r * K + k0 + c * 8;
            cpa16(tA  + doff, Afb + off);
            cpa16(tBh + doff, Bhb + off);
            cpa16(tBl + doff, Blb + off);
        }
    };

    copy_chunk(0, 0); cp_commit();

    const int rl = lane & 15, chalf = lane >> 4;

    for (int i = 0; i < nch; i++) {
        cp_wait0();
        __syncthreads();
        if (i + 1 < nch) { copy_chunk(i + 1, (i + 1) & 1); cp_commit(); }

        const int s = i & 1;
        const uint32_t tA  = tb + (s * 3 + 0) * PG_TILE;
        const uint32_t tBh = tb + (s * 3 + 1) * PG_TILE;
        const uint32_t tBl = tb + (s * 3 + 2) * PG_TILE;

#pragma unroll
        for (int ks = 0; ks < 4; ks++) {
            const uint32_t coff = (uint32_t)((ks * 2 + chalf) * 16);
            uint32_t af[4], bh[2][4], bl[2][4];
            {
                uint32_t off = SW128((uint32_t)((wm * 16 + rl) * 128) + coff);
                ldsm4(af, tA + off);
            }
#pragma unroll
            for (int np = 0; np < 2; np++) {
                uint32_t off = SW128((uint32_t)((wn * 32 + np * 16 + rl) * 128) + coff);
                ldsm4(bh[np], tBh + off);
                ldsm4(bl[np], tBl + off);
            }
#pragma unroll
            for (int np = 0; np < 2; np++)
#pragma unroll
                for (int j = 0; j < 2; j++) {
                    float* d = acc[np * 2 + j];
                    mma_f16(d, af, bh[np][j], bh[np][j + 2]);
                    mma_f16(d, af, bl[np][j], bl[np][j + 2]);
                }
        }
    }

    float* Ob = O + (long long)b * sO;
    const float* bMp = bM ? bM + (long long)b * sbM : nullptr;
    const float* bNp = bN ? bN + (long long)b * sbN : nullptr;
#pragma unroll
    for (int half = 0; half < 2; half++) {
        int row = wm * 16 + (lane >> 2) + half * 8;
#pragma unroll
        for (int nn = 0; nn < 4; nn++) {
            int n = n0 + wn * 32 + nn * 8 + (lane & 3) * 2;
#pragma unroll
            for (int e = 0; e < 2; e++) {
                float v = acc[nn][half * 2 + e];
                int nc = n + e;
                if (bMp) v += bMp[row];
                if (bNp) v += bNp[nc];
                Ob[(long long)row * ldo + nc] = v;
            }
        }
    }
}

// ---------------------------------------------------------------------------
// SIMT GEMM (8x8 microtile) — scores/av/Bt only
// ---------------------------------------------------------------------------
template<int BM, int BN, bool TA, bool TB, bool OT, bool RELU>
__global__ void __launch_bounds__((BM/8)*(BN/8)) gemm8_k(
    const float* __restrict__ A, long long sA, int lda,
    const float* __restrict__ B, long long sB, int ldb,
    float* __restrict__ C, long long sC, int ldc,
    const float* __restrict__ bM, long long sbM,
    const float* __restrict__ bN, long long sbN,
    const float* __restrict__ R, long long sR,
    const float* __restrict__ plane,
    __half* __restrict__ Cf,
    float alpha, int K)
{
    constexpr int THREADS = (BM / 8) * (BN / 8);
    constexpr int LA = BM * 16 / THREADS;
    constexpr int LB = BN * 16 / THREADS;

    const int bz = blockIdx.z;
    A += (long long)bz * sA;
    B += (long long)bz * sB;
    C += (long long)bz * sC;
    __half* Cfp = Cf ? Cf + (long long)bz * sC : nullptr;
    const float* bMp = bM ? bM + (long long)bz * sbM : nullptr;
    const float* bNp = bN ? bN + (long long)bz * sbN : nullptr;
    const float* Rp  = R  ? R  + (long long)bz * sR  : nullptr;

    const int m0 = blockIdx.y * BM;
    const int n0 = blockIdx.x * BN;

    __shared__ float As[2][16][BM + 4];
    __shared__ float Bs[2][16][BN + 4];

    const int tid = threadIdx.x;
    const int tx = tid % (BN / 8);
    const int ty = tid / (BN / 8);

    float acc[8][8];
#pragma unroll
    for (int r = 0; r < 8; r++)
#pragma unroll
        for (int c = 0; c < 8; c++) acc[r][c] = 0.f;

    float ra[LA], rb[LB];

#pragma unroll
    for (int i = 0; i < LA; i++) {
        int idx = tid + i * THREADS;
        if (TA) { int k = idx / BM, m = idx % BM; As[0][k][m] = A[(long long)k * lda + (m0 + m)]; }
        else    { int m = idx / 16, k = idx % 16; As[0][k][m] = A[(long long)(m0 + m) * lda + k]; }
    }
#pragma unroll
    for (int i = 0; i < LB; i++) {
        int idx = tid + i * THREADS;
        if (TB) { int n = idx / 16, k = idx % 16; Bs[0][k][n] = B[(long long)(n0 + n) * ldb + k]; }
        else    { int k = idx / BN, n = idx % BN; Bs[0][k][n] = B[(long long)k * ldb + (n0 + n)]; }
    }
    __syncthreads();

    int buf = 0;
    for (int k0 = 0; k0 < K; k0 += 16) {
        const bool more = (k0 + 16) < K;
        if (more) {
            const int kn = k0 + 16;
#pragma unroll
            for (int i = 0; i < LA; i++) {
                int idx = tid + i * THREADS;
                if (TA) { int k = idx / BM, m = idx % BM; ra[i] = A[(long long)(kn + k) * lda + (m0 + m)]; }
                else    { int m = idx / 16, k = idx % 16; ra[i] = A[(long long)(m0 + m) * lda + (kn + k)]; }
            }
#pragma unroll
            for (int i = 0; i < LB; i++) {
                int idx = tid + i * THREADS;
                if (TB) { int n = idx / 16, k = idx % 16; rb[i] = B[(long long)(n0 + n) * ldb + (kn + k)]; }
                else    { int k = idx / BN, n = idx % BN; rb[i] = B[(long long)(kn + k) * ldb + (n0 + n)]; }
            }
        }

#pragma unroll
        for (int k = 0; k < 16; k++) {
            float a[8], b[8];
            float4 t;
            t = *reinterpret_cast<const float4*>(&As[buf][k][ty * 8]);
            a[0] = t.x; a[1] = t.y; a[2] = t.z; a[3] = t.w;
            t = *reinterpret_cast<const float4*>(&As[buf][k][ty * 8 + 4]);
            a[4] = t.x; a[5] = t.y; a[6] = t.z; a[7] = t.w;
            t = *reinterpret_cast<const float4*>(&Bs[buf][k][tx * 8]);
            b[0] = t.x; b[1] = t.y; b[2] = t.z; b[3] = t.w;
            t = *reinterpret_cast<const float4*>(&Bs[buf][k][tx * 8 + 4]);
            b[4] = t.x; b[5] = t.y; b[6] = t.z; b[7] = t.w;
#pragma unroll
            for (int r = 0; r < 8; r++)
#pragma unroll
                for (int c = 0; c < 8; c++)
                    acc[r][c] = fmaf(a[r], b[c], acc[r][c]);
        }

        if (more) {
            int nb = buf ^ 1;
#pragma unroll
            for (int i = 0; i < LA; i++) {
                int idx = tid + i * THREADS;
                if (TA) { int k = idx / BM, m = idx % BM; As[nb][k][m] = ra[i]; }
                else    { int m = idx / 16, k = idx % 16; As[nb][k][m] = ra[i]; }
            }
#pragma unroll
            for (int i = 0; i < LB; i++) {
                int idx = tid + i * THREADS;
                if (TB) { int n = idx / 16, k = idx % 16; Bs[nb][k][n] = rb[i]; }
                else    { int k = idx / BN, n = idx % BN; Bs[nb][k][n] = rb[i]; }
            }
            __syncthreads();
            buf = nb;
        }
    }

#pragma unroll
    for (int r = 0; r < 8; r++) {
        int m = m0 + ty * 8 + r;
#pragma unroll
        for (int c = 0; c < 8; c++) {
            int n = n0 + tx * 8 + c;
            float v = acc[r][c] * alpha;
            if (bMp) v += bMp[m];
            if (bNp) v += bNp[n];
            if (RELU) v = fmaxf(v, 0.f);
            long long o = OT ? ((long long)n * ldc + m) : ((long long)m * ldc + n);
            if (Rp) v += Rp[o];
            if (plane) v += plane[o];
            C[o] = v;
            if (Cfp) Cfp[o] = __float2half(v);
        }
    }
}

// ---------------------------------------------------------------------------
// Small kernels
// ---------------------------------------------------------------------------
__global__ void wsplit_k(const float* __restrict__ src, int ld, int trans,
                         long long total, int KK,
                         __half* __restrict__ hi, __half* __restrict__ lo)
{
    long long idx = (long long)blockIdx.x * 256 + threadIdx.x;
    if (idx >= total) return;
    int n = (int)(idx / KK), k = (int)(idx % KK);
    float v = trans ? src[(long long)k * ld + n] : src[(long long)n * ld + k];
    __half h, l;
    fp16_split(v, h, l);
    hi[idx] = h; lo[idx] = l;
}

__global__ void rowdot_k(const float* __restrict__ x, const float* __restrict__ w,
                         float* __restrict__ out, int rowsPerB, int rowOff)
{
    int warp = (blockIdx.x * blockDim.x + threadIdx.x) >> 5;
    int lane = threadIdx.x & 31;
    int b = warp / rowsPerB;
    int i = warp % rowsPerB;
    if (b >= BATCH) return;
    const float* src = x + ((long long)b * SEQ + rowOff + i) * DIM;
    float s = 0.f;
    for (int d = lane; d < DIM; d += 32) s += src[d] * w[d];
#pragma unroll
    for (int o = 16; o > 0; o >>= 1) s += __shfl_down_sync(0xffffffffu, s, o);
    if (lane == 0) out[warp] = s;
}

// cw3 = C * w3 as fp16 single (b,64,768)
__global__ void cw3split_k(const float* __restrict__ x, const float* __restrict__ w3,
                           __half* __restrict__ out)
{
    long long idx = (long long)blockIdx.x * 256 + threadIdx.x;
    if (idx >= SZ_BD) return;
    int d = (int)(idx % DIM);
    long long row = idx / DIM;
    long long b = row / LC, i = row % LC;
    float v = x[((long long)b * SEQ + i) * DIM + d] * w3[d];
    out[idx] = __float2half(v);
}

// Q part of x as fp16 hi/lo (b,448,768)
__global__ void qsplit_k(const float* __restrict__ x,
                         __half* __restrict__ hi, __half* __restrict__ lo)
{
    long long idx = (long long)blockIdx.x * 256 + threadIdx.x;
    if (idx >= SZ_Q) return;
    int d = (int)(idx % DIM);
    long long row = idx / DIM;
    long long b = row / LQ, j = row % LQ;
    float v = x[((long long)b * SEQ + LC + j) * DIM + d];
    __half h, l;
    fp16_split(v, h, l);
    hi[idx] = h; lo[idx] = l;
}

// Q^T as fp16 hi/lo (b,768,448) via tiled transpose
__global__ void qtsplit_k(const float* __restrict__ x,
                          __half* __restrict__ hi, __half* __restrict__ lo)
{
    __shared__ float sm[32][33];
    int j0 = blockIdx.x * 32, d0 = blockIdx.y * 32, b = blockIdx.z;
    int tx = threadIdx.x & 31, ty = threadIdx.x >> 5;
#pragma unroll
    for (int r = 0; r < 4; r++) {
        int j = j0 + ty + r * 8;
        sm[ty + r * 8][tx] = x[((long long)b * SEQ + LC + j) * DIM + d0 + tx];
    }
    __syncthreads();
    __half* hb = hi + (long long)b * DIM * LQ;
    __half* lb = lo + (long long)b * DIM * LQ;
#pragma unroll
    for (int r = 0; r < 4; r++) {
        int d = d0 + ty + r * 8;
        float v = sm[tx][ty + r * 8];
        __half h, l;
        fp16_split(v, h, l);
        long long o = (long long)d * LQ + j0 + tx;
        hb[o] = h; lb[o] = l;
    }
}

// row softmax, float in -> fp16 single out (S1)
__global__ void softmax_rows_f16_k(const float* __restrict__ in,
                                   __half* __restrict__ out, int len)
{
    long long base = (long long)blockIdx.x * len;
    int t = threadIdx.x;
    __shared__ float sh[128];
    float m = -1e30f;
    for (int i = t; i < len; i += 128) m = fmaxf(m, in[base + i]);
    sh[t] = m; __syncthreads();
    for (int o = 64; o > 0; o >>= 1) { if (t < o) sh[t] = fmaxf(sh[t], sh[t + o]); __syncthreads(); }
    m = sh[0]; __syncthreads();
    float s = 0.f;
    float loc[4];
    for (int i = t, c = 0; i < len; i += 128, c++) { float e = expf(in[base + i] - m); loc[c] = e; s += e; }
    sh[t] = s; __syncthreads();
    for (int o = 64; o > 0; o >>= 1) { if (t < o) sh[t] += sh[t + o]; __syncthreads(); }
    float inv = 1.f / sh[0];
    for (int i = t, c = 0; i < len; i += 128, c++)
        out[base + i] = __float2half(loc[c] * inv);
}

// row softmax, float in-place (scores)
__global__ void softmax_rows_k(const float* __restrict__ in, float* __restrict__ out, int len)
{
    long long base = (long long)blockIdx.x * len;
    int t = threadIdx.x;
    __shared__ float sh[128];
    float m = -1e30f;
    for (int i = t; i < len; i += 128) m = fmaxf(m, in[base + i]);
    sh[t] = m; __syncthreads();
    for (int o = 64; o > 0; o >>= 1) { if (t < o) sh[t] = fmaxf(sh[t], sh[t + o]); __syncthreads(); }
    m = sh[0]; __syncthreads();
    float s = 0.f;
    for (int i = t; i < len; i += 128) { float e = expf(in[base + i] - m); out[base + i] = e; s += e; }
    sh[t] = s; __syncthreads();
    for (int o = 64; o > 0; o >>= 1) { if (t < o) sh[t] += sh[t + o]; __syncthreads(); }
    float inv = 1.f / sh[0];
    for (int i = t; i < len; i += 128) out[base + i] *= inv;
}

// column softmax over i of S (B,64,448) -> fp16 hi/lo (S2 is a B operand)
__global__ void softmax_cols_f16_k(const float* __restrict__ S,
                                   __half* __restrict__ oh, __half* __restrict__ ol)
{
    int idx = blockIdx.x * blockDim.x + threadIdx.x;
    if (idx >= BATCH * LQ) return;
    int b = idx / LQ, j = idx % LQ;
    long long base = (long long)b * LC * LQ + j;
    float m = -1e30f;
#pragma unroll 4
    for (int i = 0; i < LC; i++) m = fmaxf(m, S[base + (long long)i * LQ]);
    float s = 0.f;
    float e[LC];
#pragma unroll 4
    for (int i = 0; i < LC; i++) { e[i] = expf(S[base + (long long)i * LQ] - m); s += e[i]; }
    float inv = 1.f / s;
#pragma unroll 4
    for (int i = 0; i < LC; i++) {
        __half h, l;
        fp16_split(e[i] * inv, h, l);
        oh[base + (long long)i * LQ] = h;
        ol[base + (long long)i * LQ] = l;
    }
}

// fused concat-gather + depthwise k=5 -> Y fp16 single (b,l,c)
__global__ void rz_dw_fuse_k(const float* __restrict__ x, const float* __restrict__ Abuf,
                             const float* __restrict__ Btbuf,
                             const float* __restrict__ dww, const float* __restrict__ dwb,
                             __half* __restrict__ Y)
{
    int c = blockIdx.x * 256 + threadIdx.x;
    int l = blockIdx.y;
    int b = blockIdx.z;
    int g = c / DIM;
    int d = c % DIM;
    float acc = dwb[c];
#pragma unroll
    for (int t = 0; t < 5; t++) {
        int l2 = l + t - 2;
        if (l2 < 0 || l2 >= LC) continue;
        float v;
        long long xo = ((long long)b * SEQ + l2) * DIM + d;
        long long ao = ((long long)b * LC + l2) * DIM + d;
        if (g == 0)      v = x[xo];
        else if (g == 1) v = Abuf[ao];
        else if (g == 2) v = x[xo] * Abuf[ao];
        else             v = x[xo] * Btbuf[ao];
        acc = fmaf(v, dww[c * 5 + t], acc);
    }
    Y[((long long)b * LC + l) * C4 + c] = __float2half(acc);
}

__global__ void pe_init_k(float* __restrict__ pe)
{
    int idx = blockIdx.x * 256 + threadIdx.x;
    if (idx >= DIM * LC) return;
    int d = idx / LC, l = idx % LC;
    float fd = (float)d;
    bool even = (d & 1) == 0;
    float freq = even ? powf(10000.f, -fd / 768.f)
                      : -powf(10000.f, (1.f - fd) / 768.f);
    float ph = even ? 0.f : 1.57079632679489662f;
    pe[idx] = sinf((float)l * freq + ph);
}

__global__ void ln_stats_k(const float* __restrict__ in, float* __restrict__ mean,
                           float* __restrict__ rstd)
{
    int b = blockIdx.x;
    const float4* p = reinterpret_cast<const float4*>(in + (long long)b * (DIM * LC));
    float s = 0.f, s2 = 0.f;
    for (int i = threadIdx.x; i < DIM * LC / 4; i += 512) {
        float4 v = p[i];
        s += v.x + v.y + v.z + v.w;
        s2 += v.x * v.x + v.y * v.y + v.z * v.z + v.w * v.w;
    }
    __shared__ float sh[512], sh2[512];
    sh[threadIdx.x] = s; sh2[threadIdx.x] = s2; __syncthreads();
    for (int o = 256; o > 0; o >>= 1) {
        if (threadIdx.x < o) { sh[threadIdx.x] += sh[threadIdx.x + o]; sh2[threadIdx.x] += sh2[threadIdx.x + o]; }
        __syncthreads();
    }
    if (threadIdx.x == 0) {
        float m = sh[0] / (float)(DIM * LC);
        float var = sh2[0] / (float)(DIM * LC) - m * m;
        mean[b] = m;
        rstd[b] = rsqrtf(var + 1e-5f);
    }
}

// fused ln + dwconv3 + transpose-convert: (b,d,l) float -> (b,l,d) fp16 single
__global__ void ln_conv_t_k(const float* __restrict__ in, const float* __restrict__ mean,
                            const float* __restrict__ rstd, const float* __restrict__ lw,
                            const float* __restrict__ lb, const float* __restrict__ cw,
                            const float* __restrict__ cb,
                            __half* __restrict__ out)
{
    __shared__ float sm[32][65];
    int b = blockIdx.x, d0 = blockIdx.y * 32;
    float mu = mean[b], rs = rstd[b];
    const float* ib = in + (long long)b * (DIM * LC);
#pragma unroll
    for (int it = 0; it < 8; it++) {
        int idx = threadIdx.x + it * 256;
        int dd = idx >> 6, l = idx & 63;
        int d = d0 + dd;
        const float* rowp = ib + (long long)d * 64;
        int wb = d * 64;
        float a = cb[d];
#pragma unroll
        for (int t = 0; t < 3; t++) {
            int l2 = l + t - 1;
            if (l2 < 0 || l2 >= 64) continue;
            float v = (rowp[l2] - mu) * rs * lw[wb + l2] + lb[wb + l2];
            a = fmaf(v, cw[d * 3 + t], a);
        }
        sm[dd][l] = a;
    }
    __syncthreads();
    __half* ob = out + (long long)b * 64 * 768;
#pragma unroll
    for (int it = 0; it < 8; it++) {
        int idx = threadIdx.x + it * 256;
        int l = idx >> 5, dd = idx & 31;
        ob[(long long)l * 768 + d0 + dd] = __float2half(sm[dd][l]);
    }
}

// fused ln + transpose-convert (no conv)
__global__ void ln_apply_t_k(const float* __restrict__ in, const float* __restrict__ mean,
                             const float* __restrict__ rstd, const float* __restrict__ lw,
                             const float* __restrict__ lb,
                             __half* __restrict__ out)
{
    __shared__ float sm[32][65];
    int b = blockIdx.x, d0 = blockIdx.y * 32;
    float mu = mean[b], rs = rstd[b];
    const float* ib = in + (long long)b * (DIM * LC);
#pragma unroll
    for (int it = 0; it < 8; it++) {
        int idx = threadIdx.x + it * 256;
        int dd = idx >> 6, l = idx & 63;
        int d = d0 + dd;
        float v = (ib[(long long)d * 64 + l] - mu) * rs * lw[d * 64 + l] + lb[d * 64 + l];
        sm[dd][l] = v;
    }
    __syncthreads();
    __half* ob = out + (long long)b * 64 * 768;
#pragma unroll
    for (int it = 0; it < 8; it++) {
        int idx = threadIdx.x + it * 256;
        int l = idx >> 5, dd = idx & 31;
        ob[(long long)l * 768 + d0 + dd] = __float2half(sm[dd][l]);
    }
}

__global__ void final_head_k(const float* __restrict__ X, const float* __restrict__ w,
                             const float* __restrict__ bias, float* __restrict__ out)
{
    int b = blockIdx.x;
    const float* p = X + (long long)b * (DIM * LC);
    float s = 0.f;
    for (int i = threadIdx.x; i < DIM * LC; i += 256) s = fmaf(p[i], w[i], s);
    __shared__ float sh[256];
    sh[threadIdx.x] = s; __syncthreads();
    for (int o = 128; o > 0; o >>= 1) {
        if (threadIdx.x < o) sh[threadIdx.x] += sh[threadIdx.x + o];
        __syncthreads();
    }
    if (threadIdx.x == 0) out[b] = 1.f / (1.f + expf(-(sh[0] + bias[0])));
}

// ---------------------------------------------------------------------------
// Host-side helpers
// ---------------------------------------------------------------------------
template<int BM, int BN, bool TA, bool TB, bool OT, bool RELU>
static inline void run_gemm(const float* A, long long sA, int lda,
                            const float* B, long long sB, int ldb,
                            float* C, long long sC, int ldc,
                            const float* bM, long long sbM,
                            const float* bN, long long sbN,
                            const float* R, long long sR,
                            const float* plane,
                            __half* Cf,
                            float alpha, int M, int N, int K)
{
    dim3 grid(N / BN, M / BM, BATCH);
    gemm8_k<BM, BN, TA, TB, OT, RELU><<<grid, (BM / 8) * (BN / 8)>>>(
        A, sA, lda, B, sB, ldb, C, sC, ldc, bM, sbM, bN, sbN, R, sR, plane, Cf, alpha, K);
}

template<int OMODE>
static inline void run_mgemm(const __half* Af,
                             const __half* Bh, const __half* Bl,
                             float* O, long long sO, int ldo,
                             const float* bias,
                             const float* R, long long sR,
                             const float* plane,
                             int N, int K, int relu)
{
    cudaFuncSetAttribute((const void*)mgemm_k<OMODE>,
                         cudaFuncAttributeMaxDynamicSharedMemorySize, MT_SMEM);
    dim3 grid(N / 128, BATCH / 2);
    mgemm_k<OMODE><<<grid, 256, MT_SMEM>>>(
        Af, Bh, Bl, O, sO, ldo, bias, R, sR, plane, K, relu);
}

static inline void run_pgemm(const __half* Af, long long sA,
                             const __half* Bh, const __half* Bl, long long sB,
                             float* O, long long sO, int ldo,
                             const float* bM, long long sbM,
                             const float* bN, long long sbN,
                             int N, int K)
{
    cudaFuncSetAttribute((const void*)pgemm_k,
                         cudaFuncAttributeMaxDynamicSharedMemorySize, PG_SMEM);
    dim3 grid(N / 64, BATCH);
    pgemm_k<<<grid, 256, PG_SMEM>>>(Af, sA, Bh, Bl, sB, O, sO, ldo, bM, sbM, bN, sbN, K);
}

struct EncW {
    const float *c1dw, *c1db, *c1pw, *c1pb;
    const float *c2dw, *c2db, *c2pw, *c2pb;
    const float *wq, *wk, *wv, *wo;
    const float *fcw, *fcb;
    const float *nbw, *nbb, *n1w, *n1b, *n2w, *n2b, *nEw, *nEb;
};

struct HfW {
    __half *rzh, *rzl, *c1h, *c1l, *c2h, *c2l, *fch, *fcl;
    __half *qkvh, *qkvl, *oh, *ol;
};

static void enc_block(const float* Xin,
                      float* t1, float* t2, float* t3, float* qkv,
                      float* Xout, const float* outPlane, float* mean, float* rstd,
                      float* scores, const EncW& w, const HfW& hw,
                      __half* a1, __half* a2)
{
    const float scale = 0.03608439182435161f; // 1/sqrt(768)
    const long long SQKV = 64LL * 2304;

    // ln(normb) + dwconv c1 -> a1 fp16 (b,l,d)
    ln_stats_k<<<BATCH, 512>>>(Xin, mean, rstd);
    ln_conv_t_k<<<dim3(BATCH, 24), 256>>>(Xin, mean, rstd, w.nbw, w.nbb, w.c1dw, w.c1db, a1);
    // pw c1 (mma): relu(W@x + b) + Xin -> t2 (b,d,l)
    run_mgemm<1>(a1, hw.c1h, hw.c1l, t2, SE, 64, w.c1pb, Xin, SE, nullptr, DIM, DIM, 1);
    // ln(norm1) + dwconv c2 -> a1
    ln_stats_k<<<BATCH, 512>>>(t2, mean, rstd);
    ln_conv_t_k<<<dim3(BATCH, 24), 256>>>(t2, mean, rstd, w.n1w, w.n1b, w.c2dw, w.c2db, a1);
    // pw c2 (mma) -> t3
    run_mgemm<1>(a1, hw.c2h, hw.c2l, t3, SE, 64, w.c2pb, t2, SE, nullptr, DIM, DIM, 1);
    // ln(norm2) -> a1
    ln_stats_k<<<BATCH, 512>>>(t3, mean, rstd);
    ln_apply_t_k<<<dim3(BATCH, 24), 256>>>(t3, mean, rstd, w.n2w, w.n2b, a1);
    // merged q|k|v (mma, N=2304): (b,l,2304)
    run_mgemm<0>(a1, hw.qkvh, hw.qkvl, qkv, SQKV, 2304, nullptr, nullptr, 0, nullptr, 2304, DIM, 0);
    // scores = q @ k^T * scale (SIMT fp32)
    run_gemm<64, 64, false, true, false, false>(qkv, SQKV, 2304, qkv + DIM, SQKV, 2304,
                                                scores, (long long)LC * LC, LC,
                                                nullptr, 0, nullptr, 0, nullptr, 0, nullptr, nullptr,
                                                scale, LC, LC, DIM);
    softmax_rows_k<<<BATCH * LC, 128>>>(scores, scores, LC);
    // av = attn @ v -> t1 float + a2 fp16 (b,l,768)
    run_gemm<64, 128, false, false, false, false>(scores, (long long)LC * LC, LC, qkv + 2 * DIM, SQKV, 2304,
                                                  t1, SE, DIM,
                                                  nullptr, 0, nullptr, 0, nullptr, 0, nullptr, a2,
                                                  1.f, LC, DIM, LC);
    // sa = (av @ wo)^T + t3 -> t2 (mma, transposed store)
    run_mgemm<1>(a2, hw.oh, hw.ol, t2, SE, 64, nullptr, t3, SE, nullptr, DIM, DIM, 0);
    // ln(norme) -> a1
    ln_stats_k<<<BATCH, 512>>>(t2, mean, rstd);
    ln_apply_t_k<<<dim3(BATCH, 24), 256>>>(t2, mean, rstd, w.nEw, w.nEb, a1);
    // fc + relu + t2 (+pe) -> Xout (mma)
    run_mgemm<1>(a1, hw.fch, hw.fcl, Xout, SE, 64, w.fcb, t2, SE, outPlane, DIM, DIM, 1);
}

// ---------------------------------------------------------------------------
// Entry point
// ---------------------------------------------------------------------------
extern "C" void kernel_launch(void* const* d_in, const int* in_sizes, int n_in,
                              void* d_out, int out_size)
{
    (void)in_sizes; (void)n_in; (void)out_size;
    const float* x       = (const float*)d_in[0];
    const float* Wv      = (const float*)d_in[1];
    const float* rz_dw_w = (const float*)d_in[2];
    const float* rz_dw_b = (const float*)d_in[3];
    const float* rz_pw_w = (const float*)d_in[4];
    const float* rz_pw_b = (const float*)d_in[5];
    EncW w;
    w.c1dw = (const float*)d_in[6];  w.c1db = (const float*)d_in[7];
    w.c1pw = (const float*)d_in[8];  w.c1pb = (const float*)d_in[9];
    w.c2dw = (const float*)d_in[10]; w.c2db = (const float*)d_in[11];
    w.c2pw = (const float*)d_in[12]; w.c2pb = (const float*)d_in[13];
    w.wq   = (const float*)d_in[14]; w.wk   = (const float*)d_in[15];
    w.wv   = (const float*)d_in[16]; w.wo   = (const float*)d_in[17];
    w.fcw  = (const float*)d_in[18]; w.fcb  = (const float*)d_in[19];
    w.nbw  = (const float*)d_in[20]; w.nbb  = (const float*)d_in[21];
    w.n1w  = (const float*)d_in[22]; w.n1b  = (const float*)d_in[23];
    w.n2w  = (const float*)d_in[24]; w.n2b  = (const float*)d_in[25];
    w.nEw  = (const float*)d_in[26]; w.nEb  = (const float*)d_in[27];
    const float* fcf_w = (const float*)d_in[28];
    const float* fcf_b = (const float*)d_in[29];

    float* pool = nullptr;
    cudaGetSymbolAddress((void**)&pool, g_pool);

    float* c1s  = pool + OFF_C1;
    float* q2s  = pool + OFF_Q2;
    float* S    = pool + OFF_S;
    float* Abuf = pool + OFF_A;
    float* Tbuf = pool + OFF_T;
    float* Btb  = pool + OFF_BT;
    float* E[8];
    for (int i = 0; i < 8; i++) E[i] = pool + OFF_E0 + (long long)i * SZ_E;
    float* mean = pool + OFF_MEAN;
    float* rstd = pool + OFF_RSTD;
    float* pe   = pool + OFF_PE;

    __half* cw3f = (__half*)(pool + OFF_CW3);
    __half* S1f  = (__half*)(pool + OFF_S1);
    __half* S2h  = (__half*)(pool + OFF_S2);
    __half* S2l  = S2h + SZ_S;
    __half* Yf   = (__half*)(pool + OFF_Y);
    __half* Qsh  = (__half*)(pool + OFF_QS);
    __half* Qsl  = Qsh + SZ_Q;
    __half* Qth  = (__half*)(pool + OFF_QT);
    __half* Qtl  = Qth + SZ_Q;
    __half* a1   = (__half*)(pool + OFF_ACT);
    __half* a2   = a1 + SZ_BD;

    HfW hw;
    {
        __half* p = (__half*)(pool + OFF_WB);
        hw.rzh  = p; p += (long long)DIM * C4;
        hw.rzl  = p; p += (long long)DIM * C4;
        hw.c1h  = p; p += (long long)DIM * DIM;
        hw.c1l  = p; p += (long long)DIM * DIM;
        hw.c2h  = p; p += (long long)DIM * DIM;
        hw.c2l  = p; p += (long long)DIM * DIM;
        hw.fch  = p; p += (long long)DIM * DIM;
        hw.fcl  = p; p += (long long)DIM * DIM;
        hw.qkvh = p; p += 3LL * DIM * DIM;
        hw.qkvl = p; p += 3LL * DIM * DIM;
        hw.oh   = p; p += (long long)DIM * DIM;
        hw.ol   = p;
    }

    const long long WDD = (long long)DIM * DIM;

    pe_init_k<<<(DIM * LC + 255) / 256, 256>>>(pe);
    rowdot_k<<<(BATCH * LC * 32) / 256, 256>>>(x, Wv, c1s, LC, 0);
    rowdot_k<<<(BATCH * LQ * 32) / 256, 256>>>(x, Wv + DIM, q2s, LQ, LC);
    cw3split_k<<<(int)((SZ_BD + 255) / 256), 256>>>(x, Wv + 2 * DIM, cw3f);
    qsplit_k<<<(int)((SZ_Q + 255) / 256), 256>>>(x, Qsh, Qsl);

    // S = cw3 @ Q^T + c1[:,None] + q2[None,:]   (tensor, per-batch)
    run_pgemm(cw3f, 64LL * DIM, Qsh, Qsl, (long long)LQ * DIM,
              S, (long long)LC * LQ, LQ, c1s, LC, q2s, LQ, LQ, DIM);

    qtsplit_k<<<dim3(LQ / 32, DIM / 32, BATCH), 256>>>(x, Qth, Qtl);
    softmax_rows_f16_k<<<BATCH * LC, 128>>>(S, S1f, LQ);
    softmax_cols_f16_k<<<(BATCH * LQ + 255) / 256, 256>>>(S, S2h, S2l);

    // A = S1 @ Q  (tensor, per-batch; B = Q^T)
    run_pgemm(S1f, (long long)LC * LQ, Qth, Qtl, (long long)DIM * LQ,
              Abuf, (long long)LC * DIM, DIM, nullptr, 0, nullptr, 0, DIM, LQ);

    // T = S1 @ S2^T (tensor, per-batch)
    run_pgemm(S1f, (long long)LC * LQ, S2h, S2l, (long long)LC * LQ,
              Tbuf, (long long)LC * LC, LC, nullptr, 0, nullptr, 0, LC, LQ);

    // Bt = T @ C (SIMT, K=64)
    run_gemm<64, 128, false, false, false, false>(
        Tbuf, (long long)LC * LC, LC,
        x, (long long)SEQ * DIM, DIM,
        Btb, (long long)LC * DIM, DIM,
        nullptr, 0, nullptr, 0, nullptr, 0, nullptr, nullptr, 1.f, LC, DIM, LC);

    // fused concat-gather + depthwise k=5 -> Y fp16 (b,l,c)
    rz_dw_fuse_k<<<dim3(C4 / 256, LC, BATCH), 256>>>(x, Abuf, Btb, rz_dw_w, rz_dw_b, Yf);

    // ---- weight conversion (fp16 hi/lo, n x k, k-contiguous) ----
    {
        long long trz = (long long)DIM * C4;
        int gs = (int)((WDD + 255) / 256);
        wsplit_k<<<(int)((trz + 255) / 256), 256>>>(rz_pw_w, C4, 0, trz, C4, hw.rzh, hw.rzl);
        wsplit_k<<<gs, 256>>>(w.c1pw, DIM, 0, WDD, DIM, hw.c1h, hw.c1l);
        wsplit_k<<<gs, 256>>>(w.c2pw, DIM, 0, WDD, DIM, hw.c2h, hw.c2l);
        wsplit_k<<<gs, 256>>>(w.fcw,  DIM, 0, WDD, DIM, hw.fch, hw.fcl);
        wsplit_k<<<gs, 256>>>(w.wq,   DIM, 1, WDD, DIM, hw.qkvh,           hw.qkvl);
        wsplit_k<<<gs, 256>>>(w.wk,   DIM, 1, WDD, DIM, hw.qkvh + WDD,     hw.qkvl + WDD);
        wsplit_k<<<gs, 256>>>(w.wv,   DIM, 1, WDD, DIM, hw.qkvh + 2 * WDD, hw.qkvl + 2 * WDD);
        wsplit_k<<<gs, 256>>>(w.wo,   DIM, 1, WDD, DIM, hw.oh,  hw.ol);
    }

    // pointwise 3072 -> 768 (mma): +bias +pe -> E0 (b,d,l)
    run_mgemm<1>(Yf, hw.rzh, hw.rzl, E[0], SE, 64, rz_pw_b, nullptr, 0, pe, DIM, C4, 0);

    // ---- two encoder blocks ----
    enc_block(E[0], E[1], E[2], E[3], E[4], E[7], pe, mean, rstd, Tbuf, w, hw, a1, a2);
    enc_block(E[7], E[1], E[2], E[3], E[4], E[0], nullptr, mean, rstd, Tbuf, w, hw, a1, a2);

    // ---- final sigmoid head ----
    final_head_k<<<BATCH, 256>>>(E[0], fcf_w, fcf_b, (float*)d_out);
}

// round 7
// speedup vs baseline: 4.1826x; 1.3254x over previous
#include <cuda_runtime.h>
#include <cuda_fp16.h>
#include <math.h>
#include <stdint.h>

// ---------------------------------------------------------------------------
// Problem constants
// ---------------------------------------------------------------------------
namespace {
constexpr int BATCH = 128;
constexpr int LC    = 64;
constexpr int LQ    = 448;
constexpr int DIM   = 768;
constexpr int SEQ   = 512;
constexpr int C4    = 3072;

constexpr long long SZ_C1 = (long long)BATCH * LC;
constexpr long long SZ_Q2 = (long long)BATCH * LQ;
constexpr long long SZ_BD = (long long)BATCH * LC * DIM;
constexpr long long SZ_S  = (long long)BATCH * LC * LQ;
constexpr long long SZ_T  = (long long)BATCH * LC * LC;
constexpr long long SZ_Y  = (long long)BATCH * LC * C4;
constexpr long long SZ_E  = SZ_BD;
constexpr long long SZ_Q  = (long long)BATCH * LQ * DIM;
constexpr long long SE    = (long long)DIM * LC;

constexpr long long OFF_C1  = 0;
constexpr long long OFF_Q2  = OFF_C1 + SZ_C1;
constexpr long long OFF_CW3 = OFF_Q2 + SZ_Q2;    // cw3 fp16
constexpr long long OFF_S   = OFF_CW3 + SZ_BD;
constexpr long long OFF_S1  = OFF_S  + SZ_S;     // S1 fp16
constexpr long long OFF_S2  = OFF_S1 + SZ_S;     // S2 fp16
constexpr long long OFF_A   = OFF_S2 + SZ_S;
constexpr long long OFF_T   = OFF_A  + SZ_BD;
constexpr long long OFF_BT  = OFF_T  + SZ_T;
constexpr long long OFF_Y   = OFF_BT + SZ_BD;    // Y fp16
constexpr long long OFF_E0  = OFF_Y  + SZ_Y;
constexpr long long OFF_MEAN = OFF_E0 + 8 * SZ_E;
constexpr long long OFF_RSTD = OFF_MEAN + 128;
constexpr long long OFF_PE   = OFF_RSTD + 128;
constexpr long long OFF_ACT  = OFF_PE + (long long)DIM * LC;  // fp16 act buffers
constexpr long long OFF_WB   = OFF_ACT + 2 * SZ_BD;
constexpr long long WB_FLOATS = ((long long)DIM * C4 + 7LL * DIM * DIM) / 2 + 64;
constexpr long long OFF_QS   = OFF_WB + WB_FLOATS;   // Q fp16 (b,448,768)
constexpr long long OFF_QT   = OFF_QS + SZ_Q;        // Q^T fp16 (b,768,448)
constexpr long long POOL_SZ  = OFF_QT + SZ_Q;
} // namespace

__device__ float g_pool[POOL_SZ];

// ---------------------------------------------------------------------------
// Family-portable tensor-core primitives
// ---------------------------------------------------------------------------
__device__ __forceinline__ uint32_t smem_u32(const void* p) {
    uint32_t a;
    asm("{ .reg .u64 t; cvta.to.shared.u64 t, %1; cvt.u32.u64 %0, t; }" : "=r"(a) : "l"(p));
    return a;
}
#define SW128(o) ((o) ^ (((o) >> 3) & 0x70))

__device__ __forceinline__ void cpa16(uint32_t dst, const void* src) {
    asm volatile("cp.async.cg.shared.global [%0], [%1], 16;" :: "r"(dst), "l"(src) : "memory");
}
__device__ __forceinline__ void cp_commit() {
    asm volatile("cp.async.commit_group;" ::: "memory");
}
__device__ __forceinline__ void cp_wait1() {
    asm volatile("cp.async.wait_group 1;" ::: "memory");
}
__device__ __forceinline__ void cp_wait0() {
    asm volatile("cp.async.wait_group 0;" ::: "memory");
}
__device__ __forceinline__ void ldsm4(uint32_t* r, uint32_t a) {
    asm volatile("ldmatrix.sync.aligned.m8n8.x4.shared.b16 {%0,%1,%2,%3}, [%4];"
        : "=r"(r[0]), "=r"(r[1]), "=r"(r[2]), "=r"(r[3]) : "r"(a));
}
__device__ __forceinline__ void mma_f16(float* d, const uint32_t* a, uint32_t b0, uint32_t b1) {
    asm volatile("mma.sync.aligned.m16n8k16.row.col.f32.f16.f16.f32 "
        "{%0,%1,%2,%3}, {%4,%5,%6,%7}, {%8,%9}, {%0,%1,%2,%3};"
        : "+f"(d[0]), "+f"(d[1]), "+f"(d[2]), "+f"(d[3])
        : "r"(a[0]), "r"(a[1]), "r"(a[2]), "r"(a[3]), "r"(b0), "r"(b1));
}

// ---------------------------------------------------------------------------
// mgemm: batch-shared-B tensor GEMM (all fp16, fp32 accum)
// A: (BATCH*64, K) k-contig; B: (N, K) k-contig (weights).
// CTA = 128 rows x 128 cols, K-chunks of 64, 3-stage cp.async.
// OMODE 0: O[b*sO + l*ldo + n] ; OMODE 1: O[b*sO + n*64 + l]
// ---------------------------------------------------------------------------
namespace {
constexpr int MT_TILE = 16384;                  // 128 rows x 128 B
constexpr int MT_SMEM = 3 * 2 * MT_TILE + 1024; // 3 stages x 2 tiles = 97 KB
constexpr int PG_TILE = 8192;                   // 64 rows x 128 B
constexpr int PG_SMEM = 2 * 2 * PG_TILE + 1024; // 2 stages x 2 tiles = 33 KB
}

template<int OMODE>
__global__ void __launch_bounds__(256, 1) mgemm_k(
    const __half* __restrict__ Af,
    const __half* __restrict__ Bf,
    float* __restrict__ O, long long sO, int ldo,
    const float* __restrict__ bias,
    const float* __restrict__ R, long long sR,
    const float* __restrict__ plane,
    int K, int relu)
{
    extern __shared__ char dsm[];
    const uint32_t tb = (smem_u32(dsm) + 1023u) & ~1023u;

    const int tid = threadIdx.x, lane = tid & 31, wid = tid >> 5;
    const int n0 = blockIdx.x * 128;
    const int rbase = blockIdx.y * 128;
    const int wm = wid & 1, wn = wid >> 1;   // warp tile 64x32

    float acc[4][4][4];
#pragma unroll
    for (int a = 0; a < 4; a++)
#pragma unroll
        for (int b = 0; b < 4; b++)
#pragma unroll
            for (int c = 0; c < 4; c++) acc[a][b][c] = 0.f;

    const int nch = K / 64;

    auto copy_chunk = [&](int ci, int s) {
        const int k0 = ci * 64;
        const uint32_t tA = tb + (s * 2 + 0) * MT_TILE;
        const uint32_t tB = tb + (s * 2 + 1) * MT_TILE;
#pragma unroll
        for (int it = 0; it < 4; it++) {
            int idx = tid + it * 256;
            int r = idx >> 3, c = idx & 7;
            uint32_t doff = SW128((uint32_t)(r * 128 + c * 16));
            cpa16(tA + doff, Af + (long long)(rbase + r) * K + k0 + c * 8);
            cpa16(tB + doff, Bf + (long long)(n0 + r) * K + k0 + c * 8);
        }
    };

    copy_chunk(0, 0); cp_commit();
    copy_chunk(1, 1); cp_commit();

    const int rl = lane & 15, chalf = lane >> 4;

    for (int i = 0; i < nch; i++) {
        if (i + 1 < nch) cp_wait1(); else cp_wait0();
        __syncthreads();
        if (i + 2 < nch) { copy_chunk(i + 2, (i + 2) % 3); cp_commit(); }

        const int s = i % 3;
        const uint32_t tA = tb + (s * 2 + 0) * MT_TILE;
        const uint32_t tB = tb + (s * 2 + 1) * MT_TILE;

#pragma unroll
        for (int ks = 0; ks < 4; ks++) {
            const uint32_t coff = (uint32_t)((ks * 2 + chalf) * 16);
            uint32_t af[4][4], bf[2][4];
#pragma unroll
            for (int mt = 0; mt < 4; mt++) {
                uint32_t off = SW128((uint32_t)((wm * 64 + mt * 16 + rl) * 128) + coff);
                ldsm4(af[mt], tA + off);
            }
#pragma unroll
            for (int np = 0; np < 2; np++) {
                uint32_t off = SW128((uint32_t)((wn * 32 + np * 16 + rl) * 128) + coff);
                ldsm4(bf[np], tB + off);
            }
#pragma unroll
            for (int mt = 0; mt < 4; mt++)
#pragma unroll
                for (int np = 0; np < 2; np++)
#pragma unroll
                    for (int j = 0; j < 2; j++)
                        mma_f16(acc[mt][np * 2 + j], af[mt], bf[np][j], bf[np][j + 2]);
        }
    }

    const int b0 = blockIdx.y * 2;
#pragma unroll
    for (int mt = 0; mt < 4; mt++) {
        int row0 = wm * 64 + mt * 16 + (lane >> 2);
#pragma unroll
        for (int half = 0; half < 2; half++) {
            int row = row0 + half * 8;
            int bi = b0 + (row >> 6), l = row & 63;
            float* Ob = O + (long long)bi * sO;
            const float* Rb = R ? R + (long long)bi * sR : nullptr;
#pragma unroll
            for (int nn = 0; nn < 4; nn++) {
                int n = n0 + wn * 32 + nn * 8 + (lane & 3) * 2;
#pragma unroll
                for (int e = 0; e < 2; e++) {
                    float v = acc[mt][nn][half * 2 + e];
                    int nc = n + e;
                    if (bias) v += bias[nc];
                    if (relu) v = fmaxf(v, 0.f);
                    long long o = (OMODE == 1) ? ((long long)nc * 64 + l)
                                               : ((long long)l * ldo + nc);
                    if (Rb)    v += Rb[o];
                    if (plane) v += plane[o];
                    Ob[o] = v;
                }
            }
        }
    }
}

// ---------------------------------------------------------------------------
// pgemm: per-batch GEMM, all fp16. A (b)64xK; B (b)NbxK.
// CTA = 64 x 64 tile, grid (N/64, BATCH). 2-stage cp.async.
// ---------------------------------------------------------------------------
__global__ void __launch_bounds__(256) pgemm_k(
    const __half* __restrict__ Af, long long sA,
    const __half* __restrict__ Bf, long long sB,
    float* __restrict__ O, long long sO, int ldo,
    const float* __restrict__ bM, long long sbM,
    const float* __restrict__ bN, long long sbN,
    int K)
{
    extern __shared__ char dsm[];
    const uint32_t tb = (smem_u32(dsm) + 1023u) & ~1023u;

    const int tid = threadIdx.x, lane = tid & 31, wid = tid >> 5;
    const int n0 = blockIdx.x * 64;
    const int b  = blockIdx.y;
    const int wm = wid >> 1, wn = wid & 1;    // warp tile 16x32

    const __half* Afb = Af + (long long)b * sA;
    const __half* Bfb = Bf + (long long)b * sB + (long long)n0 * K;

    float acc[4][4];
#pragma unroll
    for (int a = 0; a < 4; a++)
#pragma unroll
        for (int c = 0; c < 4; c++) acc[a][c] = 0.f;

    const int nch = K / 64;

    auto copy_chunk = [&](int ci, int s) {
        const int k0 = ci * 64;
        const uint32_t tA = tb + (s * 2 + 0) * PG_TILE;
        const uint32_t tB = tb + (s * 2 + 1) * PG_TILE;
#pragma unroll
        for (int it = 0; it < 2; it++) {
            int idx = tid + it * 256;          // 0..511
            int r = idx >> 3, c = idx & 7;
            uint32_t doff = SW128((uint32_t)(r * 128 + c * 16));
            long long off = (long long)r * K + k0 + c * 8;
            cpa16(tA + doff, Afb + off);
            cpa16(tB + doff, Bfb + off);
        }
    };

    copy_chunk(0, 0); cp_commit();

    const int rl = lane & 15, chalf = lane >> 4;

    for (int i = 0; i < nch; i++) {
        cp_wait0();
        __syncthreads();
        if (i + 1 < nch) { copy_chunk(i + 1, (i + 1) & 1); cp_commit(); }

        const int s = i & 1;
        const uint32_t tA = tb + (s * 2 + 0) * PG_TILE;
        const uint32_t tB = tb + (s * 2 + 1) * PG_TILE;

#pragma unroll
        for (int ks = 0; ks < 4; ks++) {
            const uint32_t coff = (uint32_t)((ks * 2 + chalf) * 16);
            uint32_t af[4], bf[2][4];
            {
                uint32_t off = SW128((uint32_t)((wm * 16 + rl) * 128) + coff);
                ldsm4(af, tA + off);
            }
#pragma unroll
            for (int np = 0; np < 2; np++) {
                uint32_t off = SW128((uint32_t)((wn * 32 + np * 16 + rl) * 128) + coff);
                ldsm4(bf[np], tB + off);
            }
#pragma unroll
            for (int np = 0; np < 2; np++)
#pragma unroll
                for (int j = 0; j < 2; j++)
                    mma_f16(acc[np * 2 + j], af, bf[np][j], bf[np][j + 2]);
        }
    }

    float* Ob = O + (long long)b * sO;
    const float* bMp = bM ? bM + (long long)b * sbM : nullptr;
    const float* bNp = bN ? bN + (long long)b * sbN : nullptr;
#pragma unroll
    for (int half = 0; half < 2; half++) {
        int row = wm * 16 + (lane >> 2) + half * 8;
#pragma unroll
        for (int nn = 0; nn < 4; nn++) {
            int n = n0 + wn * 32 + nn * 8 + (lane & 3) * 2;
#pragma unroll
            for (int e = 0; e < 2; e++) {
                float v = acc[nn][half * 2 + e];
                int nc = n + e;
                if (bMp) v += bMp[row];
                if (bNp) v += bNp[nc];
                Ob[(long long)row * ldo + nc] = v;
            }
        }
    }
}

// ---------------------------------------------------------------------------
// SIMT GEMM (8x8 microtile) — scores/av/Bt only
// ---------------------------------------------------------------------------
template<int BM, int BN, bool TA, bool TB, bool OT, bool RELU>
__global__ void __launch_bounds__((BM/8)*(BN/8)) gemm8_k(
    const float* __restrict__ A, long long sA, int lda,
    const float* __restrict__ B, long long sB, int ldb,
    float* __restrict__ C, long long sC, int ldc,
    const float* __restrict__ bM, long long sbM,
    const float* __restrict__ bN, long long sbN,
    const float* __restrict__ R, long long sR,
    const float* __restrict__ plane,
    __half* __restrict__ Cf,
    float alpha, int K)
{
    constexpr int THREADS = (BM / 8) * (BN / 8);
    constexpr int LA = BM * 16 / THREADS;
    constexpr int LB = BN * 16 / THREADS;

    const int bz = blockIdx.z;
    A += (long long)bz * sA;
    B += (long long)bz * sB;
    C += (long long)bz * sC;
    __half* Cfp = Cf ? Cf + (long long)bz * sC : nullptr;
    const float* bMp = bM ? bM + (long long)bz * sbM : nullptr;
    const float* bNp = bN ? bN + (long long)bz * sbN : nullptr;
    const float* Rp  = R  ? R  + (long long)bz * sR  : nullptr;

    const int m0 = blockIdx.y * BM;
    const int n0 = blockIdx.x * BN;

    __shared__ float As[2][16][BM + 4];
    __shared__ float Bs[2][16][BN + 4];

    const int tid = threadIdx.x;
    const int tx = tid % (BN / 8);
    const int ty = tid / (BN / 8);

    float acc[8][8];
#pragma unroll
    for (int r = 0; r < 8; r++)
#pragma unroll
        for (int c = 0; c < 8; c++) acc[r][c] = 0.f;

    float ra[LA], rb[LB];

#pragma unroll
    for (int i = 0; i < LA; i++) {
        int idx = tid + i * THREADS;
        if (TA) { int k = idx / BM, m = idx % BM; As[0][k][m] = A[(long long)k * lda + (m0 + m)]; }
        else    { int m = idx / 16, k = idx % 16; As[0][k][m] = A[(long long)(m0 + m) * lda + k]; }
    }
#pragma unroll
    for (int i = 0; i < LB; i++) {
        int idx = tid + i * THREADS;
        if (TB) { int n = idx / 16, k = idx % 16; Bs[0][k][n] = B[(long long)(n0 + n) * ldb + k]; }
        else    { int k = idx / BN, n = idx % BN; Bs[0][k][n] = B[(long long)k * ldb + (n0 + n)]; }
    }
    __syncthreads();

    int buf = 0;
    for (int k0 = 0; k0 < K; k0 += 16) {
        const bool more = (k0 + 16) < K;
        if (more) {
            const int kn = k0 + 16;
#pragma unroll
            for (int i = 0; i < LA; i++) {
                int idx = tid + i * THREADS;
                if (TA) { int k = idx / BM, m = idx % BM; ra[i] = A[(long long)(kn + k) * lda + (m0 + m)]; }
                else    { int m = idx / 16, k = idx % 16; ra[i] = A[(long long)(m0 + m) * lda + (kn + k)]; }
            }
#pragma unroll
            for (int i = 0; i < LB; i++) {
                int idx = tid + i * THREADS;
                if (TB) { int n = idx / 16, k = idx % 16; rb[i] = B[(long long)(n0 + n) * ldb + (kn + k)]; }
                else    { int k = idx / BN, n = idx % BN; rb[i] = B[(long long)(kn + k) * ldb + (n0 + n)]; }
            }
        }

#pragma unroll
        for (int k = 0; k < 16; k++) {
            float a[8], b[8];
            float4 t;
            t = *reinterpret_cast<const float4*>(&As[buf][k][ty * 8]);
            a[0] = t.x; a[1] = t.y; a[2] = t.z; a[3] = t.w;
            t = *reinterpret_cast<const float4*>(&As[buf][k][ty * 8 + 4]);
            a[4] = t.x; a[5] = t.y; a[6] = t.z; a[7] = t.w;
            t = *reinterpret_cast<const float4*>(&Bs[buf][k][tx * 8]);
            b[0] = t.x; b[1] = t.y; b[2] = t.z; b[3] = t.w;
            t = *reinterpret_cast<const float4*>(&Bs[buf][k][tx * 8 + 4]);
            b[4] = t.x; b[5] = t.y; b[6] = t.z; b[7] = t.w;
#pragma unroll
            for (int r = 0; r < 8; r++)
#pragma unroll
                for (int c = 0; c < 8; c++)
                    acc[r][c] = fmaf(a[r], b[c], acc[r][c]);
        }

        if (more) {
            int nb = buf ^ 1;
#pragma unroll
            for (int i = 0; i < LA; i++) {
                int idx = tid + i * THREADS;
                if (TA) { int k = idx / BM, m = idx % BM; As[nb][k][m] = ra[i]; }
                else    { int m = idx / 16, k = idx % 16; As[nb][k][m] = ra[i]; }
            }
#pragma unroll
            for (int i = 0; i < LB; i++) {
                int idx = tid + i * THREADS;
                if (TB) { int n = idx / 16, k = idx % 16; Bs[nb][k][n] = rb[i]; }
                else    { int k = idx / BN, n = idx % BN; Bs[nb][k][n] = rb[i]; }
            }
            __syncthreads();
            buf = nb;
        }
    }

#pragma unroll
    for (int r = 0; r < 8; r++) {
        int m = m0 + ty * 8 + r;
#pragma unroll
        for (int c = 0; c < 8; c++) {
            int n = n0 + tx * 8 + c;
            float v = acc[r][c] * alpha;
            if (bMp) v += bMp[m];
            if (bNp) v += bNp[n];
            if (RELU) v = fmaxf(v, 0.f);
            long long o = OT ? ((long long)n * ldc + m) : ((long long)m * ldc + n);
            if (Rp) v += Rp[o];
            if (plane) v += plane[o];
            C[o] = v;
            if (Cfp) Cfp[o] = __float2half(v);
        }
    }
}

// ---------------------------------------------------------------------------
// Small kernels
// ---------------------------------------------------------------------------
// weight -> fp16 single, n x k (k-contiguous); trans: src is k x n
__global__ void wconv_k(const float* __restrict__ src, int ld, int trans,
                        long long total, int KK, __half* __restrict__ out)
{
    long long idx = (long long)blockIdx.x * 256 + threadIdx.x;
    if (idx >= total) return;
    int n = (int)(idx / KK), k = (int)(idx % KK);
    float v = trans ? src[(long long)k * ld + n] : src[(long long)n * ld + k];
    out[idx] = __float2half(v);
}

__global__ void rowdot_k(const float* __restrict__ x, const float* __restrict__ w,
                         float* __restrict__ out, int rowsPerB, int rowOff)
{
    int warp = (blockIdx.x * blockDim.x + threadIdx.x) >> 5;
    int lane = threadIdx.x & 31;
    int b = warp / rowsPerB;
    int i = warp % rowsPerB;
    if (b >= BATCH) return;
    const float* src = x + ((long long)b * SEQ + rowOff + i) * DIM;
    float s = 0.f;
    for (int d = lane; d < DIM; d += 32) s += src[d] * w[d];
#pragma unroll
    for (int o = 16; o > 0; o >>= 1) s += __shfl_down_sync(0xffffffffu, s, o);
    if (lane == 0) out[warp] = s;
}

// cw3 = C * w3 as fp16 (b,64,768), vectorized x2
__global__ void cw3split_k(const float* __restrict__ x, const float* __restrict__ w3,
                           __half* __restrict__ out)
{
    long long i2 = (long long)blockIdx.x * 256 + threadIdx.x;
    if (i2 >= SZ_BD / 2) return;
    int d2 = (int)(i2 % (DIM / 2));
    long long row = i2 / (DIM / 2);
    long long b = row / LC, i = row % LC;
    float2 xv = reinterpret_cast<const float2*>(x)[((long long)b * SEQ + i) * (DIM / 2) + d2];
    float2 wv = reinterpret_cast<const float2*>(w3)[d2];
    __half2 o = __floats2half2_rn(xv.x * wv.x, xv.y * wv.y);
    reinterpret_cast<__half2*>(out)[i2] = o;
}

// Q part of x as fp16 (b,448,768), vectorized x2
__global__ void qsplit_k(const float* __restrict__ x, __half* __restrict__ out)
{
    long long i2 = (long long)blockIdx.x * 256 + threadIdx.x;
    if (i2 >= SZ_Q / 2) return;
    int d2 = (int)(i2 % (DIM / 2));
    long long row = i2 / (DIM / 2);
    long long b = row / LQ, j = row % LQ;
    float2 v = reinterpret_cast<const float2*>(x)[((long long)b * SEQ + LC + j) * (DIM / 2) + d2];
    reinterpret_cast<__half2*>(out)[i2] = __floats2half2_rn(v.x, v.y);
}

// Q^T as fp16 (b,768,448) via tiled transpose
__global__ void qtsplit_k(const float* __restrict__ x, __half* __restrict__ out)
{
    __shared__ float sm[32][33];
    int j0 = blockIdx.x * 32, d0 = blockIdx.y * 32, b = blockIdx.z;
    int tx = threadIdx.x & 31, ty = threadIdx.x >> 5;
#pragma unroll
    for (int r = 0; r < 4; r++) {
        int j = j0 + ty + r * 8;
        sm[ty + r * 8][tx] = x[((long long)b * SEQ + LC + j) * DIM + d0 + tx];
    }
    __syncthreads();
    __half* ob = out + (long long)b * DIM * LQ;
#pragma unroll
    for (int r = 0; r < 4; r++) {
        int d = d0 + ty + r * 8;
        ob[(long long)d * LQ + j0 + tx] = __float2half(sm[tx][ty + r * 8]);
    }
}

// row softmax, float in -> fp16 out (S1)
__global__ void softmax_rows_f16_k(const float* __restrict__ in,
                                   __half* __restrict__ out, int len)
{
    long long base = (long long)blockIdx.x * len;
    int t = threadIdx.x;
    __shared__ float sh[128];
    float m = -1e30f;
    for (int i = t; i < len; i += 128) m = fmaxf(m, in[base + i]);
    sh[t] = m; __syncthreads();
    for (int o = 64; o > 0; o >>= 1) { if (t < o) sh[t] = fmaxf(sh[t], sh[t + o]); __syncthreads(); }
    m = sh[0]; __syncthreads();
    float s = 0.f;
    float loc[4];
    for (int i = t, c = 0; i < len; i += 128, c++) { float e = expf(in[base + i] - m); loc[c] = e; s += e; }
    sh[t] = s; __syncthreads();
    for (int o = 64; o > 0; o >>= 1) { if (t < o) sh[t] += sh[t + o]; __syncthreads(); }
    float inv = 1.f / sh[0];
    for (int i = t, c = 0; i < len; i += 128, c++)
        out[base + i] = __float2half(loc[c] * inv);
}

// row softmax, float in-place (scores)
__global__ void softmax_rows_k(const float* __restrict__ in, float* __restrict__ out, int len)
{
    long long base = (long long)blockIdx.x * len;
    int t = threadIdx.x;
    __shared__ float sh[128];
    float m = -1e30f;
    for (int i = t; i < len; i += 128) m = fmaxf(m, in[base + i]);
    sh[t] = m; __syncthreads();
    for (int o = 64; o > 0; o >>= 1) { if (t < o) sh[t] = fmaxf(sh[t], sh[t + o]); __syncthreads(); }
    m = sh[0]; __syncthreads();
    float s = 0.f;
    for (int i = t; i < len; i += 128) { float e = expf(in[base + i] - m); out[base + i] = e; s += e; }
    sh[t] = s; __syncthreads();
    for (int o = 64; o > 0; o >>= 1) { if (t < o) sh[t] += sh[t + o]; __syncthreads(); }
    float inv = 1.f / sh[0];
    for (int i = t; i < len; i += 128) out[base + i] *= inv;
}

// column softmax over i of S (B,64,448) -> fp16
__global__ void softmax_cols_f16_k(const float* __restrict__ S, __half* __restrict__ out)
{
    int idx = blockIdx.x * blockDim.x + threadIdx.x;
    if (idx >= BATCH * LQ) return;
    int b = idx / LQ, j = idx % LQ;
    long long base = (long long)b * LC * LQ + j;
    float m = -1e30f;
#pragma unroll 4
    for (int i = 0; i < LC; i++) m = fmaxf(m, S[base + (long long)i * LQ]);
    float s = 0.f;
    float e[LC];
#pragma unroll 4
    for (int i = 0; i < LC; i++) { e[i] = expf(S[base + (long long)i * LQ] - m); s += e[i]; }
    float inv = 1.f / s;
#pragma unroll 4
    for (int i = 0; i < LC; i++)
        out[base + (long long)i * LQ] = __float2half(e[i] * inv);
}

// fused concat-gather + depthwise k=5 -> Y fp16 (b,l,c)
__global__ void rz_dw_fuse_k(const float* __restrict__ x, const float* __restrict__ Abuf,
                             const float* __restrict__ Btbuf,
                             const float* __restrict__ dww, const float* __restrict__ dwb,
                             __half* __restrict__ Y)
{
    int c = blockIdx.x * 256 + threadIdx.x;
    int l = blockIdx.y;
    int b = blockIdx.z;
    int g = c / DIM;
    int d = c % DIM;
    float acc = dwb[c];
#pragma unroll
    for (int t = 0; t < 5; t++) {
        int l2 = l + t - 2;
        if (l2 < 0 || l2 >= LC) continue;
        float v;
        long long xo = ((long long)b * SEQ + l2) * DIM + d;
        long long ao = ((long long)b * LC + l2) * DIM + d;
        if (g == 0)      v = x[xo];
        else if (g == 1) v = Abuf[ao];
        else if (g == 2) v = x[xo] * Abuf[ao];
        else             v = x[xo] * Btbuf[ao];
        acc = fmaf(v, dww[c * 5 + t], acc);
    }
    Y[((long long)b * LC + l) * C4 + c] = __float2half(acc);
}

__global__ void pe_init_k(float* __restrict__ pe)
{
    int idx = blockIdx.x * 256 + threadIdx.x;
    if (idx >= DIM * LC) return;
    int d = idx / LC, l = idx % LC;
    float fd = (float)d;
    bool even = (d & 1) == 0;
    float freq = even ? powf(10000.f, -fd / 768.f)
                      : -powf(10000.f, (1.f - fd) / 768.f);
    float ph = even ? 0.f : 1.57079632679489662f;
    pe[idx] = sinf((float)l * freq + ph);
}

__global__ void ln_stats_k(const float* __restrict__ in, float* __restrict__ mean,
                           float* __restrict__ rstd)
{
    int b = blockIdx.x;
    const float4* p = reinterpret_cast<const float4*>(in + (long long)b * (DIM * LC));
    float s = 0.f, s2 = 0.f;
    for (int i = threadIdx.x; i < DIM * LC / 4; i += 512) {
        float4 v = p[i];
        s += v.x + v.y + v.z + v.w;
        s2 += v.x * v.x + v.y * v.y + v.z * v.z + v.w * v.w;
    }
    __shared__ float sh[512], sh2[512];
    sh[threadIdx.x] = s; sh2[threadIdx.x] = s2; __syncthreads();
    for (int o = 256; o > 0; o >>= 1) {
        if (threadIdx.x < o) { sh[threadIdx.x] += sh[threadIdx.x + o]; sh2[threadIdx.x] += sh2[threadIdx.x + o]; }
        __syncthreads();
    }
    if (threadIdx.x == 0) {
        float m = sh[0] / (float)(DIM * LC);
        float var = sh2[0] / (float)(DIM * LC) - m * m;
        mean[b] = m;
        rstd[b] = rsqrtf(var + 1e-5f);
    }
}

// fused ln + dwconv3 + transpose-convert: (b,d,l) float -> (b,l,d) fp16
__global__ void ln_conv_t_k(const float* __restrict__ in, const float* __restrict__ mean,
                            const float* __restrict__ rstd, const float* __restrict__ lw,
                            const float* __restrict__ lb, const float* __restrict__ cw,
                            const float* __restrict__ cb,
                            __half* __restrict__ out)
{
    __shared__ float sm[32][65];
    int b = blockIdx.x, d0 = blockIdx.y * 32;
    float mu = mean[b], rs = rstd[b];
    const float* ib = in + (long long)b * (DIM * LC);
#pragma unroll
    for (int it = 0; it < 8; it++) {
        int idx = threadIdx.x + it * 256;
        int dd = idx >> 6, l = idx & 63;
        int d = d0 + dd;
        const float* rowp = ib + (long long)d * 64;
        int wb = d * 64;
        float a = cb[d];
#pragma unroll
        for (int t = 0; t < 3; t++) {
            int l2 = l + t - 1;
            if (l2 < 0 || l2 >= 64) continue;
            float v = (rowp[l2] - mu) * rs * lw[wb + l2] + lb[wb + l2];
            a = fmaf(v, cw[d * 3 + t], a);
        }
        sm[dd][l] = a;
    }
    __syncthreads();
    __half* ob = out + (long long)b * 64 * 768;
#pragma unroll
    for (int it = 0; it < 8; it++) {
        int idx = threadIdx.x + it * 256;
        int l = idx >> 5, dd = idx & 31;
        ob[(long long)l * 768 + d0 + dd] = __float2half(sm[dd][l]);
    }
}

// fused ln + transpose-convert (no conv)
__global__ void ln_apply_t_k(const float* __restrict__ in, const float* __restrict__ mean,
                             const float* __restrict__ rstd, const float* __restrict__ lw,
                             const float* __restrict__ lb,
                             __half* __restrict__ out)
{
    __shared__ float sm[32][65];
    int b = blockIdx.x, d0 = blockIdx.y * 32;
    float mu = mean[b], rs = rstd[b];
    const float* ib = in + (long long)b * (DIM * LC);
#pragma unroll
    for (int it = 0; it < 8; it++) {
        int idx = threadIdx.x + it * 256;
        int dd = idx >> 6, l = idx & 63;
        int d = d0 + dd;
        float v = (ib[(long long)d * 64 + l] - mu) * rs * lw[d * 64 + l] + lb[d * 64 + l];
        sm[dd][l] = v;
    }
    __syncthreads();
    __half* ob = out + (long long)b * 64 * 768;
#pragma unroll
    for (int it = 0; it < 8; it++) {
        int idx = threadIdx.x + it * 256;
        int l = idx >> 5, dd = idx & 31;
        ob[(long long)l * 768 + d0 + dd] = __float2half(sm[dd][l]);
    }
}

__global__ void final_head_k(const float* __restrict__ X, const float* __restrict__ w,
                             const float* __restrict__ bias, float* __restrict__ out)
{
    int b = blockIdx.x;
    const float* p = X + (long long)b * (DIM * LC);
    float s = 0.f;
    for (int i = threadIdx.x; i < DIM * LC; i += 256) s = fmaf(p[i], w[i], s);
    __shared__ float sh[256];
    sh[threadIdx.x] = s; __syncthreads();
    for (int o = 128; o > 0; o >>= 1) {
        if (threadIdx.x < o) sh[threadIdx.x] += sh[threadIdx.x + o];
        __syncthreads();
    }
    if (threadIdx.x == 0) out[b] = 1.f / (1.f + expf(-(sh[0] + bias[0])));
}

// ---------------------------------------------------------------------------
// Host-side helpers
// ---------------------------------------------------------------------------
template<int BM, int BN, bool TA, bool TB, bool OT, bool RELU>
static inline void run_gemm(const float* A, long long sA, int lda,
                            const float* B, long long sB, int ldb,
                            float* C, long long sC, int ldc,
                            const float* bM, long long sbM,
                            const float* bN, long long sbN,
                            const float* R, long long sR,
                            const float* plane,
                            __half* Cf,
                            float alpha, int M, int N, int K)
{
    dim3 grid(N / BN, M / BM, BATCH);
    gemm8_k<BM, BN, TA, TB, OT, RELU><<<grid, (BM / 8) * (BN / 8)>>>(
        A, sA, lda, B, sB, ldb, C, sC, ldc, bM, sbM, bN, sbN, R, sR, plane, Cf, alpha, K);
}

template<int OMODE>
static inline void run_mgemm(const __half* Af, const __half* Bf,
                             float* O, long long sO, int ldo,
                             const float* bias,
                             const float* R, long long sR,
                             const float* plane,
                             int N, int K, int relu)
{
    cudaFuncSetAttribute((const void*)mgemm_k<OMODE>,
                         cudaFuncAttributeMaxDynamicSharedMemorySize, MT_SMEM);
    dim3 grid(N / 128, BATCH / 2);
    mgemm_k<OMODE><<<grid, 256, MT_SMEM>>>(Af, Bf, O, sO, ldo, bias, R, sR, plane, K, relu);
}

static inline void run_pgemm(const __half* Af, long long sA,
                             const __half* Bf, long long sB,
                             float* O, long long sO, int ldo,
                             const float* bM, long long sbM,
                             const float* bN, long long sbN,
                             int N, int K)
{
    cudaFuncSetAttribute((const void*)pgemm_k,
                         cudaFuncAttributeMaxDynamicSharedMemorySize, PG_SMEM);
    dim3 grid(N / 64, BATCH);
    pgemm_k<<<grid, 256, PG_SMEM>>>(Af, sA, Bf, sB, O, sO, ldo, bM, sbM, bN, sbN, K);
}

struct EncW {
    const float *c1dw, *c1db, *c1pw, *c1pb;
    const float *c2dw, *c2db, *c2pw, *c2pb;
    const float *wq, *wk, *wv, *wo;
    const float *fcw, *fcb;
    const float *nbw, *nbb, *n1w, *n1b, *n2w, *n2b, *nEw, *nEb;
};

struct HfW {
    __half *rz, *c1, *c2, *fc, *qkv, *wo;
};

static void enc_block(const float* Xin,
                      float* t1, float* t2, float* t3, float* qkv,
                      float* Xout, const float* outPlane, float* mean, float* rstd,
                      float* scores, const EncW& w, const HfW& hw,
                      __half* a1, __half* a2)
{
    const float scale = 0.03608439182435161f; // 1/sqrt(768)
    const long long SQKV = 64LL * 2304;

    // ln(normb) + dwconv c1 -> a1 fp16 (b,l,d)
    ln_stats_k<<<BATCH, 512>>>(Xin, mean, rstd);
    ln_conv_t_k<<<dim3(BATCH, 24), 256>>>(Xin, mean, rstd, w.nbw, w.nbb, w.c1dw, w.c1db, a1);
    // pw c1 (mma): relu(W@x + b) + Xin -> t2 (b,d,l)
    run_mgemm<1>(a1, hw.c1, t2, SE, 64, w.c1pb, Xin, SE, nullptr, DIM, DIM, 1);
    // ln(norm1) + dwconv c2 -> a1
    ln_stats_k<<<BATCH, 512>>>(t2, mean, rstd);
    ln_conv_t_k<<<dim3(BATCH, 24), 256>>>(t2, mean, rstd, w.n1w, w.n1b, w.c2dw, w.c2db, a1);
    // pw c2 (mma) -> t3
    run_mgemm<1>(a1, hw.c2, t3, SE, 64, w.c2pb, t2, SE, nullptr, DIM, DIM, 1);
    // ln(norm2) -> a1
    ln_stats_k<<<BATCH, 512>>>(t3, mean, rstd);
    ln_apply_t_k<<<dim3(BATCH, 24), 256>>>(t3, mean, rstd, w.n2w, w.n2b, a1);
    // merged q|k|v (mma, N=2304): (b,l,2304)
    run_mgemm<0>(a1, hw.qkv, qkv, SQKV, 2304, nullptr, nullptr, 0, nullptr, 2304, DIM, 0);
    // scores = q @ k^T * scale (SIMT fp32)
    run_gemm<64, 64, false, true, false, false>(qkv, SQKV, 2304, qkv + DIM, SQKV, 2304,
                                                scores, (long long)LC * LC, LC,
                                                nullptr, 0, nullptr, 0, nullptr, 0, nullptr, nullptr,
                                                scale, LC, LC, DIM);
    softmax_rows_k<<<BATCH * LC, 128>>>(scores, scores, LC);
    // av = attn @ v -> t1 float + a2 fp16 (b,l,768)
    run_gemm<64, 128, false, false, false, false>(scores, (long long)LC * LC, LC, qkv + 2 * DIM, SQKV, 2304,
                                                  t1, SE, DIM,
                                                  nullptr, 0, nullptr, 0, nullptr, 0, nullptr, a2,
                                                  1.f, LC, DIM, LC);
    // sa = (av @ wo)^T + t3 -> t2 (mma, transposed store)
    run_mgemm<1>(a2, hw.wo, t2, SE, 64, nullptr, t3, SE, nullptr, DIM, DIM, 0);
    // ln(norme) -> a1
    ln_stats_k<<<BATCH, 512>>>(t2, mean, rstd);
    ln_apply_t_k<<<dim3(BATCH, 24), 256>>>(t2, mean, rstd, w.nEw, w.nEb, a1);
    // fc + relu + t2 (+pe) -> Xout (mma)
    run_mgemm<1>(a1, hw.fc, Xout, SE, 64, w.fcb, t2, SE, outPlane, DIM, DIM, 1);
}

// ---------------------------------------------------------------------------
// Entry point
// ---------------------------------------------------------------------------
extern "C" void kernel_launch(void* const* d_in, const int* in_sizes, int n_in,
                              void* d_out, int out_size)
{
    (void)in_sizes; (void)n_in; (void)out_size;
    const float* x       = (const float*)d_in[0];
    const float* Wv      = (const float*)d_in[1];
    const float* rz_dw_w = (const float*)d_in[2];
    const float* rz_dw_b = (const float*)d_in[3];
    const float* rz_pw_w = (const float*)d_in[4];
    const float* rz_pw_b = (const float*)d_in[5];
    EncW w;
    w.c1dw = (const float*)d_in[6];  w.c1db = (const float*)d_in[7];
    w.c1pw = (const float*)d_in[8];  w.c1pb = (const float*)d_in[9];
    w.c2dw = (const float*)d_in[10]; w.c2db = (const float*)d_in[11];
    w.c2pw = (const float*)d_in[12]; w.c2pb = (const float*)d_in[13];
    w.wq   = (const float*)d_in[14]; w.wk   = (const float*)d_in[15];
    w.wv   = (const float*)d_in[16]; w.wo   = (const float*)d_in[17];
    w.fcw  = (const float*)d_in[18]; w.fcb  = (const float*)d_in[19];
    w.nbw  = (const float*)d_in[20]; w.nbb  = (const float*)d_in[21];
    w.n1w  = (const float*)d_in[22]; w.n1b  = (const float*)d_in[23];
    w.n2w  = (const float*)d_in[24]; w.n2b  = (const float*)d_in[25];
    w.nEw  = (const float*)d_in[26]; w.nEb  = (const float*)d_in[27];
    const float* fcf_w = (const float*)d_in[28];
    const float* fcf_b = (const float*)d_in[29];

    float* pool = nullptr;
    cudaGetSymbolAddress((void**)&pool, g_pool);

    float* c1s  = pool + OFF_C1;
    float* q2s  = pool + OFF_Q2;
    float* S    = pool + OFF_S;
    float* Abuf = pool + OFF_A;
    float* Tbuf = pool + OFF_T;
    float* Btb  = pool + OFF_BT;
    float* E[8];
    for (int i = 0; i < 8; i++) E[i] = pool + OFF_E0 + (long long)i * SZ_E;
    float* mean = pool + OFF_MEAN;
    float* rstd = pool + OFF_RSTD;
    float* pe   = pool + OFF_PE;

    __half* cw3f = (__half*)(pool + OFF_CW3);
    __half* S1f  = (__half*)(pool + OFF_S1);
    __half* S2f  = (__half*)(pool + OFF_S2);
    __half* Yf   = (__half*)(pool + OFF_Y);
    __half* Qsf  = (__half*)(pool + OFF_QS);
    __half* Qtf  = (__half*)(pool + OFF_QT);
    __half* a1   = (__half*)(pool + OFF_ACT);
    __half* a2   = a1 + SZ_BD;

    HfW hw;
    {
        __half* p = (__half*)(pool + OFF_WB);
        hw.rz  = p; p += (long long)DIM * C4;
        hw.c1  = p; p += (long long)DIM * DIM;
        hw.c2  = p; p += (long long)DIM * DIM;
        hw.fc  = p; p += (long long)DIM * DIM;
        hw.qkv = p; p += 3LL * DIM * DIM;
        hw.wo  = p;
    }

    const long long WDD = (long long)DIM * DIM;

    pe_init_k<<<(DIM * LC + 255) / 256, 256>>>(pe);
    rowdot_k<<<(BATCH * LC * 32) / 256, 256>>>(x, Wv, c1s, LC, 0);
    rowdot_k<<<(BATCH * LQ * 32) / 256, 256>>>(x, Wv + DIM, q2s, LQ, LC);
    cw3split_k<<<(int)((SZ_BD / 2 + 255) / 256), 256>>>(x, Wv + 2 * DIM, cw3f);
    qsplit_k<<<(int)((SZ_Q / 2 + 255) / 256), 256>>>(x, Qsf);

    // S = cw3 @ Q^T + c1[:,None] + q2[None,:]   (tensor, per-batch)
    run_pgemm(cw3f, 64LL * DIM, Qsf, (long long)LQ * DIM,
              S, (long long)LC * LQ, LQ, c1s, LC, q2s, LQ, LQ, DIM);

    qtsplit_k<<<dim3(LQ / 32, DIM / 32, BATCH), 256>>>(x, Qtf);
    softmax_rows_f16_k<<<BATCH * LC, 128>>>(S, S1f, LQ);
    softmax_cols_f16_k<<<(BATCH * LQ + 255) / 256, 256>>>(S, S2f);

    // A = S1 @ Q  (tensor, per-batch; B = Q^T)
    run_pgemm(S1f, (long long)LC * LQ, Qtf, (long long)DIM * LQ,
              Abuf, (long long)LC * DIM, DIM, nullptr, 0, nullptr, 0, DIM, LQ);

    // T = S1 @ S2^T (tensor, per-batch)
    run_pgemm(S1f, (long long)LC * LQ, S2f, (long long)LC * LQ,
              Tbuf, (long long)LC * LC, LC, nullptr, 0, nullptr, 0, LC, LQ);

    // Bt = T @ C (SIMT, K=64)
    run_gemm<64, 128, false, false, false, false>(
        Tbuf, (long long)LC * LC, LC,
        x, (long long)SEQ * DIM, DIM,
        Btb, (long long)LC * DIM, DIM,
        nullptr, 0, nullptr, 0, nullptr, 0, nullptr, nullptr, 1.f, LC, DIM, LC);

    // fused concat-gather + depthwise k=5 -> Y fp16 (b,l,c)
    rz_dw_fuse_k<<<dim3(C4 / 256, LC, BATCH), 256>>>(x, Abuf, Btb, rz_dw_w, rz_dw_b, Yf);

    // ---- weight conversion (fp16, n x k, k-contiguous) ----
    {
        long long trz = (long long)DIM * C4;
        int gs = (int)((WDD + 255) / 256);
        wconv_k<<<(int)((trz + 255) / 256), 256>>>(rz_pw_w, C4, 0, trz, C4, hw.rz);
        wconv_k<<<gs, 256>>>(w.c1pw, DIM, 0, WDD, DIM, hw.c1);
        wconv_k<<<gs, 256>>>(w.c2pw, DIM, 0, WDD, DIM, hw.c2);
        wconv_k<<<gs, 256>>>(w.fcw,  DIM, 0, WDD, DIM, hw.fc);
        wconv_k<<<gs, 256>>>(w.wq,   DIM, 1, WDD, DIM, hw.qkv);
        wconv_k<<<gs, 256>>>(w.wk,   DIM, 1, WDD, DIM, hw.qkv + WDD);
        wconv_k<<<gs, 256>>>(w.wv,   DIM, 1, WDD, DIM, hw.qkv + 2 * WDD);
        wconv_k<<<gs, 256>>>(w.wo,   DIM, 1, WDD, DIM, hw.wo);
    }

    // pointwise 3072 -> 768 (mma): +bias +pe -> E0 (b,d,l)
    run_mgemm<1>(Yf, hw.rz, E[0], SE, 64, rz_pw_b, nullptr, 0, pe, DIM, C4, 0);

    // ---- two encoder blocks ----
    enc_block(E[0], E[1], E[2], E[3], E[4], E[7], pe, mean, rstd, Tbuf, w, hw, a1, a2);
    enc_block(E[7], E[1], E[2], E[3], E[4], E[0], nullptr, mean, rstd, Tbuf, w, hw, a1, a2);

    // ---- final sigmoid head ----
    final_head_k<<<BATCH, 256>>>(E[0], fcf_w, fcf_b, (float*)d_out);
}

// round 8
// speedup vs baseline: 4.6442x; 1.1104x over previous
#include <cuda_runtime.h>
#include <cuda_fp16.h>
#include <math.h>
#include <stdint.h>

// ---------------------------------------------------------------------------
// Problem constants
// ---------------------------------------------------------------------------
namespace {
constexpr int BATCH = 128;
constexpr int LC    = 64;
constexpr int LQ    = 448;
constexpr int DIM   = 768;
constexpr int SEQ   = 512;
constexpr int C4    = 3072;

constexpr long long SZ_C1 = (long long)BATCH * LC;
constexpr long long SZ_Q2 = (long long)BATCH * LQ;
constexpr long long SZ_BD = (long long)BATCH * LC * DIM;
constexpr long long SZ_S  = (long long)BATCH * LC * LQ;
constexpr long long SZ_T  = (long long)BATCH * LC * LC;
constexpr long long SZ_Y  = (long long)BATCH * LC * C4;
constexpr long long SZ_E  = SZ_BD;
constexpr long long SZ_Q  = (long long)BATCH * LQ * DIM;
constexpr long long SE    = (long long)DIM * LC;

constexpr long long OFF_C1  = 0;
constexpr long long OFF_Q2  = OFF_C1 + SZ_C1;
constexpr long long OFF_CW3 = OFF_Q2 + SZ_Q2;    // cw3 fp16
constexpr long long OFF_S   = OFF_CW3 + SZ_BD;
constexpr long long OFF_S1  = OFF_S  + SZ_S;     // S1 fp16
constexpr long long OFF_S2  = OFF_S1 + SZ_S;     // S2 fp16
constexpr long long OFF_A   = OFF_S2 + SZ_S;
constexpr long long OFF_T   = OFF_A  + SZ_BD;    // fp32 scores / front T scratch
constexpr long long OFF_BT  = OFF_T  + SZ_T;
constexpr long long OFF_Y   = OFF_BT + SZ_BD;    // Y fp16
constexpr long long OFF_E0  = OFF_Y  + SZ_Y;
constexpr long long OFF_MEAN = OFF_E0 + 8 * SZ_E;
constexpr long long OFF_RSTD = OFF_MEAN + 128;
constexpr long long OFF_PE   = OFF_RSTD + 128;
constexpr long long OFF_ACT  = OFF_PE + (long long)DIM * LC;  // fp16 act buffers
constexpr long long OFF_WB   = OFF_ACT + 2 * SZ_BD;
constexpr long long WB_FLOATS = ((long long)DIM * C4 + 7LL * DIM * DIM) / 2 + 64;
constexpr long long OFF_QS   = OFF_WB + WB_FLOATS;   // Q fp16 (b,448,768)
constexpr long long OFF_QT   = OFF_QS + SZ_Q;        // Q^T fp16 (b,768,448)
constexpr long long POOL_SZ  = OFF_QT + SZ_Q;
} // namespace

__device__ float g_pool[POOL_SZ];

// ---------------------------------------------------------------------------
// Family-portable tensor-core primitives
// ---------------------------------------------------------------------------
__device__ __forceinline__ uint32_t smem_u32(const void* p) {
    uint32_t a;
    asm("{ .reg .u64 t; cvta.to.shared.u64 t, %1; cvt.u32.u64 %0, t; }" : "=r"(a) : "l"(p));
    return a;
}
#define SW128(o) ((o) ^ (((o) >> 3) & 0x70))

__device__ __forceinline__ void cpa16(uint32_t dst, const void* src) {
    asm volatile("cp.async.cg.shared.global [%0], [%1], 16;" :: "r"(dst), "l"(src) : "memory");
}
__device__ __forceinline__ void cp_commit() {
    asm volatile("cp.async.commit_group;" ::: "memory");
}
__device__ __forceinline__ void cp_wait1() {
    asm volatile("cp.async.wait_group 1;" ::: "memory");
}
__device__ __forceinline__ void cp_wait0() {
    asm volatile("cp.async.wait_group 0;" ::: "memory");
}
__device__ __forceinline__ void ldsm4(uint32_t* r, uint32_t a) {
    asm volatile("ldmatrix.sync.aligned.m8n8.x4.shared.b16 {%0,%1,%2,%3}, [%4];"
        : "=r"(r[0]), "=r"(r[1]), "=r"(r[2]), "=r"(r[3]) : "r"(a));
}
__device__ __forceinline__ void mma_f16(float* d, const uint32_t* a, uint32_t b0, uint32_t b1) {
    asm volatile("mma.sync.aligned.m16n8k16.row.col.f32.f16.f16.f32 "
        "{%0,%1,%2,%3}, {%4,%5,%6,%7}, {%8,%9}, {%0,%1,%2,%3};"
        : "+f"(d[0]), "+f"(d[1]), "+f"(d[2]), "+f"(d[3])
        : "r"(a[0]), "r"(a[1]), "r"(a[2]), "r"(a[3]), "r"(b0), "r"(b1));
}

// ---------------------------------------------------------------------------
// mgemm: batch-shared-B tensor GEMM (fp16 in, fp32 accum)
// A: (BATCH*64, K) k-contig; B: (N, K) k-contig (weights).
// CTA = 128 rows x 128 cols, K-chunks of 64, 3-stage cp.async, 2 CTA/SM.
// OMODE 0: o = l*ldo + n ; OMODE 1: o = n*64 + l
// Output: fp32 (O) or fp16 (Oh) at o.
// ---------------------------------------------------------------------------
namespace {
constexpr int MT_TILE = 16384;                  // 128 rows x 128 B
constexpr int MT_SMEM = 3 * 2 * MT_TILE + 1024; // 97 KB
constexpr int PG_TILE = 8192;                   // 64 rows x 128 B
constexpr int PG_SMEM = 2 * 2 * PG_TILE + 1024; // 33 KB
}

template<int OMODE>
__global__ void __launch_bounds__(256, 2) mgemm_k(
    const __half* __restrict__ Af,
    const __half* __restrict__ Bf,
    float* __restrict__ O, __half* __restrict__ Oh, long long sO, int ldo,
    const float* __restrict__ bias,
    const float* __restrict__ R, long long sR,
    const float* __restrict__ plane,
    int K, int relu)
{
    extern __shared__ char dsm[];
    const uint32_t tb = (smem_u32(dsm) + 1023u) & ~1023u;

    const int tid = threadIdx.x, lane = tid & 31, wid = tid >> 5;
    const int n0 = blockIdx.x * 128;
    const int rbase = blockIdx.y * 128;
    const int wm = wid & 1, wn = wid >> 1;   // warp tile 64x32

    float acc[4][4][4];
#pragma unroll
    for (int a = 0; a < 4; a++)
#pragma unroll
        for (int b = 0; b < 4; b++)
#pragma unroll
            for (int c = 0; c < 4; c++) acc[a][b][c] = 0.f;

    const int nch = K / 64;

    auto copy_chunk = [&](int ci, int s) {
        const int k0 = ci * 64;
        const uint32_t tA = tb + (s * 2 + 0) * MT_TILE;
        const uint32_t tB = tb + (s * 2 + 1) * MT_TILE;
#pragma unroll
        for (int it = 0; it < 4; it++) {
            int idx = tid + it * 256;
            int r = idx >> 3, c = idx & 7;
            uint32_t doff = SW128((uint32_t)(r * 128 + c * 16));
            cpa16(tA + doff, Af + (long long)(rbase + r) * K + k0 + c * 8);
            cpa16(tB + doff, Bf + (long long)(n0 + r) * K + k0 + c * 8);
        }
    };

    copy_chunk(0, 0); cp_commit();
    copy_chunk(1, 1); cp_commit();

    const int rl = lane & 15, chalf = lane >> 4;

    for (int i = 0; i < nch; i++) {
        if (i + 1 < nch) cp_wait1(); else cp_wait0();
        __syncthreads();
        if (i + 2 < nch) { copy_chunk(i + 2, (i + 2) % 3); cp_commit(); }

        const int s = i % 3;
        const uint32_t tA = tb + (s * 2 + 0) * MT_TILE;
        const uint32_t tB = tb + (s * 2 + 1) * MT_TILE;

#pragma unroll
        for (int ks = 0; ks < 4; ks++) {
            const uint32_t coff = (uint32_t)((ks * 2 + chalf) * 16);
            uint32_t af[4][4], bf[2][4];
#pragma unroll
            for (int mt = 0; mt < 4; mt++) {
                uint32_t off = SW128((uint32_t)((wm * 64 + mt * 16 + rl) * 128) + coff);
                ldsm4(af[mt], tA + off);
            }
#pragma unroll
            for (int np = 0; np < 2; np++) {
                uint32_t off = SW128((uint32_t)((wn * 32 + np * 16 + rl) * 128) + coff);
                ldsm4(bf[np], tB + off);
            }
#pragma unroll
            for (int mt = 0; mt < 4; mt++)
#pragma unroll
                for (int np = 0; np < 2; np++)
#pragma unroll
                    for (int j = 0; j < 2; j++)
                        mma_f16(acc[mt][np * 2 + j], af[mt], bf[np][j], bf[np][j + 2]);
        }
    }

    const int b0 = blockIdx.y * 2;
#pragma unroll
    for (int mt = 0; mt < 4; mt++) {
        int row0 = wm * 64 + mt * 16 + (lane >> 2);
#pragma unroll
        for (int half = 0; half < 2; half++) {
            int row = row0 + half * 8;
            int bi = b0 + (row >> 6), l = row & 63;
            float* Ob = O ? O + (long long)bi * sO : nullptr;
            __half* Ohb = Oh ? Oh + (long long)bi * sO : nullptr;
            const float* Rb = R ? R + (long long)bi * sR : nullptr;
#pragma unroll
            for (int nn = 0; nn < 4; nn++) {
                int n = n0 + wn * 32 + nn * 8 + (lane & 3) * 2;
#pragma unroll
                for (int e = 0; e < 2; e++) {
                    float v = acc[mt][nn][half * 2 + e];
                    int nc = n + e;
                    if (bias) v += bias[nc];
                    if (relu) v = fmaxf(v, 0.f);
                    long long o = (OMODE == 1) ? ((long long)nc * 64 + l)
                                               : ((long long)l * ldo + nc);
                    if (Rb)    v += Rb[o];
                    if (plane) v += plane[o];
                    if (Ohb) Ohb[o] = __float2half(v);
                    else     Ob[o]  = v;
                }
            }
        }
    }
}

// ---------------------------------------------------------------------------
// pgemm: per-batch GEMM, fp16 in, fp32 accum.
// A: (b) 64 rows x K (row stride lda); B: (b) Nb rows x K (row stride ldb).
// CTA = 64 x 64 tile, grid (N/64, BATCH). 2-stage cp.async.
// Out: o = row*ldo + n; fp32 (O) or fp16 (Oh). v = acc*alpha + bM[row] + bN[n].
// ---------------------------------------------------------------------------
__global__ void __launch_bounds__(256) pgemm_k(
    const __half* __restrict__ Af, long long sA, int lda,
    const __half* __restrict__ Bf, long long sB, int ldb,
    float* __restrict__ O, __half* __restrict__ Oh, long long sO, int ldo,
    const float* __restrict__ bM, long long sbM,
    const float* __restrict__ bN, long long sbN,
    float alpha, int K)
{
    extern __shared__ char dsm[];
    const uint32_t tb = (smem_u32(dsm) + 1023u) & ~1023u;

    const int tid = threadIdx.x, lane = tid & 31, wid = tid >> 5;
    const int n0 = blockIdx.x * 64;
    const int b  = blockIdx.y;
    const int wm = wid >> 1, wn = wid & 1;    // warp tile 16x32

    const __half* Afb = Af + (long long)b * sA;
    const __half* Bfb = Bf + (long long)b * sB + (long long)n0 * ldb;

    float acc[4][4];
#pragma unroll
    for (int a = 0; a < 4; a++)
#pragma unroll
        for (int c = 0; c < 4; c++) acc[a][c] = 0.f;

    const int nch = K / 64;

    auto copy_chunk = [&](int ci, int s) {
        const int k0 = ci * 64;
        const uint32_t tA = tb + (s * 2 + 0) * PG_TILE;
        const uint32_t tB = tb + (s * 2 + 1) * PG_TILE;
#pragma unroll
        for (int it = 0; it < 2; it++) {
            int idx = tid + it * 256;          // 0..511
            int r = idx >> 3, c = idx & 7;
            uint32_t doff = SW128((uint32_t)(r * 128 + c * 16));
            cpa16(tA + doff, Afb + (long long)r * lda + k0 + c * 8);
            cpa16(tB + doff, Bfb + (long long)r * ldb + k0 + c * 8);
        }
    };

    copy_chunk(0, 0); cp_commit();

    const int rl = lane & 15, chalf = lane >> 4;

    for (int i = 0; i < nch; i++) {
        cp_wait0();
        __syncthreads();
        if (i + 1 < nch) { copy_chunk(i + 1, (i + 1) & 1); cp_commit(); }

        const int s = i & 1;
        const uint32_t tA = tb + (s * 2 + 0) * PG_TILE;
        const uint32_t tB = tb + (s * 2 + 1) * PG_TILE;

#pragma unroll
        for (int ks = 0; ks < 4; ks++) {
            const uint32_t coff = (uint32_t)((ks * 2 + chalf) * 16);
            uint32_t af[4], bf[2][4];
            {
                uint32_t off = SW128((uint32_t)((wm * 16 + rl) * 128) + coff);
                ldsm4(af, tA + off);
            }
#pragma unroll
            for (int np = 0; np < 2; np++) {
                uint32_t off = SW128((uint32_t)((wn * 32 + np * 16 + rl) * 128) + coff);
                ldsm4(bf[np], tB + off);
            }
#pragma unroll
            for (int np = 0; np < 2; np++)
#pragma unroll
                for (int j = 0; j < 2; j++)
                    mma_f16(acc[np * 2 + j], af, bf[np][j], bf[np][j + 2]);
        }
    }

    float* Ob = O ? O + (long long)b * sO : nullptr;
    __half* Ohb = Oh ? Oh + (long long)b * sO : nullptr;
    const float* bMp = bM ? bM + (long long)b * sbM : nullptr;
    const float* bNp = bN ? bN + (long long)b * sbN : nullptr;
#pragma unroll
    for (int half = 0; half < 2; half++) {
        int row = wm * 16 + (lane >> 2) + half * 8;
#pragma unroll
        for (int nn = 0; nn < 4; nn++) {
            int n = n0 + wn * 32 + nn * 8 + (lane & 3) * 2;
#pragma unroll
            for (int e = 0; e < 2; e++) {
                float v = acc[nn][half * 2 + e] * alpha;
                int nc = n + e;
                if (bMp) v += bMp[row];
                if (bNp) v += bNp[nc];
                long long o = (long long)row * ldo + nc;
                if (Ohb) Ohb[o] = __float2half(v);
                else     Ob[o]  = v;
            }
        }
    }
}

// ---------------------------------------------------------------------------
// Small kernels
// ---------------------------------------------------------------------------
// weight -> fp16, n x k (k-contiguous); trans: src is k x n
__global__ void wconv_k(const float* __restrict__ src, int ld, int trans,
                        long long total, int KK, __half* __restrict__ out)
{
    long long idx = (long long)blockIdx.x * 256 + threadIdx.x;
    if (idx >= total) return;
    int n = (int)(idx / KK), k = (int)(idx % KK);
    float v = trans ? src[(long long)k * ld + n] : src[(long long)n * ld + k];
    out[idx] = __float2half(v);
}

__global__ void rowdot_k(const float* __restrict__ x, const float* __restrict__ w,
                         float* __restrict__ out, int rowsPerB, int rowOff)
{
    int warp = (blockIdx.x * blockDim.x + threadIdx.x) >> 5;
    int lane = threadIdx.x & 31;
    int b = warp / rowsPerB;
    int i = warp % rowsPerB;
    if (b >= BATCH) return;
    const float* src = x + ((long long)b * SEQ + rowOff + i) * DIM;
    float s = 0.f;
    for (int d = lane; d < DIM; d += 32) s += src[d] * w[d];
#pragma unroll
    for (int o = 16; o > 0; o >>= 1) s += __shfl_down_sync(0xffffffffu, s, o);
    if (lane == 0) out[warp] = s;
}

// cw3 = C * w3 as fp16 (b,64,768), vectorized x2
__global__ void cw3split_k(const float* __restrict__ x, const float* __restrict__ w3,
                           __half* __restrict__ out)
{
    long long i2 = (long long)blockIdx.x * 256 + threadIdx.x;
    if (i2 >= SZ_BD / 2) return;
    int d2 = (int)(i2 % (DIM / 2));
    long long row = i2 / (DIM / 2);
    long long b = row / LC, i = row % LC;
    float2 xv = reinterpret_cast<const float2*>(x)[((long long)b * SEQ + i) * (DIM / 2) + d2];
    float2 wv = reinterpret_cast<const float2*>(w3)[d2];
    reinterpret_cast<__half2*>(out)[i2] = __floats2half2_rn(xv.x * wv.x, xv.y * wv.y);
}

// Q part of x as fp16 (b,448,768), vectorized x2
__global__ void qsplit_k(const float* __restrict__ x, __half* __restrict__ out)
{
    long long i2 = (long long)blockIdx.x * 256 + threadIdx.x;
    if (i2 >= SZ_Q / 2) return;
    int d2 = (int)(i2 % (DIM / 2));
    long long row = i2 / (DIM / 2);
    long long b = row / LQ, j = row % LQ;
    float2 v = reinterpret_cast<const float2*>(x)[((long long)b * SEQ + LC + j) * (DIM / 2) + d2];
    reinterpret_cast<__half2*>(out)[i2] = __floats2half2_rn(v.x, v.y);
}

// Q^T as fp16 (b,768,448) via tiled transpose
__global__ void qtsplit_k(const float* __restrict__ x, __half* __restrict__ out)
{
    __shared__ float sm[32][33];
    int j0 = blockIdx.x * 32, d0 = blockIdx.y * 32, b = blockIdx.z;
    int tx = threadIdx.x & 31, ty = threadIdx.x >> 5;
#pragma unroll
    for (int r = 0; r < 4; r++) {
        int j = j0 + ty + r * 8;
        sm[ty + r * 8][tx] = x[((long long)b * SEQ + LC + j) * DIM + d0 + tx];
    }
    __syncthreads();
    __half* ob = out + (long long)b * DIM * LQ;
#pragma unroll
    for (int r = 0; r < 4; r++) {
        int d = d0 + ty + r * 8;
        ob[(long long)d * LQ + j0 + tx] = __float2half(sm[tx][ty + r * 8]);
    }
}

// C^T as fp16 (b,768,64) via tiled transpose
__global__ void ctsplit_k(const float* __restrict__ x, __half* __restrict__ out)
{
    __shared__ float sm[32][33];
    int l0 = blockIdx.x * 32, d0 = blockIdx.y * 32, b = blockIdx.z;
    int tx = threadIdx.x & 31, ty = threadIdx.x >> 5;
#pragma unroll
    for (int r = 0; r < 4; r++) {
        int l = l0 + ty + r * 8;
        sm[ty + r * 8][tx] = x[((long long)b * SEQ + l) * DIM + d0 + tx];
    }
    __syncthreads();
    __half* ob = out + (long long)b * SE;
#pragma unroll
    for (int r = 0; r < 4; r++) {
        int d = d0 + ty + r * 8;
        ob[(long long)d * 64 + l0 + tx] = __float2half(sm[tx][ty + r * 8]);
    }
}

// row softmax, float in -> fp16 out
__global__ void softmax_rows_f16_k(const float* __restrict__ in,
                                   __half* __restrict__ out, int len)
{
    long long base = (long long)blockIdx.x * len;
    int t = threadIdx.x;
    __shared__ float sh[128];
    float m = -1e30f;
    for (int i = t; i < len; i += 128) m = fmaxf(m, in[base + i]);
    sh[t] = m; __syncthreads();
    for (int o = 64; o > 0; o >>= 1) { if (t < o) sh[t] = fmaxf(sh[t], sh[t + o]); __syncthreads(); }
    m = sh[0]; __syncthreads();
    float s = 0.f;
    float loc[4];
    for (int i = t, c = 0; i < len; i += 128, c++) { float e = expf(in[base + i] - m); loc[c] = e; s += e; }
    sh[t] = s; __syncthreads();
    for (int o = 64; o > 0; o >>= 1) { if (t < o) sh[t] += sh[t + o]; __syncthreads(); }
    float inv = 1.f / sh[0];
    for (int i = t, c = 0; i < len; i += 128, c++)
        out[base + i] = __float2half(loc[c] * inv);
}

// column softmax over i of S (B,64,448) -> fp16
__global__ void softmax_cols_f16_k(const float* __restrict__ S, __half* __restrict__ out)
{
    int idx = blockIdx.x * blockDim.x + threadIdx.x;
    if (idx >= BATCH * LQ) return;
    int b = idx / LQ, j = idx % LQ;
    long long base = (long long)b * LC * LQ + j;
    float m = -1e30f;
#pragma unroll 4
    for (int i = 0; i < LC; i++) m = fmaxf(m, S[base + (long long)i * LQ]);
    float s = 0.f;
    float e[LC];
#pragma unroll 4
    for (int i = 0; i < LC; i++) { e[i] = expf(S[base + (long long)i * LQ] - m); s += e[i]; }
    float inv = 1.f / s;
#pragma unroll 4
    for (int i = 0; i < LC; i++)
        out[base + (long long)i * LQ] = __float2half(e[i] * inv);
}

// fused concat-gather + depthwise k=5 -> Y fp16 (b,l,c)
__global__ void rz_dw_fuse_k(const float* __restrict__ x, const float* __restrict__ Abuf,
                             const float* __restrict__ Btbuf,
                             const float* __restrict__ dww, const float* __restrict__ dwb,
                             __half* __restrict__ Y)
{
    int c = blockIdx.x * 256 + threadIdx.x;
    int l = blockIdx.y;
    int b = blockIdx.z;
    int g = c / DIM;
    int d = c % DIM;
    float acc = dwb[c];
#pragma unroll
    for (int t = 0; t < 5; t++) {
        int l2 = l + t - 2;
        if (l2 < 0 || l2 >= LC) continue;
        float v;
        long long xo = ((long long)b * SEQ + l2) * DIM + d;
        long long ao = ((long long)b * LC + l2) * DIM + d;
        if (g == 0)      v = x[xo];
        else if (g == 1) v = Abuf[ao];
        else if (g == 2) v = x[xo] * Abuf[ao];
        else             v = x[xo] * Btbuf[ao];
        acc = fmaf(v, dww[c * 5 + t], acc);
    }
    Y[((long long)b * LC + l) * C4 + c] = __float2half(acc);
}

__global__ void pe_init_k(float* __restrict__ pe)
{
    int idx = blockIdx.x * 256 + threadIdx.x;
    if (idx >= DIM * LC) return;
    int d = idx / LC, l = idx % LC;
    float fd = (float)d;
    bool even = (d & 1) == 0;
    float freq = even ? powf(10000.f, -fd / 768.f)
                      : -powf(10000.f, (1.f - fd) / 768.f);
    float ph = even ? 0.f : 1.57079632679489662f;
    pe[idx] = sinf((float)l * freq + ph);
}

__global__ void ln_stats_k(const float* __restrict__ in, float* __restrict__ mean,
                           float* __restrict__ rstd)
{
    int b = blockIdx.x;
    const float4* p = reinterpret_cast<const float4*>(in + (long long)b * (DIM * LC));
    float s = 0.f, s2 = 0.f;
    for (int i = threadIdx.x; i < DIM * LC / 4; i += 512) {
        float4 v = p[i];
        s += v.x + v.y + v.z + v.w;
        s2 += v.x * v.x + v.y * v.y + v.z * v.z + v.w * v.w;
    }
    __shared__ float sh[512], sh2[512];
    sh[threadIdx.x] = s; sh2[threadIdx.x] = s2; __syncthreads();
    for (int o = 256; o > 0; o >>= 1) {
        if (threadIdx.x < o) { sh[threadIdx.x] += sh[threadIdx.x + o]; sh2[threadIdx.x] += sh2[threadIdx.x + o]; }
        __syncthreads();
    }
    if (threadIdx.x == 0) {
        float m = sh[0] / (float)(DIM * LC);
        float var = sh2[0] / (float)(DIM * LC) - m * m;
        mean[b] = m;
        rstd[b] = rsqrtf(var + 1e-5f);
    }
}

// fused ln + dwconv3 + transpose-convert: (b,d,l) float -> (b,l,d) fp16
__global__ void ln_conv_t_k(const float* __restrict__ in, const float* __restrict__ mean,
                            const float* __restrict__ rstd, const float* __restrict__ lw,
                            const float* __restrict__ lb, const float* __restrict__ cw,
                            const float* __restrict__ cb,
                            __half* __restrict__ out)
{
    __shared__ float sm[32][65];
    int b = blockIdx.x, d0 = blockIdx.y * 32;
    float mu = mean[b], rs = rstd[b];
    const float* ib = in + (long long)b * (DIM * LC);
#pragma unroll
    for (int it = 0; it < 8; it++) {
        int idx = threadIdx.x + it * 256;
        int dd = idx >> 6, l = idx & 63;
        int d = d0 + dd;
        const float* rowp = ib + (long long)d * 64;
        int wb = d * 64;
        float a = cb[d];
#pragma unroll
        for (int t = 0; t < 3; t++) {
            int l2 = l + t - 1;
            if (l2 < 0 || l2 >= 64) continue;
            float v = (rowp[l2] - mu) * rs * lw[wb + l2] + lb[wb + l2];
            a = fmaf(v, cw[d * 3 + t], a);
        }
        sm[dd][l] = a;
    }
    __syncthreads();
    __half* ob = out + (long long)b * 64 * 768;
#pragma unroll
    for (int it = 0; it < 8; it++) {
        int idx = threadIdx.x + it * 256;
        int l = idx >> 5, dd = idx & 31;
        ob[(long long)l * 768 + d0 + dd] = __float2half(sm[dd][l]);
    }
}

// fused ln + transpose-convert (no conv)
__global__ void ln_apply_t_k(const float* __restrict__ in, const float* __restrict__ mean,
                             const float* __restrict__ rstd, const float* __restrict__ lw,
                             const float* __restrict__ lb,
                             __half* __restrict__ out)
{
    __shared__ float sm[32][65];
    int b = blockIdx.x, d0 = blockIdx.y * 32;
    float mu = mean[b], rs = rstd[b];
    const float* ib = in + (long long)b * (DIM * LC);
#pragma unroll
    for (int it = 0; it < 8; it++) {
        int idx = threadIdx.x + it * 256;
        int dd = idx >> 6, l = idx & 63;
        int d = d0 + dd;
        float v = (ib[(long long)d * 64 + l] - mu) * rs * lw[d * 64 + l] + lb[d * 64 + l];
        sm[dd][l] = v;
    }
    __syncthreads();
    __half* ob = out + (long long)b * 64 * 768;
#pragma unroll
    for (int it = 0; it < 8; it++) {
        int idx = threadIdx.x + it * 256;
        int l = idx >> 5, dd = idx & 31;
        ob[(long long)l * 768 + d0 + dd] = __float2half(sm[dd][l]);
    }
}

__global__ void final_head_k(const float* __restrict__ X, const float* __restrict__ w,
                             const float* __restrict__ bias, float* __restrict__ out)
{
    int b = blockIdx.x;
    const float* p = X + (long long)b * (DIM * LC);
    float s = 0.f;
    for (int i = threadIdx.x; i < DIM * LC; i += 256) s = fmaf(p[i], w[i], s);
    __shared__ float sh[256];
    sh[threadIdx.x] = s; __syncthreads();
    for (int o = 128; o > 0; o >>= 1) {
        if (threadIdx.x < o) sh[threadIdx.x] += sh[threadIdx.x + o];
        __syncthreads();
    }
    if (threadIdx.x == 0) out[b] = 1.f / (1.f + expf(-(sh[0] + bias[0])));
}

// ---------------------------------------------------------------------------
// Host-side helpers
// ---------------------------------------------------------------------------
template<int OMODE>
static inline void run_mgemm(const __half* Af, const __half* Bf,
                             float* O, __half* Oh, long long sO, int ldo,
                             const float* bias,
                             const float* R, long long sR,
                             const float* plane,
                             int N, int K, int relu)
{
    cudaFuncSetAttribute((const void*)mgemm_k<OMODE>,
                         cudaFuncAttributeMaxDynamicSharedMemorySize, MT_SMEM);
    dim3 grid(N / 128, BATCH / 2);
    mgemm_k<OMODE><<<grid, 256, MT_SMEM>>>(Af, Bf, O, Oh, sO, ldo, bias, R, sR, plane, K, relu);
}

static inline void run_pgemm(const __half* Af, long long sA, int lda,
                             const __half* Bf, long long sB, int ldb,
                             float* O, __half* Oh, long long sO, int ldo,
                             const float* bM, long long sbM,
                             const float* bN, long long sbN,
                             float alpha, int N, int K)
{
    cudaFuncSetAttribute((const void*)pgemm_k,
                         cudaFuncAttributeMaxDynamicSharedMemorySize, PG_SMEM);
    dim3 grid(N / 64, BATCH);
    pgemm_k<<<grid, 256, PG_SMEM>>>(Af, sA, lda, Bf, sB, ldb, O, Oh, sO, ldo,
                                    bM, sbM, bN, sbN, alpha, K);
}

struct EncW {
    const float *c1dw, *c1db, *c1pw, *c1pb;
    const float *c2dw, *c2db, *c2pw, *c2pb;
    const float *wq, *wk, *wv, *wo;
    const float *fcw, *fcb;
    const float *nbw, *nbb, *n1w, *n1b, *n2w, *n2b, *nEw, *nEb;
};

struct HfW {
    __half *rz, *c1, *c2, *fc, *qkv, *wo;
};

static void enc_block(const float* Xin,
                      float* t2, float* t3, float* scores,
                      __half* qkf, __half* vT, __half* attnf,
                      float* Xout, const float* outPlane, float* mean, float* rstd,
                      const EncW& w, const HfW& hw,
                      __half* a1, __half* a2)
{
    const float scale = 0.03608439182435161f; // 1/sqrt(768)
    const long long SQK = 64LL * 1536;
    const long long SAT = 64LL * 64;

    // ln(normb) + dwconv c1 -> a1 fp16 (b,l,d)
    ln_stats_k<<<BATCH, 512>>>(Xin, mean, rstd);
    ln_conv_t_k<<<dim3(BATCH, 24), 256>>>(Xin, mean, rstd, w.nbw, w.nbb, w.c1dw, w.c1db, a1);
    // pw c1 (mma): relu(W@x + b) + Xin -> t2 (b,d,l)
    run_mgemm<1>(a1, hw.c1, t2, nullptr, SE, 64, w.c1pb, Xin, SE, nullptr, DIM, DIM, 1);
    // ln(norm1) + dwconv c2 -> a1
    ln_stats_k<<<BATCH, 512>>>(t2, mean, rstd);
    ln_conv_t_k<<<dim3(BATCH, 24), 256>>>(t2, mean, rstd, w.n1w, w.n1b, w.c2dw, w.c2db, a1);
    // pw c2 (mma) -> t3
    run_mgemm<1>(a1, hw.c2, t3, nullptr, SE, 64, w.c2pb, t2, SE, nullptr, DIM, DIM, 1);
    // ln(norm2) -> a1
    ln_stats_k<<<BATCH, 512>>>(t3, mean, rstd);
    ln_apply_t_k<<<dim3(BATCH, 24), 256>>>(t3, mean, rstd, w.n2w, w.n2b, a1);
    // q|k (mma, N=1536) -> qkf fp16 (b,l,1536)
    run_mgemm<0>(a1, hw.qkv, nullptr, qkf, SQK, 1536, nullptr, nullptr, 0, nullptr, 1536, DIM, 0);
    // v (mma, N=768, transposed) -> vT fp16 (b,768,64)
    run_mgemm<1>(a1, hw.qkv + 2LL * DIM * DIM, nullptr, vT, SE, 64,
                 nullptr, nullptr, 0, nullptr, DIM, DIM, 0);
    // scores = q @ k^T * scale (tensor, per-batch) -> fp32
    run_pgemm(qkf, SQK, 1536, qkf + DIM, SQK, 1536,
              scores, nullptr, SAT, 64, nullptr, 0, nullptr, 0, scale, LC, DIM);
    softmax_rows_f16_k<<<BATCH * LC, 128>>>(scores, attnf, LC);
    // av = attn @ v (tensor; B = v^T) -> a2 fp16 (b,l,768)
    run_pgemm(attnf, SAT, 64, vT, SE, 64,
              nullptr, a2, SE, DIM, nullptr, 0, nullptr, 0, 1.f, DIM, LC);
    // sa = (av @ wo)^T + t3 -> t2 (mma, transposed store)
    run_mgemm<1>(a2, hw.wo, t2, nullptr, SE, 64, nullptr, t3, SE, nullptr, DIM, DIM, 0);
    // ln(norme) -> a1
    ln_stats_k<<<BATCH, 512>>>(t2, mean, rstd);
    ln_apply_t_k<<<dim3(BATCH, 24), 256>>>(t2, mean, rstd, w.nEw, w.nEb, a1);
    // fc + relu + t2 (+pe) -> Xout (mma)
    run_mgemm<1>(a1, hw.fc, Xout, nullptr, SE, 64, w.fcb, t2, SE, outPlane, DIM, DIM, 1);
}

// ---------------------------------------------------------------------------
// Entry point
// ---------------------------------------------------------------------------
extern "C" void kernel_launch(void* const* d_in, const int* in_sizes, int n_in,
                              void* d_out, int out_size)
{
    (void)in_sizes; (void)n_in; (void)out_size;
    const float* x       = (const float*)d_in[0];
    const float* Wv      = (const float*)d_in[1];
    const float* rz_dw_w = (const float*)d_in[2];
    const float* rz_dw_b = (const float*)d_in[3];
    const float* rz_pw_w = (const float*)d_in[4];
    const float* rz_pw_b = (const float*)d_in[5];
    EncW w;
    w.c1dw = (const float*)d_in[6];  w.c1db = (const float*)d_in[7];
    w.c1pw = (const float*)d_in[8];  w.c1pb = (const float*)d_in[9];
    w.c2dw = (const float*)d_in[10]; w.c2db = (const float*)d_in[11];
    w.c2pw = (const float*)d_in[12]; w.c2pb = (const float*)d_in[13];
    w.wq   = (const float*)d_in[14]; w.wk   = (const float*)d_in[15];
    w.wv   = (const float*)d_in[16]; w.wo   = (const float*)d_in[17];
    w.fcw  = (const float*)d_in[18]; w.fcb  = (const float*)d_in[19];
    w.nbw  = (const float*)d_in[20]; w.nbb  = (const float*)d_in[21];
    w.n1w  = (const float*)d_in[22]; w.n1b  = (const float*)d_in[23];
    w.n2w  = (const float*)d_in[24]; w.n2b  = (const float*)d_in[25];
    w.nEw  = (const float*)d_in[26]; w.nEb  = (const float*)d_in[27];
    const float* fcf_w = (const float*)d_in[28];
    const float* fcf_b = (const float*)d_in[29];

    float* pool = nullptr;
    cudaGetSymbolAddress((void**)&pool, g_pool);

    float* c1s  = pool + OFF_C1;
    float* q2s  = pool + OFF_Q2;
    float* S    = pool + OFF_S;
    float* Abuf = pool + OFF_A;
    float* Tbuf = pool + OFF_T;     // fp32 scores scratch
    float* Btb  = pool + OFF_BT;
    float* E[8];
    for (int i = 0; i < 8; i++) E[i] = pool + OFF_E0 + (long long)i * SZ_E;
    float* mean = pool + OFF_MEAN;
    float* rstd = pool + OFF_RSTD;
    float* pe   = pool + OFF_PE;

    __half* cw3f  = (__half*)(pool + OFF_CW3);
    __half* S1f   = (__half*)(pool + OFF_S1);
    __half* S2f   = (__half*)(pool + OFF_S2);
    __half* Yf    = (__half*)(pool + OFF_Y);
    __half* Qsf   = (__half*)(pool + OFF_QS);
    __half* Qtf   = (__half*)(pool + OFF_QT);
    __half* a1    = (__half*)(pool + OFF_ACT);
    __half* a2    = a1 + SZ_BD;
    __half* qkf   = (__half*)E[4];   // (b,64,1536) = SZ_E floats exactly
    __half* vT    = (__half*)E[5];   // (b,768,64)
    __half* attnf = (__half*)E[6];   // (b,64,64); also front-end Tf
    __half* Tf    = (__half*)E[6];
    __half* cTf   = (__half*)E[1];   // (b,768,64), front-end only

    HfW hw;
    {
        __half* p = (__half*)(pool + OFF_WB);
        hw.rz  = p; p += (long long)DIM * C4;
        hw.c1  = p; p += (long long)DIM * DIM;
        hw.c2  = p; p += (long long)DIM * DIM;
        hw.fc  = p; p += (long long)DIM * DIM;
        hw.qkv = p; p += 3LL * DIM * DIM;
        hw.wo  = p;
    }

    const long long WDD = (long long)DIM * DIM;

    pe_init_k<<<(DIM * LC + 255) / 256, 256>>>(pe);
    rowdot_k<<<(BATCH * LC * 32) / 256, 256>>>(x, Wv, c1s, LC, 0);
    rowdot_k<<<(BATCH * LQ * 32) / 256, 256>>>(x, Wv + DIM, q2s, LQ, LC);
    cw3split_k<<<(int)((SZ_BD / 2 + 255) / 256), 256>>>(x, Wv + 2 * DIM, cw3f);
    qsplit_k<<<(int)((SZ_Q / 2 + 255) / 256), 256>>>(x, Qsf);

    // S = cw3 @ Q^T + c1[:,None] + q2[None,:]   (tensor, per-batch)
    run_pgemm(cw3f, 64LL * DIM, DIM, Qsf, (long long)LQ * DIM, DIM,
              S, nullptr, (long long)LC * LQ, LQ, c1s, LC, q2s, LQ, 1.f, LQ, DIM);

    qtsplit_k<<<dim3(LQ / 32, DIM / 32, BATCH), 256>>>(x, Qtf);
    ctsplit_k<<<dim3(2, DIM / 32, BATCH), 256>>>(x, cTf);
    softmax_rows_f16_k<<<BATCH * LC, 128>>>(S, S1f, LQ);
    softmax_cols_f16_k<<<(BATCH * LQ + 255) / 256, 256>>>(S, S2f);

    // A = S1 @ Q (tensor; B = Q^T) -> fp32
    run_pgemm(S1f, (long long)LC * LQ, LQ, Qtf, (long long)DIM * LQ, LQ,
              Abuf, nullptr, (long long)LC * DIM, DIM, nullptr, 0, nullptr, 0, 1.f, DIM, LQ);

    // T = S1 @ S2^T (tensor) -> fp16
    run_pgemm(S1f, (long long)LC * LQ, LQ, S2f, (long long)LC * LQ, LQ,
              nullptr, Tf, (long long)LC * LC, LC, nullptr, 0, nullptr, 0, 1.f, LC, LQ);

    // Bt = T @ C (tensor; B = C^T) -> fp32
    run_pgemm(Tf, (long long)LC * LC, LC, cTf, SE, LC,
              Btb, nullptr, (long long)LC * DIM, DIM, nullptr, 0, nullptr, 0, 1.f, DIM, LC);

    // fused concat-gather + depthwise k=5 -> Y fp16 (b,l,c)
    rz_dw_fuse_k<<<dim3(C4 / 256, LC, BATCH), 256>>>(x, Abuf, Btb, rz_dw_w, rz_dw_b, Yf);

    // ---- weight conversion (fp16, n x k, k-contiguous) ----
    {
        long long trz = (long long)DIM * C4;
        int gs = (int)((WDD + 255) / 256);
        wconv_k<<<(int)((trz + 255) / 256), 256>>>(rz_pw_w, C4, 0, trz, C4, hw.rz);
        wconv_k<<<gs, 256>>>(w.c1pw, DIM, 0, WDD, DIM, hw.c1);
        wconv_k<<<gs, 256>>>(w.c2pw, DIM, 0, WDD, DIM, hw.c2);
        wconv_k<<<gs, 256>>>(w.fcw,  DIM, 0, WDD, DIM, hw.fc);
        wconv_k<<<gs, 256>>>(w.wq,   DIM, 1, WDD, DIM, hw.qkv);
        wconv_k<<<gs, 256>>>(w.wk,   DIM, 1, WDD, DIM, hw.qkv + WDD);
        wconv_k<<<gs, 256>>>(w.wv,   DIM, 1, WDD, DIM, hw.qkv + 2 * WDD);
        wconv_k<<<gs, 256>>>(w.wo,   DIM, 1, WDD, DIM, hw.wo);
    }

    // pointwise 3072 -> 768 (mma): +bias +pe -> E0 (b,d,l)
    run_mgemm<1>(Yf, hw.rz, E[0], nullptr, SE, 64, rz_pw_b, nullptr, 0, pe, DIM, C4, 0);

    // ---- two encoder blocks ----
    enc_block(E[0], E[2], E[3], Tbuf, qkf, vT, attnf, E[7], pe, mean, rstd, w, hw, a1, a2);
    enc_block(E[7], E[2], E[3], Tbuf, qkf, vT, attnf, E[0], nullptr, mean, rstd, w, hw, a1, a2);

    // ---- final sigmoid head ----
    final_head_k<<<BATCH, 256>>>(E[0], fcf_w, fcf_b, (float*)d_out);
}